// round 10
// baseline (speedup 1.0000x reference)
#include <cuda_runtime.h>
#include <cuda_fp16.h>
#include <math.h>
#include <stdint.h>

#define KB   8
#define KS   1029
#define KBS  (KB*KS)          // 8232
#define KD   768
#define KHW  1024
#define KNH  12
#define KHD  64
#define KR1  5
#define KDFF 3072
#define KNQ  2304
#define LN_EPS 1e-5f

// ---------------- device scratch (static: allocation-guard safe) -------------
__device__ float  g_tokens[KBS*KD];
__device__ float  g_xw[KBS*KD];
__device__ __half g_xw_h[KBS*KD];
__device__ __half g_qkv[(size_t)KBS*KNQ];
__device__ __half g_attn_h[KBS*KD];
__device__ float  g_h1[KBS*KD];
__device__ __half g_ff_h[KBS*KD];
__device__ __half g_mid_h[(size_t)KBS*KDFF];
__device__ float  g_res[KBS*KD];
__device__ __half g_wqkv_h[KNQ*KD];
__device__ __half g_wout_h[KD*KD];
__device__ __half g_w1_h[KDFF*KD];
__device__ __half g_w2_h[KD*KDFF];

// ---------------- helpers -----------------------------------------------------
__device__ __forceinline__ uint32_t smem_u32(const void* p) {
    return (uint32_t)__cvta_generic_to_shared(p);
}
__device__ __forceinline__ void ldsm_x4(uint32_t& r0, uint32_t& r1, uint32_t& r2, uint32_t& r3, uint32_t addr) {
    asm volatile("ldmatrix.sync.aligned.m8n8.x4.shared.b16 {%0,%1,%2,%3}, [%4];\n"
                 : "=r"(r0), "=r"(r1), "=r"(r2), "=r"(r3) : "r"(addr));
}
__device__ __forceinline__ void mma_16816(float* d, const uint32_t* a, const uint32_t* b) {
    asm volatile("mma.sync.aligned.m16n8k16.row.col.f32.f16.f16.f32 "
                 "{%0,%1,%2,%3}, {%4,%5,%6,%7}, {%8,%9}, {%0,%1,%2,%3};\n"
                 : "+f"(d[0]), "+f"(d[1]), "+f"(d[2]), "+f"(d[3])
                 : "r"(a[0]), "r"(a[1]), "r"(a[2]), "r"(a[3]), "r"(b[0]), "r"(b[1]));
}
// fp16-accumulate variant (hypothesis: double-rate on sm_103a)
__device__ __forceinline__ void mma_16816_h(uint32_t* d, const uint32_t* a, const uint32_t* b) {
    asm volatile("mma.sync.aligned.m16n8k16.row.col.f16.f16.f16.f16 "
                 "{%0,%1}, {%2,%3,%4,%5}, {%6,%7}, {%0,%1};\n"
                 : "+r"(d[0]), "+r"(d[1])
                 : "r"(a[0]), "r"(a[1]), "r"(a[2]), "r"(a[3]), "r"(b[0]), "r"(b[1]));
}
__device__ __forceinline__ void cpasync16(uint32_t d, const void* g) {
    asm volatile("cp.async.cg.shared.global [%0], [%1], 16;\n" :: "r"(d), "l"(g));
}
__device__ __forceinline__ float gelu_exact(float x) {
    return 0.5f * x * (1.0f + erff(x * 0.70710678118654752f));
}

// ---------------- prep: transpose features into token matrix -----------------
__global__ void k_transpose_in(const float* __restrict__ x) {
    __shared__ float tile[32][33];
    int b = blockIdx.z;
    int hw0 = blockIdx.x * 32, c0 = blockIdx.y * 32;
    int tx = threadIdx.x, ty = threadIdx.y;
    #pragma unroll
    for (int i = 0; i < 32; i += 8)
        tile[ty + i][tx] = x[((size_t)b*KD + c0 + ty + i)*KHW + hw0 + tx];
    __syncthreads();
    #pragma unroll
    for (int i = 0; i < 32; i += 8)
        g_tokens[((size_t)(b*KS + KR1 + hw0 + ty + i))*KD + c0 + tx] = tile[tx][ty + i];
}

// ---------------- layernorm (row = 768, block 256) ----------------------------
__global__ void k_layernorm(const float* __restrict__ in,
                            const float* __restrict__ ctx, const float* __restrict__ reg,
                            const float* __restrict__ gma, const float* __restrict__ bta,
                            float* __restrict__ outf, __half* __restrict__ outh) {
    int row = blockIdx.x;
    const float* p = in + (size_t)row * KD;
    if (ctx) {
        int b = row / KS, t = row - b * KS;
        if (t < KR1)
            p = (t == 0) ? (ctx + (size_t)b * KD)
                         : (reg + ((size_t)b * (KR1-1) + (t-1)) * KD);
    }
    int tid = threadIdx.x;
    int lane = tid & 31, warp = tid >> 5;
    float v0 = p[tid], v1 = p[tid + 256], v2 = p[tid + 512];
    float s = v0 + v1 + v2;
    __shared__ float red[8];
    __shared__ float s_mu, s_rstd;
    #pragma unroll
    for (int o = 16; o; o >>= 1) s += __shfl_xor_sync(0xffffffffu, s, o);
    if (lane == 0) red[warp] = s;
    __syncthreads();
    if (tid == 0) {
        float t = 0;
        #pragma unroll
        for (int i = 0; i < 8; i++) t += red[i];
        s_mu = t * (1.0f / KD);
    }
    __syncthreads();
    float mu = s_mu;
    float d0 = v0 - mu, d1 = v1 - mu, d2 = v2 - mu;
    float q = d0*d0 + d1*d1 + d2*d2;
    #pragma unroll
    for (int o = 16; o; o >>= 1) q += __shfl_xor_sync(0xffffffffu, q, o);
    if (lane == 0) red[warp] = q;
    __syncthreads();
    if (tid == 0) {
        float t = 0;
        #pragma unroll
        for (int i = 0; i < 8; i++) t += red[i];
        s_rstd = rsqrtf(t * (1.0f / KD) + LN_EPS);
    }
    __syncthreads();
    float r = s_rstd;
    #pragma unroll
    for (int i = 0; i < 3; i++) {
        int c = tid + i * 256;
        float vv = (i == 0) ? v0 : (i == 1) ? v1 : v2;
        float o = (vv - mu) * r * gma[c] + bta[c];
        if (outf) outf[(size_t)row*KD + c] = o;
        outh[(size_t)row*KD + c] = __float2half(o);
    }
}

// ---------------- f32 -> f16 (vectorized) --------------------------------------
__global__ void k_f2h4(const float* __restrict__ in, __half* __restrict__ out, int n4) {
    int i = blockIdx.x * blockDim.x + threadIdx.x;
    if (i >= n4) return;
    float4 v = ((const float4*)in)[i];
    ((__half2*)out)[i*2]   = __floats2half2_rn(v.x, v.y);
    ((__half2*)out)[i*2+1] = __floats2half2_rn(v.z, v.w);
}

__global__ void k_f2h_rest(const float* __restrict__ a, __half* __restrict__ oa, int na4,
                           const float* __restrict__ b, __half* __restrict__ ob, int nb4,
                           const float* __restrict__ c, __half* __restrict__ oc, int nc4) {
    int i = blockIdx.x * blockDim.x + threadIdx.x;
    const float* src; __half* dst; int j = i;
    if (j < na4) { src = a; dst = oa; }
    else {
        j -= na4;
        if (j < nb4) { src = b; dst = ob; }
        else { j -= nb4; if (j >= nc4) return; src = c; dst = oc; }
    }
    float4 v = ((const float4*)src)[j];
    ((__half2*)dst)[j*2]   = __floats2half2_rn(v.x, v.y);
    ((__half2*)dst)[j*2+1] = __floats2half2_rn(v.z, v.w);
}

#define SSTR 72                       // half stride (144B rows) conflict-free ldmatrix

// ============ WIDE GEMM: 128(m) x 256(n), warp tile 64x64, NSTG=3 =============
// fp16 accumulate within each K=64 chunk, promoted to fp32 per chunk.
// EPI 2: Ch = gelu(acc + bias) ; EPI 3: Ch = acc + bias
#define WASTGH (128*SSTR)             // 9216 halfs / stage
#define WBSTGH (256*SSTR)             // 18432 halfs / stage
#define WNSTG 3
#define WSMEM ((WNSTG*(WASTGH+WBSTGH))*2)   // 165888 B

template<int EPI>
__global__ void __launch_bounds__(256) k_gemmw(
    const __half* __restrict__ A, const __half* __restrict__ Wt,
    const float* __restrict__ bias,
    __half* __restrict__ Ch,
    int M, int N, int K)
{
    extern __shared__ char smemraw[];
    __half* As = (__half*)smemraw;
    __half* Bs = As + WNSTG * WASTGH;
    int tid = threadIdx.x;
    int lane = tid & 31, warp = tid >> 5;
    int wm = warp & 1, wn = warp >> 1;       // warp tile 64(m) x 64(n)
    int m0 = blockIdx.y * 128, n0 = blockIdx.x * 256;
    const int nIter = K / 64;

    float facc[4][8][4];
    #pragma unroll
    for (int i = 0; i < 4; i++)
        #pragma unroll
        for (int j = 0; j < 8; j++)
            #pragma unroll
            for (int c = 0; c < 4; c++) facc[i][j][c] = 0.f;

    int cr = tid >> 3;               // rows 0..31 per sweep
    int cc = (tid & 7) << 3;         // cols 0,8,...,56

    auto load_stage = [&](int iter, int st) {
        int k0 = iter * 64;
        uint32_t abase = smem_u32(As + st * WASTGH);
        uint32_t bbase = smem_u32(Bs + st * WBSTGH);
        #pragma unroll
        for (int h = 0; h < 4; h++) {
            int r = cr + h * 32;
            int gm = m0 + r; if (gm > M-1) gm = M-1;
            cpasync16(abase + (r * SSTR + cc) * 2, A + (size_t)gm * K + k0 + cc);
        }
        #pragma unroll
        for (int h = 0; h < 8; h++) {
            int r = cr + h * 32;
            cpasync16(bbase + (r * SSTR + cc) * 2, Wt + (size_t)(n0 + r) * K + k0 + cc);
        }
        asm volatile("cp.async.commit_group;\n" ::: "memory");
    };

    load_stage(0, 0);
    load_stage(1, 1);

    int a_rl = (lane & 15);
    int a_co = (lane & 16) ? 8 : 0;
    int b_rl = (lane & 7) + ((lane & 16) ? 8 : 0);
    int b_co = (lane & 8) ? 8 : 0;

    int s = 0;
    for (int i = 0; i < nIter; i++) {
        asm volatile("cp.async.wait_group 1;\n" ::: "memory");
        __syncthreads();
        const __half* as = As + s * WASTGH;
        const __half* bs = Bs + s * WBSTGH;
        int j = i + 2;
        int sj = s + 2; if (sj >= WNSTG) sj -= WNSTG;

        // fp16 chunk accumulators (zeroed each K=64 chunk)
        uint32_t hacc[4][8][2];
        #pragma unroll
        for (int mi = 0; mi < 4; mi++)
            #pragma unroll
            for (int ni = 0; ni < 8; ni++) { hacc[mi][ni][0] = 0u; hacc[mi][ni][1] = 0u; }

        #pragma unroll
        for (int ks = 0; ks < 4; ks++) {
            uint32_t afr[4][4];
            #pragma unroll
            for (int mi = 0; mi < 4; mi++) {
                uint32_t addr = smem_u32(as + (wm*64 + mi*16 + a_rl) * SSTR + ks*16 + a_co);
                ldsm_x4(afr[mi][0], afr[mi][1], afr[mi][2], afr[mi][3], addr);
            }
            #pragma unroll
            for (int nb = 0; nb < 4; nb++) {
                uint32_t addr = smem_u32(bs + (wn*64 + nb*16 + b_rl) * SSTR + ks*16 + b_co);
                uint32_t b0[2], b1[2];
                ldsm_x4(b0[0], b0[1], b1[0], b1[1], addr);
                #pragma unroll
                for (int mi = 0; mi < 4; mi++) {
                    mma_16816_h(hacc[mi][nb*2],   afr[mi], b0);
                    mma_16816_h(hacc[mi][nb*2+1], afr[mi], b1);
                }
            }
            if (ks == 1 && j < nIter) load_stage(j, sj);
        }

        // promote chunk to fp32
        #pragma unroll
        for (int mi = 0; mi < 4; mi++)
            #pragma unroll
            for (int ni = 0; ni < 8; ni++) {
                float2 p0 = __half22float2(*(const __half2*)&hacc[mi][ni][0]);
                float2 p1 = __half22float2(*(const __half2*)&hacc[mi][ni][1]);
                facc[mi][ni][0] += p0.x;
                facc[mi][ni][1] += p0.y;
                facc[mi][ni][2] += p1.x;
                facc[mi][ni][3] += p1.y;
            }

        if (j >= nIter)
            asm volatile("cp.async.commit_group;\n" ::: "memory");
        if (++s == WNSTG) s = 0;
    }

    __syncthreads();

    // epilogue (half outputs)
    #pragma unroll
    for (int mi = 0; mi < 4; mi++) {
        int rbase = m0 + wm*64 + mi*16 + (lane >> 2);
        #pragma unroll
        for (int ni = 0; ni < 8; ni++) {
            int col = n0 + wn*64 + ni*8 + ((lane & 3) << 1);
            float bx = __ldg(bias + col), by = __ldg(bias + col + 1);
            #pragma unroll
            for (int hh = 0; hh < 2; hh++) {
                int row = rbase + hh * 8;
                if (row < M) {
                    float v0 = facc[mi][ni][hh*2 + 0] + bx;
                    float v1 = facc[mi][ni][hh*2 + 1] + by;
                    if constexpr (EPI == 2) { v0 = gelu_exact(v0); v1 = gelu_exact(v1); }
                    *(__half2*)(Ch + (size_t)row * N + col) = __floats2half2_rn(v0, v1);
                }
            }
        }
    }
}

// ============ NARROW GEMM (proven R8): 128x128, warp 32x64, NSTG=3 ============
// EPI 1: Cf = acc + bias + res
#define GBM 128
#define GBN 128
#define NSTG 3
#define ASTGH (GBM*SSTR)              // 9216 halfs per stage side

template<int EPI>
__global__ void __launch_bounds__(256, 2) k_gemm(
    const __half* __restrict__ A, const __half* __restrict__ Wt,
    const float* __restrict__ bias, const float* __restrict__ res,
    float* __restrict__ Cf,
    int M, int N, int K)
{
    __shared__ __half As[NSTG * ASTGH];
    __shared__ __half Bs[NSTG * ASTGH];
    int tid = threadIdx.x;
    int lane = tid & 31, warp = tid >> 5;
    int wm = warp & 3, wn = warp >> 2;       // warp tile 32(m) x 64(n)
    int m0 = blockIdx.y * GBM, n0 = blockIdx.x * GBN;
    const int nIter = K / 64;

    float acc[2][8][4];
    #pragma unroll
    for (int i = 0; i < 2; i++)
        #pragma unroll
        for (int j = 0; j < 8; j++)
            #pragma unroll
            for (int c = 0; c < 4; c++) acc[i][j][c] = 0.f;

    int cr = tid >> 3;
    int cc = (tid & 7) << 3;

    auto load_stage = [&](int iter, int st) {
        int k0 = iter * 64;
        uint32_t abase = smem_u32(As + st * ASTGH);
        uint32_t bbase = smem_u32(Bs + st * ASTGH);
        #pragma unroll
        for (int h = 0; h < 4; h++) {
            int r = cr + h * 32;
            int gm = m0 + r; if (gm > M-1) gm = M-1;
            cpasync16(abase + (r * SSTR + cc) * 2, A + (size_t)gm * K + k0 + cc);
            cpasync16(bbase + (r * SSTR + cc) * 2, Wt + (size_t)(n0 + r) * K + k0 + cc);
        }
        asm volatile("cp.async.commit_group;\n" ::: "memory");
    };

    load_stage(0, 0);
    load_stage(1, 1);

    int a_rl = (lane & 15);
    int a_co = (lane & 16) ? 8 : 0;
    int b_rl = (lane & 7) + ((lane & 16) ? 8 : 0);
    int b_co = (lane & 8) ? 8 : 0;

    int s = 0;
    for (int i = 0; i < nIter; i++) {
        asm volatile("cp.async.wait_group 1;\n" ::: "memory");
        __syncthreads();
        const __half* as = As + s * ASTGH;
        const __half* bs = Bs + s * ASTGH;
        int j = i + 2;
        int sj = s + 2; if (sj >= NSTG) sj -= NSTG;

        #pragma unroll
        for (int ks = 0; ks < 4; ks++) {
            uint32_t afr[2][4];
            #pragma unroll
            for (int mi = 0; mi < 2; mi++) {
                uint32_t addr = smem_u32(as + (wm*32 + mi*16 + a_rl) * SSTR + ks*16 + a_co);
                ldsm_x4(afr[mi][0], afr[mi][1], afr[mi][2], afr[mi][3], addr);
            }
            uint32_t bfr[8][2];
            #pragma unroll
            for (int nb = 0; nb < 4; nb++) {
                uint32_t addr = smem_u32(bs + (wn*64 + nb*16 + b_rl) * SSTR + ks*16 + b_co);
                uint32_t r0, r1, r2, r3;
                ldsm_x4(r0, r1, r2, r3, addr);
                bfr[nb*2][0] = r0; bfr[nb*2][1] = r1;
                bfr[nb*2+1][0] = r2; bfr[nb*2+1][1] = r3;
            }
            #pragma unroll
            for (int mi = 0; mi < 2; mi++)
                #pragma unroll
                for (int ni = 0; ni < 8; ni++)
                    mma_16816(acc[mi][ni], afr[mi], bfr[ni]);

            if (ks == 1 && j < nIter) load_stage(j, sj);
        }
        if (j >= nIter)
            asm volatile("cp.async.commit_group;\n" ::: "memory");
        if (++s == NSTG) s = 0;
    }

    __syncthreads();

    #pragma unroll
    for (int mi = 0; mi < 2; mi++) {
        int rbase = m0 + wm*32 + mi*16 + (lane >> 2);
        #pragma unroll
        for (int ni = 0; ni < 8; ni++) {
            int col = n0 + wn*64 + ni*8 + ((lane & 3) << 1);
            float bx = __ldg(bias + col), by = __ldg(bias + col + 1);
            #pragma unroll
            for (int hh = 0; hh < 2; hh++) {
                int row = rbase + hh * 8;
                if (row < M) {
                    float v0 = acc[mi][ni][hh*2 + 0] + bx;
                    float v1 = acc[mi][ni][hh*2 + 1] + by;
                    if constexpr (EPI == 1) {
                        v0 += __ldg(res + (size_t)row * N + col);
                        v1 += __ldg(res + (size_t)row * N + col + 1);
                    }
                    Cf[(size_t)row * N + col]     = v0;
                    Cf[(size_t)row * N + col + 1] = v1;
                }
            }
        }
    }
}

// ---------------- attention: full rows (queries 0..4), 128 threads ------------
__global__ void k_attn_full() {
    int idx = blockIdx.x;
    int qi = idx % KR1; idx /= KR1;
    int h = idx % KNH;
    int b = idx / KNH;
    int tid = threadIdx.x;          // 128
    int lane = tid & 31, warp = tid >> 5;
    int row = b*KS + qi;

    __shared__ float sc[KS];
    __shared__ float qsh[KHD];
    __shared__ float wredm[4], wreds[4];
    __shared__ float osh[64];

    if (tid < KHD) qsh[tid] = __half2float(g_qkv[(size_t)row*KNQ + h*KHD + tid]);
    __syncthreads();

    for (int j = tid; j < KS; j += 128) {
        const __half2* kp = (const __half2*)(g_qkv + (size_t)(b*KS + j)*KNQ + KD + h*KHD);
        float s = 0.f;
        #pragma unroll 8
        for (int d = 0; d < KHD/2; d++) {
            float2 kf = __half22float2(kp[d]);
            s += qsh[2*d] * kf.x + qsh[2*d+1] * kf.y;
        }
        sc[j] = s * 0.125f;
    }
    __syncthreads();

    float m = -1e30f;
    for (int j = tid; j < KS; j += 128) m = fmaxf(m, sc[j]);
    #pragma unroll
    for (int o = 16; o; o >>= 1) m = fmaxf(m, __shfl_xor_sync(0xffffffffu, m, o));
    if (lane == 0) wredm[warp] = m;
    __syncthreads();
    m = fmaxf(fmaxf(wredm[0], wredm[1]), fmaxf(wredm[2], wredm[3]));

    float sum = 0.f;
    for (int j = tid; j < KS; j += 128) { float e = expf(sc[j] - m); sc[j] = e; sum += e; }
    #pragma unroll
    for (int o = 16; o; o >>= 1) sum += __shfl_xor_sync(0xffffffffu, sum, o);
    if (lane == 0) wreds[warp] = sum;
    __syncthreads();
    float inv = 1.0f / (wreds[0] + wreds[1] + wreds[2] + wreds[3]);

    int half = tid >> 6, d = tid & 63;
    float o = 0.f;
    for (int j = half; j < KS; j += 2)
        o += sc[j] * __half2float(g_qkv[(size_t)(b*KS + j)*KNQ + 2*KD + h*KHD + d]);
    if (half) osh[d] = o;
    __syncthreads();
    if (tid < 64)
        g_attn_h[(size_t)row*KD + h*KHD + tid] = __float2half((o + osh[tid]) * inv);
}

// ---------------- attention: sparse rows (feature tokens) ---------------------
__global__ void k_attn_sparse() {
    int gw = (blockIdx.x * blockDim.x + threadIdx.x) >> 5;
    int lane = threadIdx.x & 31;
    if (gw >= KB*KHW*KNH) return;
    int h = gw % KNH; int rest = gw / KNH;
    int f = rest % KHW; int b = rest / KHW;
    int row = b*KS + KR1 + f;

    float2 qf = __half22float2(((const __half2*)(g_qkv + (size_t)row*KNQ + h*KHD))[lane]);

    float sc[6];
    #pragma unroll
    for (int j = 0; j < 6; j++) {
        int krow = (j < 5) ? (b*KS + j) : row;
        float2 kf = __half22float2(
            ((const __half2*)(g_qkv + (size_t)krow*KNQ + KD + h*KHD))[lane]);
        float p = qf.x*kf.x + qf.y*kf.y;
        #pragma unroll
        for (int o = 16; o; o >>= 1) p += __shfl_xor_sync(0xffffffffu, p, o);
        sc[j] = p * 0.125f;
    }
    float m = sc[0];
    #pragma unroll
    for (int j = 1; j < 6; j++) m = fmaxf(m, sc[j]);
    float sum = 0.f;
    #pragma unroll
    for (int j = 0; j < 6; j++) { sc[j] = expf(sc[j] - m); sum += sc[j]; }
    float inv = 1.0f / sum;

    float o0 = 0.f, o1 = 0.f;
    #pragma unroll
    for (int j = 0; j < 6; j++) {
        int krow = (j < 5) ? (b*KS + j) : row;
        float2 vf = __half22float2(
            ((const __half2*)(g_qkv + (size_t)krow*KNQ + 2*KD + h*KHD))[lane]);
        o0 += sc[j] * vf.x;
        o1 += sc[j] * vf.y;
    }
    ((__half2*)(g_attn_h + (size_t)row*KD + h*KHD))[lane] = __floats2half2_rn(o0 * inv, o1 * inv);
}

// ---------------- output scatter ----------------------------------------------
__global__ void k_scatter_feat(float* __restrict__ out) {
    __shared__ float tile[32][33];
    int b = blockIdx.z;
    int hw0 = blockIdx.x * 32, c0 = blockIdx.y * 32;
    int tx = threadIdx.x, ty = threadIdx.y;
    #pragma unroll
    for (int i = 0; i < 32; i += 8)
        tile[ty + i][tx] = g_res[((size_t)(b*KS + KR1 + hw0 + ty + i))*KD + c0 + tx];
    __syncthreads();
    #pragma unroll
    for (int i = 0; i < 32; i += 8)
        out[((size_t)b*KD + c0 + ty + i)*KHW + hw0 + tx] = tile[tx][ty + i];
}

__global__ void k_scatter_small(float* __restrict__ out) {
    const size_t FEAT = (size_t)KB * KD * KHW;
    const size_t CTXS = (size_t)KB * KD;
    int i = blockIdx.x * blockDim.x + threadIdx.x;
    if (i >= KB*KR1*KD) return;
    int c = i % KD;
    int t = (i / KD) % KR1;
    int b = i / (KD*KR1);
    float v = g_res[((size_t)(b*KS + t))*KD + c];
    if (t == 0) out[FEAT + (size_t)b*KD + c] = v;
    else        out[FEAT + CTXS + ((size_t)(b*(KR1-1) + (t-1)))*KD + c] = v;
}

// ---------------- launch -------------------------------------------------------
extern "C" void kernel_launch(void* const* d_in, const int* in_sizes, int n_in,
                              void* d_out, int out_size) {
    const float* x        = (const float*)d_in[0];
    const float* ctx      = (const float*)d_in[1];
    const float* reg      = (const float*)d_in[2];
    const float* in_pw    = (const float*)d_in[3];
    const float* in_pb    = (const float*)d_in[4];
    const float* out_w    = (const float*)d_in[5];
    const float* out_b    = (const float*)d_in[6];
    const float* ln1_g    = (const float*)d_in[7];
    const float* ln1_b    = (const float*)d_in[8];
    const float* ln2_g    = (const float*)d_in[9];
    const float* ln2_b    = (const float*)d_in[10];
    const float* w1       = (const float*)d_in[11];
    const float* b1       = (const float*)d_in[12];
    const float* w2       = (const float*)d_in[13];
    const float* b2       = (const float*)d_in[14];
    float* out = (float*)d_out;

    float *p_tokens, *p_xw, *p_h1, *p_res;
    __half *p_qkv, *p_xw_h, *p_attn_h, *p_ff_h, *p_mid_h, *p_wqkv, *p_wout, *p_w1, *p_w2;
    cudaGetSymbolAddress((void**)&p_tokens, g_tokens);
    cudaGetSymbolAddress((void**)&p_xw,     g_xw);
    cudaGetSymbolAddress((void**)&p_qkv,    g_qkv);
    cudaGetSymbolAddress((void**)&p_h1,     g_h1);
    cudaGetSymbolAddress((void**)&p_res,    g_res);
    cudaGetSymbolAddress((void**)&p_xw_h,   g_xw_h);
    cudaGetSymbolAddress((void**)&p_attn_h, g_attn_h);
    cudaGetSymbolAddress((void**)&p_ff_h,   g_ff_h);
    cudaGetSymbolAddress((void**)&p_mid_h,  g_mid_h);
    cudaGetSymbolAddress((void**)&p_wqkv,   g_wqkv_h);
    cudaGetSymbolAddress((void**)&p_wout,   g_wout_h);
    cudaGetSymbolAddress((void**)&p_w1,     g_w1_h);
    cudaGetSymbolAddress((void**)&p_w2,     g_w2_h);

    cudaFuncSetAttribute(k_gemmw<2>, cudaFuncAttributeMaxDynamicSharedMemorySize, WSMEM);
    cudaFuncSetAttribute(k_gemmw<3>, cudaFuncAttributeMaxDynamicSharedMemorySize, WSMEM);

    dim3 tb32(32, 8);
    const int MT = (KBS + 127) / 128;   // 65

    // 1: transpose features into token rows
    k_transpose_in<<<dim3(KHW/32, KD/32, KB), tb32>>>(x);

    // 2: QKV weight conversion
    k_f2h4<<<(KNQ*KD/4 + 255)/256, 256>>>(in_pw, p_wqkv, KNQ*KD/4);

    // 3: LN1 (reads ctx/reg directly for token rows)
    k_layernorm<<<KBS, 256>>>(p_tokens, ctx, reg, ln1_g, ln1_b, p_xw, p_xw_h);

    // 4: QKV GEMM (wide, fp16-acc, half output)  <-- profiled slot
    k_gemmw<3><<<dim3(KNQ/256, MT), 256, WSMEM>>>(
        p_xw_h, p_wqkv, in_pb, p_qkv, KBS, KNQ, KD);

    // attention
    k_attn_full<<<KB*KNH*KR1, 128>>>();
    k_attn_sparse<<<(KB*KHW*KNH)/8, 256>>>();

    // remaining weight conversions (one launch)
    {
        int na4 = KD*KD/4, nb4 = KDFF*KD/4, nc4 = KD*KDFF/4;
        int tot = na4 + nb4 + nc4;
        k_f2h_rest<<<(tot + 255)/256, 256>>>(out_w, p_wout, na4, w1, p_w1, nb4, w2, p_w2, nc4);
    }

    // out-proj + residual (h1 = attn@Wo + bo + xw)
    k_gemm<1><<<dim3(KD/GBN, MT), 256>>>(
        p_attn_h, p_wout, out_b, p_xw, p_h1, KBS, KD, KD);

    // LN2
    k_layernorm<<<KBS, 256>>>(p_h1, nullptr, nullptr, ln2_g, ln2_b, nullptr, p_ff_h);

    // FF1 + gelu (wide, fp16-acc, half output)
    k_gemmw<2><<<dim3(KDFF/256, MT), 256, WSMEM>>>(
        p_ff_h, p_w1, b1, p_mid_h, KBS, KDFF, KD);

    // FF2 + residual (out = mid@W2 + b2 + h1)
    k_gemm<1><<<dim3(KD/GBN, MT), 256>>>(
        p_mid_h, p_w2, b2, p_h1, p_res, KBS, KD, KDFF);

    // scatter to output layout
    k_scatter_feat<<<dim3(KHW/32, KD/32, KB), tb32>>>(out);
    k_scatter_small<<<(KB*KR1*KD + 255)/256, 256>>>(out);
}

// round 11
// speedup vs baseline: 1.0140x; 1.0140x over previous
#include <cuda_runtime.h>
#include <cuda_fp16.h>
#include <math.h>
#include <stdint.h>

#define KB   8
#define KS   1029
#define KBS  (KB*KS)          // 8232
#define KD   768
#define KHW  1024
#define KNH  12
#define KHD  64
#define KR1  5
#define KDFF 3072
#define KNQ  2304
#define LN_EPS 1e-5f

// ---------------- device scratch (static: allocation-guard safe) -------------
__device__ float  g_tokens[KBS*KD];
__device__ float  g_xw[KBS*KD];
__device__ __half g_xw_h[KBS*KD];
__device__ __half g_qkv[(size_t)KBS*KNQ];
__device__ __half g_attn_h[KBS*KD];
__device__ float  g_h1[KBS*KD];
__device__ __half g_ff_h[KBS*KD];
__device__ __half g_mid_h[(size_t)KBS*KDFF];
__device__ float  g_res[KBS*KD];
__device__ __half g_wqkv_h[KNQ*KD];
__device__ __half g_wout_h[KD*KD];
__device__ __half g_w1_h[KDFF*KD];
__device__ __half g_w2_h[KD*KDFF];

// ---------------- helpers -----------------------------------------------------
__device__ __forceinline__ uint32_t smem_u32(const void* p) {
    return (uint32_t)__cvta_generic_to_shared(p);
}
__device__ __forceinline__ void ldsm_x4(uint32_t& r0, uint32_t& r1, uint32_t& r2, uint32_t& r3, uint32_t addr) {
    asm volatile("ldmatrix.sync.aligned.m8n8.x4.shared.b16 {%0,%1,%2,%3}, [%4];\n"
                 : "=r"(r0), "=r"(r1), "=r"(r2), "=r"(r3) : "r"(addr));
}
__device__ __forceinline__ void mma_16816(float* d, const uint32_t* a, const uint32_t* b) {
    asm volatile("mma.sync.aligned.m16n8k16.row.col.f32.f16.f16.f32 "
                 "{%0,%1,%2,%3}, {%4,%5,%6,%7}, {%8,%9}, {%0,%1,%2,%3};\n"
                 : "+f"(d[0]), "+f"(d[1]), "+f"(d[2]), "+f"(d[3])
                 : "r"(a[0]), "r"(a[1]), "r"(a[2]), "r"(a[3]), "r"(b[0]), "r"(b[1]));
}
__device__ __forceinline__ void cpasync16(uint32_t d, const void* g) {
    asm volatile("cp.async.cg.shared.global [%0], [%1], 16;\n" :: "r"(d), "l"(g));
}
__device__ __forceinline__ float gelu_exact(float x) {
    return 0.5f * x * (1.0f + erff(x * 0.70710678118654752f));
}

// ---------------- prep: transpose features into token matrix -----------------
__global__ void k_transpose_in(const float* __restrict__ x) {
    __shared__ float tile[32][33];
    int b = blockIdx.z;
    int hw0 = blockIdx.x * 32, c0 = blockIdx.y * 32;
    int tx = threadIdx.x, ty = threadIdx.y;
    #pragma unroll
    for (int i = 0; i < 32; i += 8)
        tile[ty + i][tx] = x[((size_t)b*KD + c0 + ty + i)*KHW + hw0 + tx];
    __syncthreads();
    #pragma unroll
    for (int i = 0; i < 32; i += 8)
        g_tokens[((size_t)(b*KS + KR1 + hw0 + ty + i))*KD + c0 + tx] = tile[tx][ty + i];
}

// ---------------- layernorm (row = 768, block 256) ----------------------------
__global__ void k_layernorm(const float* __restrict__ in,
                            const float* __restrict__ ctx, const float* __restrict__ reg,
                            const float* __restrict__ gma, const float* __restrict__ bta,
                            float* __restrict__ outf, __half* __restrict__ outh) {
    int row = blockIdx.x;
    const float* p = in + (size_t)row * KD;
    if (ctx) {
        int b = row / KS, t = row - b * KS;
        if (t < KR1)
            p = (t == 0) ? (ctx + (size_t)b * KD)
                         : (reg + ((size_t)b * (KR1-1) + (t-1)) * KD);
    }
    int tid = threadIdx.x;
    int lane = tid & 31, warp = tid >> 5;
    float v0 = p[tid], v1 = p[tid + 256], v2 = p[tid + 512];
    float s = v0 + v1 + v2;
    __shared__ float red[8];
    __shared__ float s_mu, s_rstd;
    #pragma unroll
    for (int o = 16; o; o >>= 1) s += __shfl_xor_sync(0xffffffffu, s, o);
    if (lane == 0) red[warp] = s;
    __syncthreads();
    if (tid == 0) {
        float t = 0;
        #pragma unroll
        for (int i = 0; i < 8; i++) t += red[i];
        s_mu = t * (1.0f / KD);
    }
    __syncthreads();
    float mu = s_mu;
    float d0 = v0 - mu, d1 = v1 - mu, d2 = v2 - mu;
    float q = d0*d0 + d1*d1 + d2*d2;
    #pragma unroll
    for (int o = 16; o; o >>= 1) q += __shfl_xor_sync(0xffffffffu, q, o);
    if (lane == 0) red[warp] = q;
    __syncthreads();
    if (tid == 0) {
        float t = 0;
        #pragma unroll
        for (int i = 0; i < 8; i++) t += red[i];
        s_rstd = rsqrtf(t * (1.0f / KD) + LN_EPS);
    }
    __syncthreads();
    float r = s_rstd;
    #pragma unroll
    for (int i = 0; i < 3; i++) {
        int c = tid + i * 256;
        float vv = (i == 0) ? v0 : (i == 1) ? v1 : v2;
        float o = (vv - mu) * r * gma[c] + bta[c];
        if (outf) outf[(size_t)row*KD + c] = o;
        outh[(size_t)row*KD + c] = __float2half(o);
    }
}

// ---------------- f32 -> f16 (vectorized) --------------------------------------
__global__ void k_f2h4(const float* __restrict__ in, __half* __restrict__ out, int n4) {
    int i = blockIdx.x * blockDim.x + threadIdx.x;
    if (i >= n4) return;
    float4 v = ((const float4*)in)[i];
    ((__half2*)out)[i*2]   = __floats2half2_rn(v.x, v.y);
    ((__half2*)out)[i*2+1] = __floats2half2_rn(v.z, v.w);
}

__global__ void k_f2h_rest(const float* __restrict__ a, __half* __restrict__ oa, int na4,
                           const float* __restrict__ b, __half* __restrict__ ob, int nb4,
                           const float* __restrict__ c, __half* __restrict__ oc, int nc4) {
    int i = blockIdx.x * blockDim.x + threadIdx.x;
    const float* src; __half* dst; int j = i;
    if (j < na4) { src = a; dst = oa; }
    else {
        j -= na4;
        if (j < nb4) { src = b; dst = ob; }
        else { j -= nb4; if (j >= nc4) return; src = c; dst = oc; }
    }
    float4 v = ((const float4*)src)[j];
    ((__half2*)dst)[j*2]   = __floats2half2_rn(v.x, v.y);
    ((__half2*)dst)[j*2+1] = __floats2half2_rn(v.z, v.w);
}

#define SSTR 72                       // half stride (144B rows) conflict-free ldmatrix

// ============ WIDE GEMM (R9, f32 acc): 128x256, warp 64x64, NSTG=3 ============
// EPI 2: Ch = gelu(acc + bias) ; EPI 3: Ch = acc + bias
#define WASTGH (128*SSTR)
#define WBSTGH (256*SSTR)
#define WNSTG 3
#define WSMEM ((WNSTG*(WASTGH+WBSTGH))*2)   // 165888 B

template<int EPI>
__global__ void __launch_bounds__(256) k_gemmw(
    const __half* __restrict__ A, const __half* __restrict__ Wt,
    const float* __restrict__ bias,
    __half* __restrict__ Ch,
    int M, int N, int K)
{
    extern __shared__ char smemraw[];
    __half* As = (__half*)smemraw;
    __half* Bs = As + WNSTG * WASTGH;
    int tid = threadIdx.x;
    int lane = tid & 31, warp = tid >> 5;
    int wm = warp & 1, wn = warp >> 1;       // warp tile 64(m) x 64(n)
    int m0 = blockIdx.y * 128, n0 = blockIdx.x * 256;
    const int nIter = K / 64;

    float acc[4][8][4];
    #pragma unroll
    for (int i = 0; i < 4; i++)
        #pragma unroll
        for (int j = 0; j < 8; j++)
            #pragma unroll
            for (int c = 0; c < 4; c++) acc[i][j][c] = 0.f;

    int cr = tid >> 3;
    int cc = (tid & 7) << 3;

    auto load_stage = [&](int iter, int st) {
        int k0 = iter * 64;
        uint32_t abase = smem_u32(As + st * WASTGH);
        uint32_t bbase = smem_u32(Bs + st * WBSTGH);
        #pragma unroll
        for (int h = 0; h < 4; h++) {
            int r = cr + h * 32;
            int gm = m0 + r; if (gm > M-1) gm = M-1;
            cpasync16(abase + (r * SSTR + cc) * 2, A + (size_t)gm * K + k0 + cc);
        }
        #pragma unroll
        for (int h = 0; h < 8; h++) {
            int r = cr + h * 32;
            cpasync16(bbase + (r * SSTR + cc) * 2, Wt + (size_t)(n0 + r) * K + k0 + cc);
        }
        asm volatile("cp.async.commit_group;\n" ::: "memory");
    };

    load_stage(0, 0);
    load_stage(1, 1);

    int a_rl = (lane & 15);
    int a_co = (lane & 16) ? 8 : 0;
    int b_rl = (lane & 7) + ((lane & 16) ? 8 : 0);
    int b_co = (lane & 8) ? 8 : 0;

    int s = 0;
    for (int i = 0; i < nIter; i++) {
        asm volatile("cp.async.wait_group 1;\n" ::: "memory");
        __syncthreads();
        const __half* as = As + s * WASTGH;
        const __half* bs = Bs + s * WBSTGH;
        int j = i + 2;
        int sj = s + 2; if (sj >= WNSTG) sj -= WNSTG;

        #pragma unroll
        for (int ks = 0; ks < 4; ks++) {
            uint32_t afr[4][4];
            #pragma unroll
            for (int mi = 0; mi < 4; mi++) {
                uint32_t addr = smem_u32(as + (wm*64 + mi*16 + a_rl) * SSTR + ks*16 + a_co);
                ldsm_x4(afr[mi][0], afr[mi][1], afr[mi][2], afr[mi][3], addr);
            }
            #pragma unroll
            for (int nb = 0; nb < 4; nb++) {
                uint32_t addr = smem_u32(bs + (wn*64 + nb*16 + b_rl) * SSTR + ks*16 + b_co);
                uint32_t b0[2], b1[2];
                ldsm_x4(b0[0], b0[1], b1[0], b1[1], addr);
                #pragma unroll
                for (int mi = 0; mi < 4; mi++) {
                    mma_16816(acc[mi][nb*2],   afr[mi], b0);
                    mma_16816(acc[mi][nb*2+1], afr[mi], b1);
                }
            }
            if (ks == 1 && j < nIter) load_stage(j, sj);
        }
        if (j >= nIter)
            asm volatile("cp.async.commit_group;\n" ::: "memory");
        if (++s == WNSTG) s = 0;
    }

    __syncthreads();

    #pragma unroll
    for (int mi = 0; mi < 4; mi++) {
        int rbase = m0 + wm*64 + mi*16 + (lane >> 2);
        #pragma unroll
        for (int ni = 0; ni < 8; ni++) {
            int col = n0 + wn*64 + ni*8 + ((lane & 3) << 1);
            float bx = __ldg(bias + col), by = __ldg(bias + col + 1);
            #pragma unroll
            for (int hh = 0; hh < 2; hh++) {
                int row = rbase + hh * 8;
                if (row < M) {
                    float v0 = acc[mi][ni][hh*2 + 0] + bx;
                    float v1 = acc[mi][ni][hh*2 + 1] + by;
                    if constexpr (EPI == 2) { v0 = gelu_exact(v0); v1 = gelu_exact(v1); }
                    *(__half2*)(Ch + (size_t)row * N + col) = __floats2half2_rn(v0, v1);
                }
            }
        }
    }
}

// ============ NARROW-64 GEMM: 64(m) x 128(n), warp 32x32, NSTG=3 ==============
// For N=768 GEMMs: grid 129x6 = 774 blocks -> 2.6 waves (vs 1.32 at M-tile 128).
// EPI 1: Cf = acc + bias + res
#define N6ASTGH (64*SSTR)             // 4608 halfs
#define N6BSTGH (128*SSTR)            // 9216 halfs
#define N6NSTG 3

template<int EPI>
__global__ void __launch_bounds__(256, 2) k_gemm64(
    const __half* __restrict__ A, const __half* __restrict__ Wt,
    const float* __restrict__ bias, const float* __restrict__ res,
    float* __restrict__ Cf,
    int M, int N, int K)
{
    __shared__ __half As[N6NSTG * N6ASTGH];
    __shared__ __half Bs[N6NSTG * N6BSTGH];
    int tid = threadIdx.x;
    int lane = tid & 31, warp = tid >> 5;
    int wm = warp & 1, wn = warp >> 1;       // warp tile 32(m) x 32(n)
    int m0 = blockIdx.y * 64, n0 = blockIdx.x * 128;
    const int nIter = K / 64;

    float acc[2][4][4];
    #pragma unroll
    for (int i = 0; i < 2; i++)
        #pragma unroll
        for (int j = 0; j < 4; j++)
            #pragma unroll
            for (int c = 0; c < 4; c++) acc[i][j][c] = 0.f;

    int cr = tid >> 3;               // rows 0..31 per sweep
    int cc = (tid & 7) << 3;

    auto load_stage = [&](int iter, int st) {
        int k0 = iter * 64;
        uint32_t abase = smem_u32(As + st * N6ASTGH);
        uint32_t bbase = smem_u32(Bs + st * N6BSTGH);
        #pragma unroll
        for (int h = 0; h < 2; h++) {
            int r = cr + h * 32;
            int gm = m0 + r; if (gm > M-1) gm = M-1;
            cpasync16(abase + (r * SSTR + cc) * 2, A + (size_t)gm * K + k0 + cc);
        }
        #pragma unroll
        for (int h = 0; h < 4; h++) {
            int r = cr + h * 32;
            cpasync16(bbase + (r * SSTR + cc) * 2, Wt + (size_t)(n0 + r) * K + k0 + cc);
        }
        asm volatile("cp.async.commit_group;\n" ::: "memory");
    };

    load_stage(0, 0);
    load_stage(1, 1);

    int a_rl = (lane & 15);
    int a_co = (lane & 16) ? 8 : 0;
    int b_rl = (lane & 7) + ((lane & 16) ? 8 : 0);
    int b_co = (lane & 8) ? 8 : 0;

    int s = 0;
    for (int i = 0; i < nIter; i++) {
        asm volatile("cp.async.wait_group 1;\n" ::: "memory");
        __syncthreads();
        const __half* as = As + s * N6ASTGH;
        const __half* bs = Bs + s * N6BSTGH;
        int j = i + 2;
        int sj = s + 2; if (sj >= N6NSTG) sj -= N6NSTG;

        #pragma unroll
        for (int ks = 0; ks < 4; ks++) {
            uint32_t afr[2][4];
            #pragma unroll
            for (int mi = 0; mi < 2; mi++) {
                uint32_t addr = smem_u32(as + (wm*32 + mi*16 + a_rl) * SSTR + ks*16 + a_co);
                ldsm_x4(afr[mi][0], afr[mi][1], afr[mi][2], afr[mi][3], addr);
            }
            uint32_t bfr[4][2];
            #pragma unroll
            for (int nb = 0; nb < 2; nb++) {
                uint32_t addr = smem_u32(bs + (wn*32 + nb*16 + b_rl) * SSTR + ks*16 + b_co);
                uint32_t r0, r1, r2, r3;
                ldsm_x4(r0, r1, r2, r3, addr);
                bfr[nb*2][0] = r0; bfr[nb*2][1] = r1;
                bfr[nb*2+1][0] = r2; bfr[nb*2+1][1] = r3;
            }
            #pragma unroll
            for (int mi = 0; mi < 2; mi++)
                #pragma unroll
                for (int ni = 0; ni < 4; ni++)
                    mma_16816(acc[mi][ni], afr[mi], bfr[ni]);

            if (ks == 1 && j < nIter) load_stage(j, sj);
        }
        if (j >= nIter)
            asm volatile("cp.async.commit_group;\n" ::: "memory");
        if (++s == N6NSTG) s = 0;
    }

    __syncthreads();

    #pragma unroll
    for (int mi = 0; mi < 2; mi++) {
        int rbase = m0 + wm*32 + mi*16 + (lane >> 2);
        #pragma unroll
        for (int ni = 0; ni < 4; ni++) {
            int col = n0 + wn*32 + ni*8 + ((lane & 3) << 1);
            float bx = __ldg(bias + col), by = __ldg(bias + col + 1);
            #pragma unroll
            for (int hh = 0; hh < 2; hh++) {
                int row = rbase + hh * 8;
                if (row < M) {
                    float v0 = acc[mi][ni][hh*2 + 0] + bx;
                    float v1 = acc[mi][ni][hh*2 + 1] + by;
                    if constexpr (EPI == 1) {
                        v0 += __ldg(res + (size_t)row * N + col);
                        v1 += __ldg(res + (size_t)row * N + col + 1);
                    }
                    Cf[(size_t)row * N + col]     = v0;
                    Cf[(size_t)row * N + col + 1] = v1;
                }
            }
        }
    }
}

// ---------------- attention: full rows (queries 0..4), 128 threads ------------
__global__ void k_attn_full() {
    int idx = blockIdx.x;
    int qi = idx % KR1; idx /= KR1;
    int h = idx % KNH;
    int b = idx / KNH;
    int tid = threadIdx.x;          // 128
    int lane = tid & 31, warp = tid >> 5;
    int row = b*KS + qi;

    __shared__ float sc[KS];
    __shared__ float qsh[KHD];
    __shared__ float wredm[4], wreds[4];
    __shared__ float osh[64];

    if (tid < KHD) qsh[tid] = __half2float(g_qkv[(size_t)row*KNQ + h*KHD + tid]);
    __syncthreads();

    for (int j = tid; j < KS; j += 128) {
        const __half2* kp = (const __half2*)(g_qkv + (size_t)(b*KS + j)*KNQ + KD + h*KHD);
        float s = 0.f;
        #pragma unroll 8
        for (int d = 0; d < KHD/2; d++) {
            float2 kf = __half22float2(kp[d]);
            s += qsh[2*d] * kf.x + qsh[2*d+1] * kf.y;
        }
        sc[j] = s * 0.125f;
    }
    __syncthreads();

    float m = -1e30f;
    for (int j = tid; j < KS; j += 128) m = fmaxf(m, sc[j]);
    #pragma unroll
    for (int o = 16; o; o >>= 1) m = fmaxf(m, __shfl_xor_sync(0xffffffffu, m, o));
    if (lane == 0) wredm[warp] = m;
    __syncthreads();
    m = fmaxf(fmaxf(wredm[0], wredm[1]), fmaxf(wredm[2], wredm[3]));

    float sum = 0.f;
    for (int j = tid; j < KS; j += 128) { float e = expf(sc[j] - m); sc[j] = e; sum += e; }
    #pragma unroll
    for (int o = 16; o; o >>= 1) sum += __shfl_xor_sync(0xffffffffu, sum, o);
    if (lane == 0) wreds[warp] = sum;
    __syncthreads();
    float inv = 1.0f / (wreds[0] + wreds[1] + wreds[2] + wreds[3]);

    int half = tid >> 6, d = tid & 63;
    float o = 0.f;
    for (int j = half; j < KS; j += 2)
        o += sc[j] * __half2float(g_qkv[(size_t)(b*KS + j)*KNQ + 2*KD + h*KHD + d]);
    if (half) osh[d] = o;
    __syncthreads();
    if (tid < 64)
        g_attn_h[(size_t)row*KD + h*KHD + tid] = __float2half((o + osh[tid]) * inv);
}

// ---------------- attention: sparse rows (feature tokens) ---------------------
__global__ void k_attn_sparse() {
    int gw = (blockIdx.x * blockDim.x + threadIdx.x) >> 5;
    int lane = threadIdx.x & 31;
    if (gw >= KB*KHW*KNH) return;
    int h = gw % KNH; int rest = gw / KNH;
    int f = rest % KHW; int b = rest / KHW;
    int row = b*KS + KR1 + f;

    float2 qf = __half22float2(((const __half2*)(g_qkv + (size_t)row*KNQ + h*KHD))[lane]);

    float sc[6];
    #pragma unroll
    for (int j = 0; j < 6; j++) {
        int krow = (j < 5) ? (b*KS + j) : row;
        float2 kf = __half22float2(
            ((const __half2*)(g_qkv + (size_t)krow*KNQ + KD + h*KHD))[lane]);
        float p = qf.x*kf.x + qf.y*kf.y;
        #pragma unroll
        for (int o = 16; o; o >>= 1) p += __shfl_xor_sync(0xffffffffu, p, o);
        sc[j] = p * 0.125f;
    }
    float m = sc[0];
    #pragma unroll
    for (int j = 1; j < 6; j++) m = fmaxf(m, sc[j]);
    float sum = 0.f;
    #pragma unroll
    for (int j = 0; j < 6; j++) { sc[j] = expf(sc[j] - m); sum += sc[j]; }
    float inv = 1.0f / sum;

    float o0 = 0.f, o1 = 0.f;
    #pragma unroll
    for (int j = 0; j < 6; j++) {
        int krow = (j < 5) ? (b*KS + j) : row;
        float2 vf = __half22float2(
            ((const __half2*)(g_qkv + (size_t)krow*KNQ + 2*KD + h*KHD))[lane]);
        o0 += sc[j] * vf.x;
        o1 += sc[j] * vf.y;
    }
    ((__half2*)(g_attn_h + (size_t)row*KD + h*KHD))[lane] = __floats2half2_rn(o0 * inv, o1 * inv);
}

// ---------------- output scatter ----------------------------------------------
__global__ void k_scatter_feat(float* __restrict__ out) {
    __shared__ float tile[32][33];
    int b = blockIdx.z;
    int hw0 = blockIdx.x * 32, c0 = blockIdx.y * 32;
    int tx = threadIdx.x, ty = threadIdx.y;
    #pragma unroll
    for (int i = 0; i < 32; i += 8)
        tile[ty + i][tx] = g_res[((size_t)(b*KS + KR1 + hw0 + ty + i))*KD + c0 + tx];
    __syncthreads();
    #pragma unroll
    for (int i = 0; i < 32; i += 8)
        out[((size_t)b*KD + c0 + ty + i)*KHW + hw0 + tx] = tile[tx][ty + i];
}

__global__ void k_scatter_small(float* __restrict__ out) {
    const size_t FEAT = (size_t)KB * KD * KHW;
    const size_t CTXS = (size_t)KB * KD;
    int i = blockIdx.x * blockDim.x + threadIdx.x;
    if (i >= KB*KR1*KD) return;
    int c = i % KD;
    int t = (i / KD) % KR1;
    int b = i / (KD*KR1);
    float v = g_res[((size_t)(b*KS + t))*KD + c];
    if (t == 0) out[FEAT + (size_t)b*KD + c] = v;
    else        out[FEAT + CTXS + ((size_t)(b*(KR1-1) + (t-1)))*KD + c] = v;
}

// ---------------- launch -------------------------------------------------------
extern "C" void kernel_launch(void* const* d_in, const int* in_sizes, int n_in,
                              void* d_out, int out_size) {
    const float* x        = (const float*)d_in[0];
    const float* ctx      = (const float*)d_in[1];
    const float* reg      = (const float*)d_in[2];
    const float* in_pw    = (const float*)d_in[3];
    const float* in_pb    = (const float*)d_in[4];
    const float* out_w    = (const float*)d_in[5];
    const float* out_b    = (const float*)d_in[6];
    const float* ln1_g    = (const float*)d_in[7];
    const float* ln1_b    = (const float*)d_in[8];
    const float* ln2_g    = (const float*)d_in[9];
    const float* ln2_b    = (const float*)d_in[10];
    const float* w1       = (const float*)d_in[11];
    const float* b1       = (const float*)d_in[12];
    const float* w2       = (const float*)d_in[13];
    const float* b2       = (const float*)d_in[14];
    float* out = (float*)d_out;

    float *p_tokens, *p_xw, *p_h1, *p_res;
    __half *p_qkv, *p_xw_h, *p_attn_h, *p_ff_h, *p_mid_h, *p_wqkv, *p_wout, *p_w1, *p_w2;
    cudaGetSymbolAddress((void**)&p_tokens, g_tokens);
    cudaGetSymbolAddress((void**)&p_xw,     g_xw);
    cudaGetSymbolAddress((void**)&p_qkv,    g_qkv);
    cudaGetSymbolAddress((void**)&p_h1,     g_h1);
    cudaGetSymbolAddress((void**)&p_res,    g_res);
    cudaGetSymbolAddress((void**)&p_xw_h,   g_xw_h);
    cudaGetSymbolAddress((void**)&p_attn_h, g_attn_h);
    cudaGetSymbolAddress((void**)&p_ff_h,   g_ff_h);
    cudaGetSymbolAddress((void**)&p_mid_h,  g_mid_h);
    cudaGetSymbolAddress((void**)&p_wqkv,   g_wqkv_h);
    cudaGetSymbolAddress((void**)&p_wout,   g_wout_h);
    cudaGetSymbolAddress((void**)&p_w1,     g_w1_h);
    cudaGetSymbolAddress((void**)&p_w2,     g_w2_h);

    cudaFuncSetAttribute(k_gemmw<2>, cudaFuncAttributeMaxDynamicSharedMemorySize, WSMEM);
    cudaFuncSetAttribute(k_gemmw<3>, cudaFuncAttributeMaxDynamicSharedMemorySize, WSMEM);

    dim3 tb32(32, 8);
    const int MT = (KBS + 127) / 128;    // 65
    const int MT64 = (KBS + 63) / 64;    // 129

    // 1: transpose features into token rows
    k_transpose_in<<<dim3(KHW/32, KD/32, KB), tb32>>>(x);

    // 2: QKV weight conversion
    k_f2h4<<<(KNQ*KD/4 + 255)/256, 256>>>(in_pw, p_wqkv, KNQ*KD/4);

    // 3: LN1 (reads ctx/reg directly for token rows)
    k_layernorm<<<KBS, 256>>>(p_tokens, ctx, reg, ln1_g, ln1_b, p_xw, p_xw_h);

    // 4: QKV GEMM (wide, f32-acc, half output)  <-- profiled slot
    k_gemmw<3><<<dim3(KNQ/256, MT), 256, WSMEM>>>(
        p_xw_h, p_wqkv, in_pb, p_qkv, KBS, KNQ, KD);

    // attention
    k_attn_full<<<KB*KNH*KR1, 128>>>();
    k_attn_sparse<<<(KB*KHW*KNH)/8, 256>>>();

    // remaining weight conversions (one launch)
    {
        int na4 = KD*KD/4, nb4 = KDFF*KD/4, nc4 = KD*KDFF/4;
        int tot = na4 + nb4 + nc4;
        k_f2h_rest<<<(tot + 255)/256, 256>>>(out_w, p_wout, na4, w1, p_w1, nb4, w2, p_w2, nc4);
    }

    // out-proj + residual (h1 = attn@Wo + bo + xw) : 64-row tiles
    k_gemm64<1><<<dim3(KD/128, MT64), 256>>>(
        p_attn_h, p_wout, out_b, p_xw, p_h1, KBS, KD, KD);

    // LN2
    k_layernorm<<<KBS, 256>>>(p_h1, nullptr, nullptr, ln2_g, ln2_b, nullptr, p_ff_h);

    // FF1 + gelu (wide, half output)
    k_gemmw<2><<<dim3(KDFF/256, MT), 256, WSMEM>>>(
        p_ff_h, p_w1, b1, p_mid_h, KBS, KDFF, KD);

    // FF2 + residual (out = mid@W2 + b2 + h1) : 64-row tiles
    k_gemm64<1><<<dim3(KD/128, MT64), 256>>>(
        p_mid_h, p_w2, b2, p_h1, p_res, KBS, KD, KDFF);

    // scatter to output layout
    k_scatter_feat<<<dim3(KHW/32, KD/32, KB), tb32>>>(out);
    k_scatter_small<<<(KB*KR1*KD + 255)/256, 256>>>(out);
}

// round 12
// speedup vs baseline: 1.0290x; 1.0149x over previous
#include <cuda_runtime.h>
#include <cuda_fp16.h>
#include <math.h>
#include <stdint.h>

#define KB   8
#define KS   1029
#define KBS  (KB*KS)          // 8232
#define KD   768
#define KHW  1024
#define KNH  12
#define KHD  64
#define KR1  5
#define KDFF 3072
#define KNQ  2304
#define LN_EPS 1e-5f

// ---------------- device scratch (static: allocation-guard safe) -------------
__device__ float  g_tokens[KBS*KD];
__device__ float  g_xw[KBS*KD];
__device__ __half g_xw_h[KBS*KD];
__device__ __half g_qkv[(size_t)KBS*KNQ];
__device__ __half g_attn_h[KBS*KD];
__device__ float  g_h1[KBS*KD];
__device__ __half g_ff_h[KBS*KD];
__device__ __half g_mid_h[(size_t)KBS*KDFF];
__device__ float  g_res[KBS*KD];
__device__ float  g_part[KBS*KD];
__device__ __half g_wqkv_h[KNQ*KD];
__device__ __half g_wout_h[KD*KD];
__device__ __half g_w1_h[KDFF*KD];
__device__ __half g_w2_h[KD*KDFF];

// ---------------- helpers -----------------------------------------------------
__device__ __forceinline__ uint32_t smem_u32(const void* p) {
    return (uint32_t)__cvta_generic_to_shared(p);
}
__device__ __forceinline__ void ldsm_x4(uint32_t& r0, uint32_t& r1, uint32_t& r2, uint32_t& r3, uint32_t addr) {
    asm volatile("ldmatrix.sync.aligned.m8n8.x4.shared.b16 {%0,%1,%2,%3}, [%4];\n"
                 : "=r"(r0), "=r"(r1), "=r"(r2), "=r"(r3) : "r"(addr));
}
__device__ __forceinline__ void mma_16816(float* d, const uint32_t* a, const uint32_t* b) {
    asm volatile("mma.sync.aligned.m16n8k16.row.col.f32.f16.f16.f32 "
                 "{%0,%1,%2,%3}, {%4,%5,%6,%7}, {%8,%9}, {%0,%1,%2,%3};\n"
                 : "+f"(d[0]), "+f"(d[1]), "+f"(d[2]), "+f"(d[3])
                 : "r"(a[0]), "r"(a[1]), "r"(a[2]), "r"(a[3]), "r"(b[0]), "r"(b[1]));
}
__device__ __forceinline__ void cpasync16(uint32_t d, const void* g) {
    asm volatile("cp.async.cg.shared.global [%0], [%1], 16;\n" :: "r"(d), "l"(g));
}
__device__ __forceinline__ float gelu_exact(float x) {
    return 0.5f * x * (1.0f + erff(x * 0.70710678118654752f));
}

// ---------------- prep: transpose features into token matrix -----------------
__global__ void k_transpose_in(const float* __restrict__ x) {
    __shared__ float tile[32][33];
    int b = blockIdx.z;
    int hw0 = blockIdx.x * 32, c0 = blockIdx.y * 32;
    int tx = threadIdx.x, ty = threadIdx.y;
    #pragma unroll
    for (int i = 0; i < 32; i += 8)
        tile[ty + i][tx] = x[((size_t)b*KD + c0 + ty + i)*KHW + hw0 + tx];
    __syncthreads();
    #pragma unroll
    for (int i = 0; i < 32; i += 8)
        g_tokens[((size_t)(b*KS + KR1 + hw0 + ty + i))*KD + c0 + tx] = tile[tx][ty + i];
}

// ---------------- layernorm (row = 768, block 256) ----------------------------
__global__ void k_layernorm(const float* __restrict__ in,
                            const float* __restrict__ ctx, const float* __restrict__ reg,
                            const float* __restrict__ gma, const float* __restrict__ bta,
                            float* __restrict__ outf, __half* __restrict__ outh) {
    int row = blockIdx.x;
    const float* p = in + (size_t)row * KD;
    if (ctx) {
        int b = row / KS, t = row - b * KS;
        if (t < KR1)
            p = (t == 0) ? (ctx + (size_t)b * KD)
                         : (reg + ((size_t)b * (KR1-1) + (t-1)) * KD);
    }
    int tid = threadIdx.x;
    int lane = tid & 31, warp = tid >> 5;
    float v0 = p[tid], v1 = p[tid + 256], v2 = p[tid + 512];
    float s = v0 + v1 + v2;
    __shared__ float red[8];
    __shared__ float s_mu, s_rstd;
    #pragma unroll
    for (int o = 16; o; o >>= 1) s += __shfl_xor_sync(0xffffffffu, s, o);
    if (lane == 0) red[warp] = s;
    __syncthreads();
    if (tid == 0) {
        float t = 0;
        #pragma unroll
        for (int i = 0; i < 8; i++) t += red[i];
        s_mu = t * (1.0f / KD);
    }
    __syncthreads();
    float mu = s_mu;
    float d0 = v0 - mu, d1 = v1 - mu, d2 = v2 - mu;
    float q = d0*d0 + d1*d1 + d2*d2;
    #pragma unroll
    for (int o = 16; o; o >>= 1) q += __shfl_xor_sync(0xffffffffu, q, o);
    if (lane == 0) red[warp] = q;
    __syncthreads();
    if (tid == 0) {
        float t = 0;
        #pragma unroll
        for (int i = 0; i < 8; i++) t += red[i];
        s_rstd = rsqrtf(t * (1.0f / KD) + LN_EPS);
    }
    __syncthreads();
    float r = s_rstd;
    #pragma unroll
    for (int i = 0; i < 3; i++) {
        int c = tid + i * 256;
        float vv = (i == 0) ? v0 : (i == 1) ? v1 : v2;
        float o = (vv - mu) * r * gma[c] + bta[c];
        if (outf) outf[(size_t)row*KD + c] = o;
        outh[(size_t)row*KD + c] = __float2half(o);
    }
}

// ---------------- f32 -> f16 (vectorized) --------------------------------------
__global__ void k_f2h4(const float* __restrict__ in, __half* __restrict__ out, int n4) {
    int i = blockIdx.x * blockDim.x + threadIdx.x;
    if (i >= n4) return;
    float4 v = ((const float4*)in)[i];
    ((__half2*)out)[i*2]   = __floats2half2_rn(v.x, v.y);
    ((__half2*)out)[i*2+1] = __floats2half2_rn(v.z, v.w);
}

__global__ void k_f2h_rest(const float* __restrict__ a, __half* __restrict__ oa, int na4,
                           const float* __restrict__ b, __half* __restrict__ ob, int nb4,
                           const float* __restrict__ c, __half* __restrict__ oc, int nc4) {
    int i = blockIdx.x * blockDim.x + threadIdx.x;
    const float* src; __half* dst; int j = i;
    if (j < na4) { src = a; dst = oa; }
    else {
        j -= na4;
        if (j < nb4) { src = b; dst = ob; }
        else { j -= nb4; if (j >= nc4) return; src = c; dst = oc; }
    }
    float4 v = ((const float4*)src)[j];
    ((__half2*)dst)[j*2]   = __floats2half2_rn(v.x, v.y);
    ((__half2*)dst)[j*2+1] = __floats2half2_rn(v.z, v.w);
}

#define SSTR 72                       // half stride (144B rows) conflict-free ldmatrix

// ============ WIDE GEMM (f32 acc): 128x256, warp 64x64, NSTG=3 ================
// EPI 2: Ch = gelu(acc + bias) ; EPI 3: Ch = acc + bias
#define WASTGH (128*SSTR)
#define WBSTGH (256*SSTR)
#define WNSTG 3
#define WSMEM ((WNSTG*(WASTGH+WBSTGH))*2)   // 165888 B

template<int EPI>
__global__ void __launch_bounds__(256) k_gemmw(
    const __half* __restrict__ A, const __half* __restrict__ Wt,
    const float* __restrict__ bias,
    __half* __restrict__ Ch,
    int M, int N, int K)
{
    extern __shared__ char smemraw[];
    __half* As = (__half*)smemraw;
    __half* Bs = As + WNSTG * WASTGH;
    int tid = threadIdx.x;
    int lane = tid & 31, warp = tid >> 5;
    int wm = warp & 1, wn = warp >> 1;       // warp tile 64(m) x 64(n)
    int m0 = blockIdx.y * 128, n0 = blockIdx.x * 256;
    const int nIter = K / 64;

    float acc[4][8][4];
    #pragma unroll
    for (int i = 0; i < 4; i++)
        #pragma unroll
        for (int j = 0; j < 8; j++)
            #pragma unroll
            for (int c = 0; c < 4; c++) acc[i][j][c] = 0.f;

    int cr = tid >> 3;
    int cc = (tid & 7) << 3;

    auto load_stage = [&](int iter, int st) {
        int k0 = iter * 64;
        uint32_t abase = smem_u32(As + st * WASTGH);
        uint32_t bbase = smem_u32(Bs + st * WBSTGH);
        #pragma unroll
        for (int h = 0; h < 4; h++) {
            int r = cr + h * 32;
            int gm = m0 + r; if (gm > M-1) gm = M-1;
            cpasync16(abase + (r * SSTR + cc) * 2, A + (size_t)gm * K + k0 + cc);
        }
        #pragma unroll
        for (int h = 0; h < 8; h++) {
            int r = cr + h * 32;
            cpasync16(bbase + (r * SSTR + cc) * 2, Wt + (size_t)(n0 + r) * K + k0 + cc);
        }
        asm volatile("cp.async.commit_group;\n" ::: "memory");
    };

    load_stage(0, 0);
    load_stage(1, 1);

    int a_rl = (lane & 15);
    int a_co = (lane & 16) ? 8 : 0;
    int b_rl = (lane & 7) + ((lane & 16) ? 8 : 0);
    int b_co = (lane & 8) ? 8 : 0;

    int s = 0;
    for (int i = 0; i < nIter; i++) {
        asm volatile("cp.async.wait_group 1;\n" ::: "memory");
        __syncthreads();
        const __half* as = As + s * WASTGH;
        const __half* bs = Bs + s * WBSTGH;
        int j = i + 2;
        int sj = s + 2; if (sj >= WNSTG) sj -= WNSTG;

        #pragma unroll
        for (int ks = 0; ks < 4; ks++) {
            uint32_t afr[4][4];
            #pragma unroll
            for (int mi = 0; mi < 4; mi++) {
                uint32_t addr = smem_u32(as + (wm*64 + mi*16 + a_rl) * SSTR + ks*16 + a_co);
                ldsm_x4(afr[mi][0], afr[mi][1], afr[mi][2], afr[mi][3], addr);
            }
            #pragma unroll
            for (int nb = 0; nb < 4; nb++) {
                uint32_t addr = smem_u32(bs + (wn*64 + nb*16 + b_rl) * SSTR + ks*16 + b_co);
                uint32_t b0[2], b1[2];
                ldsm_x4(b0[0], b0[1], b1[0], b1[1], addr);
                #pragma unroll
                for (int mi = 0; mi < 4; mi++) {
                    mma_16816(acc[mi][nb*2],   afr[mi], b0);
                    mma_16816(acc[mi][nb*2+1], afr[mi], b1);
                }
            }
            if (ks == 1 && j < nIter) load_stage(j, sj);
        }
        if (j >= nIter)
            asm volatile("cp.async.commit_group;\n" ::: "memory");
        if (++s == WNSTG) s = 0;
    }

    __syncthreads();

    #pragma unroll
    for (int mi = 0; mi < 4; mi++) {
        int rbase = m0 + wm*64 + mi*16 + (lane >> 2);
        #pragma unroll
        for (int ni = 0; ni < 8; ni++) {
            int col = n0 + wn*64 + ni*8 + ((lane & 3) << 1);
            float bx = __ldg(bias + col), by = __ldg(bias + col + 1);
            #pragma unroll
            for (int hh = 0; hh < 2; hh++) {
                int row = rbase + hh * 8;
                if (row < M) {
                    float v0 = acc[mi][ni][hh*2 + 0] + bx;
                    float v1 = acc[mi][ni][hh*2 + 1] + by;
                    if constexpr (EPI == 2) { v0 = gelu_exact(v0); v1 = gelu_exact(v1); }
                    *(__half2*)(Ch + (size_t)row * N + col) = __floats2half2_rn(v0, v1);
                }
            }
        }
    }
}

// ============ NARROW GEMM (proven R8/R9): 128x128, warp 32x64, NSTG=3 =========
// Split-K via gridDim.z: z=0 writes Cf = acc + bias + res; z>0 writes Pf = acc.
#define GBM 128
#define GBN 128
#define NSTG 3
#define ASTGH (GBM*SSTR)              // 9216 halfs per stage side

__global__ void __launch_bounds__(256, 2) k_gemm(
    const __half* __restrict__ A, const __half* __restrict__ Wt,
    const float* __restrict__ bias, const float* __restrict__ res,
    float* __restrict__ Cf, float* __restrict__ Pf,
    int M, int N, int K)
{
    __shared__ __half As[NSTG * ASTGH];
    __shared__ __half Bs[NSTG * ASTGH];
    int tid = threadIdx.x;
    int lane = tid & 31, warp = tid >> 5;
    int wm = warp & 3, wn = warp >> 2;       // warp tile 32(m) x 64(n)
    int m0 = blockIdx.y * GBM, n0 = blockIdx.x * GBN;
    const int kLen = K / gridDim.z;
    const int kBase = blockIdx.z * kLen;
    const int nIter = kLen / 64;

    float acc[2][8][4];
    #pragma unroll
    for (int i = 0; i < 2; i++)
        #pragma unroll
        for (int j = 0; j < 8; j++)
            #pragma unroll
            for (int c = 0; c < 4; c++) acc[i][j][c] = 0.f;

    int cr = tid >> 3;
    int cc = (tid & 7) << 3;

    auto load_stage = [&](int iter, int st) {
        int k0 = kBase + iter * 64;
        uint32_t abase = smem_u32(As + st * ASTGH);
        uint32_t bbase = smem_u32(Bs + st * ASTGH);
        #pragma unroll
        for (int h = 0; h < 4; h++) {
            int r = cr + h * 32;
            int gm = m0 + r; if (gm > M-1) gm = M-1;
            cpasync16(abase + (r * SSTR + cc) * 2, A + (size_t)gm * K + k0 + cc);
            cpasync16(bbase + (r * SSTR + cc) * 2, Wt + (size_t)(n0 + r) * K + k0 + cc);
        }
        asm volatile("cp.async.commit_group;\n" ::: "memory");
    };

    load_stage(0, 0);
    load_stage(1, 1);

    int a_rl = (lane & 15);
    int a_co = (lane & 16) ? 8 : 0;
    int b_rl = (lane & 7) + ((lane & 16) ? 8 : 0);
    int b_co = (lane & 8) ? 8 : 0;

    int s = 0;
    for (int i = 0; i < nIter; i++) {
        asm volatile("cp.async.wait_group 1;\n" ::: "memory");
        __syncthreads();
        const __half* as = As + s * ASTGH;
        const __half* bs = Bs + s * ASTGH;
        int j = i + 2;
        int sj = s + 2; if (sj >= NSTG) sj -= NSTG;

        #pragma unroll
        for (int ks = 0; ks < 4; ks++) {
            uint32_t afr[2][4];
            #pragma unroll
            for (int mi = 0; mi < 2; mi++) {
                uint32_t addr = smem_u32(as + (wm*32 + mi*16 + a_rl) * SSTR + ks*16 + a_co);
                ldsm_x4(afr[mi][0], afr[mi][1], afr[mi][2], afr[mi][3], addr);
            }
            uint32_t bfr[8][2];
            #pragma unroll
            for (int nb = 0; nb < 4; nb++) {
                uint32_t addr = smem_u32(bs + (wn*64 + nb*16 + b_rl) * SSTR + ks*16 + b_co);
                uint32_t r0, r1, r2, r3;
                ldsm_x4(r0, r1, r2, r3, addr);
                bfr[nb*2][0] = r0; bfr[nb*2][1] = r1;
                bfr[nb*2+1][0] = r2; bfr[nb*2+1][1] = r3;
            }
            #pragma unroll
            for (int mi = 0; mi < 2; mi++)
                #pragma unroll
                for (int ni = 0; ni < 8; ni++)
                    mma_16816(acc[mi][ni], afr[mi], bfr[ni]);

            if (ks == 1 && j < nIter) load_stage(j, sj);
        }
        if (j >= nIter)
            asm volatile("cp.async.commit_group;\n" ::: "memory");
        if (++s == NSTG) s = 0;
    }

    __syncthreads();

    bool main_split = (blockIdx.z == 0);
    #pragma unroll
    for (int mi = 0; mi < 2; mi++) {
        int rbase = m0 + wm*32 + mi*16 + (lane >> 2);
        #pragma unroll
        for (int ni = 0; ni < 8; ni++) {
            int col = n0 + wn*64 + ni*8 + ((lane & 3) << 1);
            #pragma unroll
            for (int hh = 0; hh < 2; hh++) {
                int row = rbase + hh * 8;
                if (row < M) {
                    float v0 = acc[mi][ni][hh*2 + 0];
                    float v1 = acc[mi][ni][hh*2 + 1];
                    if (main_split) {
                        v0 += __ldg(bias + col) + __ldg(res + (size_t)row * N + col);
                        v1 += __ldg(bias + col + 1) + __ldg(res + (size_t)row * N + col + 1);
                        Cf[(size_t)row * N + col]     = v0;
                        Cf[(size_t)row * N + col + 1] = v1;
                    } else {
                        Pf[(size_t)row * N + col]     = v0;
                        Pf[(size_t)row * N + col + 1] = v1;
                    }
                }
            }
        }
    }
}

// ---------------- attention: full rows (queries 0..4), 128 threads ------------
__global__ void k_attn_full() {
    int idx = blockIdx.x;
    int qi = idx % KR1; idx /= KR1;
    int h = idx % KNH;
    int b = idx / KNH;
    int tid = threadIdx.x;          // 128
    int lane = tid & 31, warp = tid >> 5;
    int row = b*KS + qi;

    __shared__ float sc[KS];
    __shared__ float qsh[KHD];
    __shared__ float wredm[4], wreds[4];
    __shared__ float osh[64];

    if (tid < KHD) qsh[tid] = __half2float(g_qkv[(size_t)row*KNQ + h*KHD + tid]);
    __syncthreads();

    for (int j = tid; j < KS; j += 128) {
        const __half2* kp = (const __half2*)(g_qkv + (size_t)(b*KS + j)*KNQ + KD + h*KHD);
        float s = 0.f;
        #pragma unroll 8
        for (int d = 0; d < KHD/2; d++) {
            float2 kf = __half22float2(kp[d]);
            s += qsh[2*d] * kf.x + qsh[2*d+1] * kf.y;
        }
        sc[j] = s * 0.125f;
    }
    __syncthreads();

    float m = -1e30f;
    for (int j = tid; j < KS; j += 128) m = fmaxf(m, sc[j]);
    #pragma unroll
    for (int o = 16; o; o >>= 1) m = fmaxf(m, __shfl_xor_sync(0xffffffffu, m, o));
    if (lane == 0) wredm[warp] = m;
    __syncthreads();
    m = fmaxf(fmaxf(wredm[0], wredm[1]), fmaxf(wredm[2], wredm[3]));

    float sum = 0.f;
    for (int j = tid; j < KS; j += 128) { float e = expf(sc[j] - m); sc[j] = e; sum += e; }
    #pragma unroll
    for (int o = 16; o; o >>= 1) sum += __shfl_xor_sync(0xffffffffu, sum, o);
    if (lane == 0) wreds[warp] = sum;
    __syncthreads();
    float inv = 1.0f / (wreds[0] + wreds[1] + wreds[2] + wreds[3]);

    int half = tid >> 6, d = tid & 63;
    float o = 0.f;
    for (int j = half; j < KS; j += 2)
        o += sc[j] * __half2float(g_qkv[(size_t)(b*KS + j)*KNQ + 2*KD + h*KHD + d]);
    if (half) osh[d] = o;
    __syncthreads();
    if (tid < 64)
        g_attn_h[(size_t)row*KD + h*KHD + tid] = __float2half((o + osh[tid]) * inv);
}

// ---------------- attention: sparse rows (feature tokens) ---------------------
__global__ void k_attn_sparse() {
    int gw = (blockIdx.x * blockDim.x + threadIdx.x) >> 5;
    int lane = threadIdx.x & 31;
    if (gw >= KB*KHW*KNH) return;
    int h = gw % KNH; int rest = gw / KNH;
    int f = rest % KHW; int b = rest / KHW;
    int row = b*KS + KR1 + f;

    float2 qf = __half22float2(((const __half2*)(g_qkv + (size_t)row*KNQ + h*KHD))[lane]);

    float sc[6];
    #pragma unroll
    for (int j = 0; j < 6; j++) {
        int krow = (j < 5) ? (b*KS + j) : row;
        float2 kf = __half22float2(
            ((const __half2*)(g_qkv + (size_t)krow*KNQ + KD + h*KHD))[lane]);
        float p = qf.x*kf.x + qf.y*kf.y;
        #pragma unroll
        for (int o = 16; o; o >>= 1) p += __shfl_xor_sync(0xffffffffu, p, o);
        sc[j] = p * 0.125f;
    }
    float m = sc[0];
    #pragma unroll
    for (int j = 1; j < 6; j++) m = fmaxf(m, sc[j]);
    float sum = 0.f;
    #pragma unroll
    for (int j = 0; j < 6; j++) { sc[j] = expf(sc[j] - m); sum += sc[j]; }
    float inv = 1.0f / sum;

    float o0 = 0.f, o1 = 0.f;
    #pragma unroll
    for (int j = 0; j < 6; j++) {
        int krow = (j < 5) ? (b*KS + j) : row;
        float2 vf = __half22float2(
            ((const __half2*)(g_qkv + (size_t)krow*KNQ + 2*KD + h*KHD))[lane]);
        o0 += sc[j] * vf.x;
        o1 += sc[j] * vf.y;
    }
    ((__half2*)(g_attn_h + (size_t)row*KD + h*KHD))[lane] = __floats2half2_rn(o0 * inv, o1 * inv);
}

// ---------------- output scatter (adds split-K partial) -----------------------
__global__ void k_scatter_feat(float* __restrict__ out) {
    __shared__ float tile[32][33];
    int b = blockIdx.z;
    int hw0 = blockIdx.x * 32, c0 = blockIdx.y * 32;
    int tx = threadIdx.x, ty = threadIdx.y;
    #pragma unroll
    for (int i = 0; i < 32; i += 8) {
        size_t idx = ((size_t)(b*KS + KR1 + hw0 + ty + i))*KD + c0 + tx;
        tile[ty + i][tx] = g_res[idx] + g_part[idx];
    }
    __syncthreads();
    #pragma unroll
    for (int i = 0; i < 32; i += 8)
        out[((size_t)b*KD + c0 + ty + i)*KHW + hw0 + tx] = tile[tx][ty + i];
}

__global__ void k_scatter_small(float* __restrict__ out) {
    const size_t FEAT = (size_t)KB * KD * KHW;
    const size_t CTXS = (size_t)KB * KD;
    int i = blockIdx.x * blockDim.x + threadIdx.x;
    if (i >= KB*KR1*KD) return;
    int c = i % KD;
    int t = (i / KD) % KR1;
    int b = i / (KD*KR1);
    size_t idx = ((size_t)(b*KS + t))*KD + c;
    float v = g_res[idx] + g_part[idx];
    if (t == 0) out[FEAT + (size_t)b*KD + c] = v;
    else        out[FEAT + CTXS + ((size_t)(b*(KR1-1) + (t-1)))*KD + c] = v;
}

// ---------------- launch -------------------------------------------------------
extern "C" void kernel_launch(void* const* d_in, const int* in_sizes, int n_in,
                              void* d_out, int out_size) {
    const float* x        = (const float*)d_in[0];
    const float* ctx      = (const float*)d_in[1];
    const float* reg      = (const float*)d_in[2];
    const float* in_pw    = (const float*)d_in[3];
    const float* in_pb    = (const float*)d_in[4];
    const float* out_w    = (const float*)d_in[5];
    const float* out_b    = (const float*)d_in[6];
    const float* ln1_g    = (const float*)d_in[7];
    const float* ln1_b    = (const float*)d_in[8];
    const float* ln2_g    = (const float*)d_in[9];
    const float* ln2_b    = (const float*)d_in[10];
    const float* w1       = (const float*)d_in[11];
    const float* b1       = (const float*)d_in[12];
    const float* w2       = (const float*)d_in[13];
    const float* b2       = (const float*)d_in[14];
    float* out = (float*)d_out;

    float *p_tokens, *p_xw, *p_h1, *p_res, *p_part;
    __half *p_qkv, *p_xw_h, *p_attn_h, *p_ff_h, *p_mid_h, *p_wqkv, *p_wout, *p_w1, *p_w2;
    cudaGetSymbolAddress((void**)&p_tokens, g_tokens);
    cudaGetSymbolAddress((void**)&p_xw,     g_xw);
    cudaGetSymbolAddress((void**)&p_qkv,    g_qkv);
    cudaGetSymbolAddress((void**)&p_h1,     g_h1);
    cudaGetSymbolAddress((void**)&p_res,    g_res);
    cudaGetSymbolAddress((void**)&p_part,   g_part);
    cudaGetSymbolAddress((void**)&p_xw_h,   g_xw_h);
    cudaGetSymbolAddress((void**)&p_attn_h, g_attn_h);
    cudaGetSymbolAddress((void**)&p_ff_h,   g_ff_h);
    cudaGetSymbolAddress((void**)&p_mid_h,  g_mid_h);
    cudaGetSymbolAddress((void**)&p_wqkv,   g_wqkv_h);
    cudaGetSymbolAddress((void**)&p_wout,   g_wout_h);
    cudaGetSymbolAddress((void**)&p_w1,     g_w1_h);
    cudaGetSymbolAddress((void**)&p_w2,     g_w2_h);

    cudaFuncSetAttribute(k_gemmw<2>, cudaFuncAttributeMaxDynamicSharedMemorySize, WSMEM);
    cudaFuncSetAttribute(k_gemmw<3>, cudaFuncAttributeMaxDynamicSharedMemorySize, WSMEM);

    dim3 tb32(32, 8);
    const int MT = (KBS + 127) / 128;    // 65

    // 1: transpose features into token rows
    k_transpose_in<<<dim3(KHW/32, KD/32, KB), tb32>>>(x);

    // 2: QKV weight conversion
    k_f2h4<<<(KNQ*KD/4 + 255)/256, 256>>>(in_pw, p_wqkv, KNQ*KD/4);

    // 3: LN1 (reads ctx/reg directly for token rows)
    k_layernorm<<<KBS, 256>>>(p_tokens, ctx, reg, ln1_g, ln1_b, p_xw, p_xw_h);

    // 4: QKV GEMM (wide, f32-acc, half output)  <-- profiled slot
    k_gemmw<3><<<dim3(KNQ/256, MT), 256, WSMEM>>>(
        p_xw_h, p_wqkv, in_pb, p_qkv, KBS, KNQ, KD);

    // attention
    k_attn_full<<<KB*KNH*KR1, 128>>>();
    k_attn_sparse<<<(KB*KHW*KNH)/8, 256>>>();

    // remaining weight conversions (one launch)
    {
        int na4 = KD*KD/4, nb4 = KDFF*KD/4, nc4 = KD*KDFF/4;
        int tot = na4 + nb4 + nc4;
        k_f2h_rest<<<(tot + 255)/256, 256>>>(out_w, p_wout, na4, w1, p_w1, nb4, w2, p_w2, nc4);
    }

    // out-proj + residual (h1 = attn@Wo + bo + xw), no split (z=1)
    k_gemm<<<dim3(KD/GBN, MT, 1), 256>>>(
        p_attn_h, p_wout, out_b, p_xw, p_h1, nullptr, KBS, KD, KD);

    // LN2
    k_layernorm<<<KBS, 256>>>(p_h1, nullptr, nullptr, ln2_g, ln2_b, nullptr, p_ff_h);

    // FF1 + gelu (wide, half output)
    k_gemmw<2><<<dim3(KDFF/256, MT), 256, WSMEM>>>(
        p_ff_h, p_w1, b1, p_mid_h, KBS, KDFF, KD);

    // FF2 split-K=2: z=0 -> g_res = acc + b2 + h1 ; z=1 -> g_part = acc
    k_gemm<<<dim3(KD/GBN, MT, 2), 256>>>(
        p_mid_h, p_w2, b2, p_h1, p_res, p_part, KBS, KD, KDFF);

    // scatter to output layout (adds g_part)
    k_scatter_feat<<<dim3(KHW/32, KD/32, KB), tb32>>>(out);
    k_scatter_small<<<(KB*KR1*KD + 255)/256, 256>>>(out);
}

// round 13
// speedup vs baseline: 1.0584x; 1.0286x over previous
#include <cuda_runtime.h>
#include <cuda_fp16.h>
#include <math.h>
#include <stdint.h>

#define KB   8
#define KS   1029
#define KBS  (KB*KS)          // 8232
#define KD   768
#define KHW  1024
#define KNH  12
#define KHD  64
#define KR1  5
#define KDFF 3072
#define KNQ  2304
#define LN_EPS 1e-5f

// ---------------- device scratch (static: allocation-guard safe) -------------
__device__ float  g_xw[KBS*KD];
__device__ __half g_xw_h[KBS*KD];
__device__ __half g_qkv[(size_t)KBS*KNQ];
__device__ __half g_attn_h[KBS*KD];
__device__ float  g_h1[KBS*KD];
__device__ __half g_ff_h[KBS*KD];
__device__ __half g_mid_h[(size_t)KBS*KDFF];
__device__ float  g_res[KBS*KD];
__device__ __half g_wqkv_h[KNQ*KD];
__device__ __half g_wout_h[KD*KD];
__device__ __half g_w1_h[KDFF*KD];
__device__ __half g_w2_h[KD*KDFF];

// ---------------- helpers -----------------------------------------------------
__device__ __forceinline__ uint32_t smem_u32(const void* p) {
    return (uint32_t)__cvta_generic_to_shared(p);
}
__device__ __forceinline__ void ldsm_x4(uint32_t& r0, uint32_t& r1, uint32_t& r2, uint32_t& r3, uint32_t addr) {
    asm volatile("ldmatrix.sync.aligned.m8n8.x4.shared.b16 {%0,%1,%2,%3}, [%4];\n"
                 : "=r"(r0), "=r"(r1), "=r"(r2), "=r"(r3) : "r"(addr));
}
__device__ __forceinline__ void mma_16816(float* d, const uint32_t* a, const uint32_t* b) {
    asm volatile("mma.sync.aligned.m16n8k16.row.col.f32.f16.f16.f32 "
                 "{%0,%1,%2,%3}, {%4,%5,%6,%7}, {%8,%9}, {%0,%1,%2,%3};\n"
                 : "+f"(d[0]), "+f"(d[1]), "+f"(d[2]), "+f"(d[3])
                 : "r"(a[0]), "r"(a[1]), "r"(a[2]), "r"(a[3]), "r"(b[0]), "r"(b[1]));
}
__device__ __forceinline__ void cpasync16(uint32_t d, const void* g) {
    asm volatile("cp.async.cg.shared.global [%0], [%1], 16;\n" :: "r"(d), "l"(g));
}
__device__ __forceinline__ float gelu_exact(float x) {
    return 0.5f * x * (1.0f + erff(x * 0.70710678118654752f));
}

// ---------------- fused LN1 over feature tokens (reads NCHW x directly) -------
// grid (KHW/32, KB), 256 threads. Block = 32 hw rows x 768 channels.
// dynamic smem: tile[768*33] floats + mu[32] + rstd[32]
#define LN1_SMEM ((768*33 + 64) * 4)
__global__ void k_ln1_feat(const float* __restrict__ x,
                           const float* __restrict__ gma, const float* __restrict__ bta,
                           float* __restrict__ outf, __half* __restrict__ outh) {
    extern __shared__ float tile[];
    float* smu = tile + 768*33;
    float* srs = smu + 32;
    int b = blockIdx.y, hw0 = blockIdx.x * 32;
    int tid = threadIdx.x;
    int w = tid >> 5, l = tid & 31;

    // load: warp w handles channels c = w + 8k, lane = hw offset (coalesced)
    #pragma unroll 8
    for (int k = 0; k < 96; k++) {
        int c = w + 8*k;
        tile[c*33 + l] = x[(((size_t)b*KD + c) << 10) + hw0 + l];
    }
    __syncthreads();

    // stats: warp w handles rows 4w..4w+3
    #pragma unroll
    for (int rr = 0; rr < 4; rr++) {
        int row = w*4 + rr;
        float s = 0.f, q = 0.f;
        #pragma unroll
        for (int k = 0; k < 24; k++) {
            float v = tile[(l + 32*k)*33 + row];
            s += v; q += v*v;
        }
        #pragma unroll
        for (int o = 16; o; o >>= 1) {
            s += __shfl_xor_sync(0xffffffffu, s, o);
            q += __shfl_xor_sync(0xffffffffu, q, o);
        }
        if (l == 0) {
            float mu = s * (1.0f/KD);
            smu[row] = mu;
            srs[row] = rsqrtf(q * (1.0f/KD) - mu*mu + LN_EPS);
        }
    }
    __syncthreads();

    // write: warp w rows 4w..4w+3, lane over channels (coalesced)
    #pragma unroll
    for (int rr = 0; rr < 4; rr++) {
        int row = w*4 + rr;
        float mu = smu[row], rs = srs[row];
        size_t gbase = ((size_t)(b*KS + KR1 + hw0 + row))*KD;
        #pragma unroll 4
        for (int i = 0; i < 24; i++) {
            int c = l + 32*i;
            float v = (tile[c*33 + row] - mu) * rs * __ldg(gma + c) + __ldg(bta + c);
            outf[gbase + c] = v;
            outh[gbase + c] = __float2half(v);
        }
    }
}

// ---------------- LN1 for token rows (ctx + registers), grid KB*KR1 -----------
__global__ void k_ln1_tok(const float* __restrict__ ctx, const float* __restrict__ reg,
                          const float* __restrict__ gma, const float* __restrict__ bta,
                          float* __restrict__ outf, __half* __restrict__ outh) {
    int rb = blockIdx.x;
    int b = rb / KR1, t = rb % KR1;
    const float* p = (t == 0) ? (ctx + (size_t)b*KD)
                              : (reg + ((size_t)b*(KR1-1) + (t-1))*KD);
    size_t row = (size_t)b*KS + t;
    int tid = threadIdx.x;
    int lane = tid & 31, warp = tid >> 5;
    float v0 = p[tid], v1 = p[tid + 256], v2 = p[tid + 512];
    float s = v0 + v1 + v2;
    __shared__ float red[8];
    __shared__ float s_mu, s_rstd;
    #pragma unroll
    for (int o = 16; o; o >>= 1) s += __shfl_xor_sync(0xffffffffu, s, o);
    if (lane == 0) red[warp] = s;
    __syncthreads();
    if (tid == 0) {
        float t2 = 0;
        #pragma unroll
        for (int i = 0; i < 8; i++) t2 += red[i];
        s_mu = t2 * (1.0f / KD);
    }
    __syncthreads();
    float mu = s_mu;
    float d0 = v0 - mu, d1 = v1 - mu, d2 = v2 - mu;
    float q = d0*d0 + d1*d1 + d2*d2;
    #pragma unroll
    for (int o = 16; o; o >>= 1) q += __shfl_xor_sync(0xffffffffu, q, o);
    if (lane == 0) red[warp] = q;
    __syncthreads();
    if (tid == 0) {
        float t2 = 0;
        #pragma unroll
        for (int i = 0; i < 8; i++) t2 += red[i];
        s_rstd = rsqrtf(t2 * (1.0f / KD) + LN_EPS);
    }
    __syncthreads();
    float r = s_rstd;
    #pragma unroll
    for (int i = 0; i < 3; i++) {
        int c = tid + i * 256;
        float vv = (i == 0) ? v0 : (i == 1) ? v1 : v2;
        float o = (vv - mu) * r * gma[c] + bta[c];
        outf[row*KD + c] = o;
        outh[row*KD + c] = __float2half(o);
    }
}

// ---------------- layernorm (row = 768, block 256) — LN2 ---------------------
__global__ void k_layernorm(const float* __restrict__ in,
                            const float* __restrict__ gma, const float* __restrict__ bta,
                            __half* __restrict__ outh) {
    int row = blockIdx.x;
    const float* p = in + (size_t)row * KD;
    int tid = threadIdx.x;
    int lane = tid & 31, warp = tid >> 5;
    float v0 = p[tid], v1 = p[tid + 256], v2 = p[tid + 512];
    float s = v0 + v1 + v2;
    __shared__ float red[8];
    __shared__ float s_mu, s_rstd;
    #pragma unroll
    for (int o = 16; o; o >>= 1) s += __shfl_xor_sync(0xffffffffu, s, o);
    if (lane == 0) red[warp] = s;
    __syncthreads();
    if (tid == 0) {
        float t = 0;
        #pragma unroll
        for (int i = 0; i < 8; i++) t += red[i];
        s_mu = t * (1.0f / KD);
    }
    __syncthreads();
    float mu = s_mu;
    float d0 = v0 - mu, d1 = v1 - mu, d2 = v2 - mu;
    float q = d0*d0 + d1*d1 + d2*d2;
    #pragma unroll
    for (int o = 16; o; o >>= 1) q += __shfl_xor_sync(0xffffffffu, q, o);
    if (lane == 0) red[warp] = q;
    __syncthreads();
    if (tid == 0) {
        float t = 0;
        #pragma unroll
        for (int i = 0; i < 8; i++) t += red[i];
        s_rstd = rsqrtf(t * (1.0f / KD) + LN_EPS);
    }
    __syncthreads();
    float r = s_rstd;
    #pragma unroll
    for (int i = 0; i < 3; i++) {
        int c = tid + i * 256;
        float vv = (i == 0) ? v0 : (i == 1) ? v1 : v2;
        float o = (vv - mu) * r * gma[c] + bta[c];
        outh[(size_t)row*KD + c] = __float2half(o);
    }
}

// ---------------- f32 -> f16 (vectorized) --------------------------------------
__global__ void k_f2h4(const float* __restrict__ in, __half* __restrict__ out, int n4) {
    int i = blockIdx.x * blockDim.x + threadIdx.x;
    if (i >= n4) return;
    float4 v = ((const float4*)in)[i];
    ((__half2*)out)[i*2]   = __floats2half2_rn(v.x, v.y);
    ((__half2*)out)[i*2+1] = __floats2half2_rn(v.z, v.w);
}

__global__ void k_f2h_rest(const float* __restrict__ a, __half* __restrict__ oa, int na4,
                           const float* __restrict__ b, __half* __restrict__ ob, int nb4,
                           const float* __restrict__ c, __half* __restrict__ oc, int nc4) {
    int i = blockIdx.x * blockDim.x + threadIdx.x;
    const float* src; __half* dst; int j = i;
    if (j < na4) { src = a; dst = oa; }
    else {
        j -= na4;
        if (j < nb4) { src = b; dst = ob; }
        else { j -= nb4; if (j >= nc4) return; src = c; dst = oc; }
    }
    float4 v = ((const float4*)src)[j];
    ((__half2*)dst)[j*2]   = __floats2half2_rn(v.x, v.y);
    ((__half2*)dst)[j*2+1] = __floats2half2_rn(v.z, v.w);
}

#define SSTR 72                       // half stride (144B rows) conflict-free ldmatrix

// ============ WIDE GEMM (f32 acc): 128x256, warp 64x64, NSTG=3 ================
// EPI 2: Ch = gelu(acc + bias) ; EPI 3: Ch = acc + bias
#define WASTGH (128*SSTR)
#define WBSTGH (256*SSTR)
#define WNSTG 3
#define WSMEM ((WNSTG*(WASTGH+WBSTGH))*2)   // 165888 B

template<int EPI>
__global__ void __launch_bounds__(256) k_gemmw(
    const __half* __restrict__ A, const __half* __restrict__ Wt,
    const float* __restrict__ bias,
    __half* __restrict__ Ch,
    int M, int N, int K)
{
    extern __shared__ char smemraw[];
    __half* As = (__half*)smemraw;
    __half* Bs = As + WNSTG * WASTGH;
    int tid = threadIdx.x;
    int lane = tid & 31, warp = tid >> 5;
    int wm = warp & 1, wn = warp >> 1;       // warp tile 64(m) x 64(n)
    int m0 = blockIdx.y * 128, n0 = blockIdx.x * 256;
    const int nIter = K / 64;

    float acc[4][8][4];
    #pragma unroll
    for (int i = 0; i < 4; i++)
        #pragma unroll
        for (int j = 0; j < 8; j++)
            #pragma unroll
            for (int c = 0; c < 4; c++) acc[i][j][c] = 0.f;

    int cr = tid >> 3;
    int cc = (tid & 7) << 3;

    auto load_stage = [&](int iter, int st) {
        int k0 = iter * 64;
        uint32_t abase = smem_u32(As + st * WASTGH);
        uint32_t bbase = smem_u32(Bs + st * WBSTGH);
        #pragma unroll
        for (int h = 0; h < 4; h++) {
            int r = cr + h * 32;
            int gm = m0 + r; if (gm > M-1) gm = M-1;
            cpasync16(abase + (r * SSTR + cc) * 2, A + (size_t)gm * K + k0 + cc);
        }
        #pragma unroll
        for (int h = 0; h < 8; h++) {
            int r = cr + h * 32;
            cpasync16(bbase + (r * SSTR + cc) * 2, Wt + (size_t)(n0 + r) * K + k0 + cc);
        }
        asm volatile("cp.async.commit_group;\n" ::: "memory");
    };

    load_stage(0, 0);
    load_stage(1, 1);

    int a_rl = (lane & 15);
    int a_co = (lane & 16) ? 8 : 0;
    int b_rl = (lane & 7) + ((lane & 16) ? 8 : 0);
    int b_co = (lane & 8) ? 8 : 0;

    int s = 0;
    for (int i = 0; i < nIter; i++) {
        asm volatile("cp.async.wait_group 1;\n" ::: "memory");
        __syncthreads();
        const __half* as = As + s * WASTGH;
        const __half* bs = Bs + s * WBSTGH;
        int j = i + 2;
        int sj = s + 2; if (sj >= WNSTG) sj -= WNSTG;

        #pragma unroll
        for (int ks = 0; ks < 4; ks++) {
            uint32_t afr[4][4];
            #pragma unroll
            for (int mi = 0; mi < 4; mi++) {
                uint32_t addr = smem_u32(as + (wm*64 + mi*16 + a_rl) * SSTR + ks*16 + a_co);
                ldsm_x4(afr[mi][0], afr[mi][1], afr[mi][2], afr[mi][3], addr);
            }
            #pragma unroll
            for (int nb = 0; nb < 4; nb++) {
                uint32_t addr = smem_u32(bs + (wn*64 + nb*16 + b_rl) * SSTR + ks*16 + b_co);
                uint32_t b0[2], b1[2];
                ldsm_x4(b0[0], b0[1], b1[0], b1[1], addr);
                #pragma unroll
                for (int mi = 0; mi < 4; mi++) {
                    mma_16816(acc[mi][nb*2],   afr[mi], b0);
                    mma_16816(acc[mi][nb*2+1], afr[mi], b1);
                }
            }
            if (ks == 1 && j < nIter) load_stage(j, sj);
        }
        if (j >= nIter)
            asm volatile("cp.async.commit_group;\n" ::: "memory");
        if (++s == WNSTG) s = 0;
    }

    __syncthreads();

    #pragma unroll
    for (int mi = 0; mi < 4; mi++) {
        int rbase = m0 + wm*64 + mi*16 + (lane >> 2);
        #pragma unroll
        for (int ni = 0; ni < 8; ni++) {
            int col = n0 + wn*64 + ni*8 + ((lane & 3) << 1);
            float bx = __ldg(bias + col), by = __ldg(bias + col + 1);
            #pragma unroll
            for (int hh = 0; hh < 2; hh++) {
                int row = rbase + hh * 8;
                if (row < M) {
                    float v0 = acc[mi][ni][hh*2 + 0] + bx;
                    float v1 = acc[mi][ni][hh*2 + 1] + by;
                    if constexpr (EPI == 2) { v0 = gelu_exact(v0); v1 = gelu_exact(v1); }
                    *(__half2*)(Ch + (size_t)row * N + col) = __floats2half2_rn(v0, v1);
                }
            }
        }
    }
}

// ============ NARROW GEMM (proven R8/R9): 128x128, warp 32x64, NSTG=3 =========
// EPI 1: Cf = acc + bias + res
#define GBM 128
#define GBN 128
#define NSTG 3
#define ASTGH (GBM*SSTR)              // 9216 halfs per stage side

template<int EPI>
__global__ void __launch_bounds__(256, 2) k_gemm(
    const __half* __restrict__ A, const __half* __restrict__ Wt,
    const float* __restrict__ bias, const float* __restrict__ res,
    float* __restrict__ Cf,
    int M, int N, int K)
{
    __shared__ __half As[NSTG * ASTGH];
    __shared__ __half Bs[NSTG * ASTGH];
    int tid = threadIdx.x;
    int lane = tid & 31, warp = tid >> 5;
    int wm = warp & 3, wn = warp >> 2;       // warp tile 32(m) x 64(n)
    int m0 = blockIdx.y * GBM, n0 = blockIdx.x * GBN;
    const int nIter = K / 64;

    float acc[2][8][4];
    #pragma unroll
    for (int i = 0; i < 2; i++)
        #pragma unroll
        for (int j = 0; j < 8; j++)
            #pragma unroll
            for (int c = 0; c < 4; c++) acc[i][j][c] = 0.f;

    int cr = tid >> 3;
    int cc = (tid & 7) << 3;

    auto load_stage = [&](int iter, int st) {
        int k0 = iter * 64;
        uint32_t abase = smem_u32(As + st * ASTGH);
        uint32_t bbase = smem_u32(Bs + st * ASTGH);
        #pragma unroll
        for (int h = 0; h < 4; h++) {
            int r = cr + h * 32;
            int gm = m0 + r; if (gm > M-1) gm = M-1;
            cpasync16(abase + (r * SSTR + cc) * 2, A + (size_t)gm * K + k0 + cc);
            cpasync16(bbase + (r * SSTR + cc) * 2, Wt + (size_t)(n0 + r) * K + k0 + cc);
        }
        asm volatile("cp.async.commit_group;\n" ::: "memory");
    };

    load_stage(0, 0);
    load_stage(1, 1);

    int a_rl = (lane & 15);
    int a_co = (lane & 16) ? 8 : 0;
    int b_rl = (lane & 7) + ((lane & 16) ? 8 : 0);
    int b_co = (lane & 8) ? 8 : 0;

    int s = 0;
    for (int i = 0; i < nIter; i++) {
        asm volatile("cp.async.wait_group 1;\n" ::: "memory");
        __syncthreads();
        const __half* as = As + s * ASTGH;
        const __half* bs = Bs + s * ASTGH;
        int j = i + 2;
        int sj = s + 2; if (sj >= NSTG) sj -= NSTG;

        #pragma unroll
        for (int ks = 0; ks < 4; ks++) {
            uint32_t afr[2][4];
            #pragma unroll
            for (int mi = 0; mi < 2; mi++) {
                uint32_t addr = smem_u32(as + (wm*32 + mi*16 + a_rl) * SSTR + ks*16 + a_co);
                ldsm_x4(afr[mi][0], afr[mi][1], afr[mi][2], afr[mi][3], addr);
            }
            uint32_t bfr[8][2];
            #pragma unroll
            for (int nb = 0; nb < 4; nb++) {
                uint32_t addr = smem_u32(bs + (wn*64 + nb*16 + b_rl) * SSTR + ks*16 + b_co);
                uint32_t r0, r1, r2, r3;
                ldsm_x4(r0, r1, r2, r3, addr);
                bfr[nb*2][0] = r0; bfr[nb*2][1] = r1;
                bfr[nb*2+1][0] = r2; bfr[nb*2+1][1] = r3;
            }
            #pragma unroll
            for (int mi = 0; mi < 2; mi++)
                #pragma unroll
                for (int ni = 0; ni < 8; ni++)
                    mma_16816(acc[mi][ni], afr[mi], bfr[ni]);

            if (ks == 1 && j < nIter) load_stage(j, sj);
        }
        if (j >= nIter)
            asm volatile("cp.async.commit_group;\n" ::: "memory");
        if (++s == NSTG) s = 0;
    }

    __syncthreads();

    #pragma unroll
    for (int mi = 0; mi < 2; mi++) {
        int rbase = m0 + wm*32 + mi*16 + (lane >> 2);
        #pragma unroll
        for (int ni = 0; ni < 8; ni++) {
            int col = n0 + wn*64 + ni*8 + ((lane & 3) << 1);
            float bx = __ldg(bias + col), by = __ldg(bias + col + 1);
            #pragma unroll
            for (int hh = 0; hh < 2; hh++) {
                int row = rbase + hh * 8;
                if (row < M) {
                    float v0 = acc[mi][ni][hh*2 + 0] + bx;
                    float v1 = acc[mi][ni][hh*2 + 1] + by;
                    if constexpr (EPI == 1) {
                        v0 += __ldg(res + (size_t)row * N + col);
                        v1 += __ldg(res + (size_t)row * N + col + 1);
                    }
                    Cf[(size_t)row * N + col]     = v0;
                    Cf[(size_t)row * N + col + 1] = v1;
                }
            }
        }
    }
}

// ---------------- attention: full rows (queries 0..4), 128 threads ------------
__global__ void k_attn_full() {
    int idx = blockIdx.x;
    int qi = idx % KR1; idx /= KR1;
    int h = idx % KNH;
    int b = idx / KNH;
    int tid = threadIdx.x;          // 128
    int lane = tid & 31, warp = tid >> 5;
    int row = b*KS + qi;

    __shared__ float sc[KS];
    __shared__ float qsh[KHD];
    __shared__ float wredm[4], wreds[4];
    __shared__ float osh[64];

    if (tid < KHD) qsh[tid] = __half2float(g_qkv[(size_t)row*KNQ + h*KHD + tid]);
    __syncthreads();

    for (int j = tid; j < KS; j += 128) {
        const __half2* kp = (const __half2*)(g_qkv + (size_t)(b*KS + j)*KNQ + KD + h*KHD);
        float s = 0.f;
        #pragma unroll 8
        for (int d = 0; d < KHD/2; d++) {
            float2 kf = __half22float2(kp[d]);
            s += qsh[2*d] * kf.x + qsh[2*d+1] * kf.y;
        }
        sc[j] = s * 0.125f;
    }
    __syncthreads();

    float m = -1e30f;
    for (int j = tid; j < KS; j += 128) m = fmaxf(m, sc[j]);
    #pragma unroll
    for (int o = 16; o; o >>= 1) m = fmaxf(m, __shfl_xor_sync(0xffffffffu, m, o));
    if (lane == 0) wredm[warp] = m;
    __syncthreads();
    m = fmaxf(fmaxf(wredm[0], wredm[1]), fmaxf(wredm[2], wredm[3]));

    float sum = 0.f;
    for (int j = tid; j < KS; j += 128) { float e = expf(sc[j] - m); sc[j] = e; sum += e; }
    #pragma unroll
    for (int o = 16; o; o >>= 1) sum += __shfl_xor_sync(0xffffffffu, sum, o);
    if (lane == 0) wreds[warp] = sum;
    __syncthreads();
    float inv = 1.0f / (wreds[0] + wreds[1] + wreds[2] + wreds[3]);

    int half = tid >> 6, d = tid & 63;
    float o = 0.f;
    for (int j = half; j < KS; j += 2)
        o += sc[j] * __half2float(g_qkv[(size_t)(b*KS + j)*KNQ + 2*KD + h*KHD + d]);
    if (half) osh[d] = o;
    __syncthreads();
    if (tid < 64)
        g_attn_h[(size_t)row*KD + h*KHD + tid] = __float2half((o + osh[tid]) * inv);
}

// ---------------- attention: sparse rows (feature tokens) ---------------------
__global__ void k_attn_sparse() {
    int gw = (blockIdx.x * blockDim.x + threadIdx.x) >> 5;
    int lane = threadIdx.x & 31;
    if (gw >= KB*KHW*KNH) return;
    int h = gw % KNH; int rest = gw / KNH;
    int f = rest % KHW; int b = rest / KHW;
    int row = b*KS + KR1 + f;

    float2 qf = __half22float2(((const __half2*)(g_qkv + (size_t)row*KNQ + h*KHD))[lane]);

    float sc[6];
    #pragma unroll
    for (int j = 0; j < 6; j++) {
        int krow = (j < 5) ? (b*KS + j) : row;
        float2 kf = __half22float2(
            ((const __half2*)(g_qkv + (size_t)krow*KNQ + KD + h*KHD))[lane]);
        float p = qf.x*kf.x + qf.y*kf.y;
        #pragma unroll
        for (int o = 16; o; o >>= 1) p += __shfl_xor_sync(0xffffffffu, p, o);
        sc[j] = p * 0.125f;
    }
    float m = sc[0];
    #pragma unroll
    for (int j = 1; j < 6; j++) m = fmaxf(m, sc[j]);
    float sum = 0.f;
    #pragma unroll
    for (int j = 0; j < 6; j++) { sc[j] = expf(sc[j] - m); sum += sc[j]; }
    float inv = 1.0f / sum;

    float o0 = 0.f, o1 = 0.f;
    #pragma unroll
    for (int j = 0; j < 6; j++) {
        int krow = (j < 5) ? (b*KS + j) : row;
        float2 vf = __half22float2(
            ((const __half2*)(g_qkv + (size_t)krow*KNQ + 2*KD + h*KHD))[lane]);
        o0 += sc[j] * vf.x;
        o1 += sc[j] * vf.y;
    }
    ((__half2*)(g_attn_h + (size_t)row*KD + h*KHD))[lane] = __floats2half2_rn(o0 * inv, o1 * inv);
}

// ---------------- output scatter ----------------------------------------------
__global__ void k_scatter_feat(float* __restrict__ out) {
    __shared__ float tile[32][33];
    int b = blockIdx.z;
    int hw0 = blockIdx.x * 32, c0 = blockIdx.y * 32;
    int tx = threadIdx.x, ty = threadIdx.y;
    #pragma unroll
    for (int i = 0; i < 32; i += 8)
        tile[ty + i][tx] = g_res[((size_t)(b*KS + KR1 + hw0 + ty + i))*KD + c0 + tx];
    __syncthreads();
    #pragma unroll
    for (int i = 0; i < 32; i += 8)
        out[((size_t)b*KD + c0 + ty + i)*KHW + hw0 + tx] = tile[tx][ty + i];
}

__global__ void k_scatter_small(float* __restrict__ out) {
    const size_t FEAT = (size_t)KB * KD * KHW;
    const size_t CTXS = (size_t)KB * KD;
    int i = blockIdx.x * blockDim.x + threadIdx.x;
    if (i >= KB*KR1*KD) return;
    int c = i % KD;
    int t = (i / KD) % KR1;
    int b = i / (KD*KR1);
    float v = g_res[((size_t)(b*KS + t))*KD + c];
    if (t == 0) out[FEAT + (size_t)b*KD + c] = v;
    else        out[FEAT + CTXS + ((size_t)(b*(KR1-1) + (t-1)))*KD + c] = v;
}

// ---------------- launch -------------------------------------------------------
extern "C" void kernel_launch(void* const* d_in, const int* in_sizes, int n_in,
                              void* d_out, int out_size) {
    const float* x        = (const float*)d_in[0];
    const float* ctx      = (const float*)d_in[1];
    const float* reg      = (const float*)d_in[2];
    const float* in_pw    = (const float*)d_in[3];
    const float* in_pb    = (const float*)d_in[4];
    const float* out_w    = (const float*)d_in[5];
    const float* out_b    = (const float*)d_in[6];
    const float* ln1_g    = (const float*)d_in[7];
    const float* ln1_b    = (const float*)d_in[8];
    const float* ln2_g    = (const float*)d_in[9];
    const float* ln2_b    = (const float*)d_in[10];
    const float* w1       = (const float*)d_in[11];
    const float* b1       = (const float*)d_in[12];
    const float* w2       = (const float*)d_in[13];
    const float* b2       = (const float*)d_in[14];
    float* out = (float*)d_out;

    float *p_xw, *p_h1, *p_res;
    __half *p_qkv, *p_xw_h, *p_attn_h, *p_ff_h, *p_mid_h, *p_wqkv, *p_wout, *p_w1, *p_w2;
    cudaGetSymbolAddress((void**)&p_xw,     g_xw);
    cudaGetSymbolAddress((void**)&p_qkv,    g_qkv);
    cudaGetSymbolAddress((void**)&p_h1,     g_h1);
    cudaGetSymbolAddress((void**)&p_res,    g_res);
    cudaGetSymbolAddress((void**)&p_xw_h,   g_xw_h);
    cudaGetSymbolAddress((void**)&p_attn_h, g_attn_h);
    cudaGetSymbolAddress((void**)&p_ff_h,   g_ff_h);
    cudaGetSymbolAddress((void**)&p_mid_h,  g_mid_h);
    cudaGetSymbolAddress((void**)&p_wqkv,   g_wqkv_h);
    cudaGetSymbolAddress((void**)&p_wout,   g_wout_h);
    cudaGetSymbolAddress((void**)&p_w1,     g_w1_h);
    cudaGetSymbolAddress((void**)&p_w2,     g_w2_h);

    cudaFuncSetAttribute(k_gemmw<2>, cudaFuncAttributeMaxDynamicSharedMemorySize, WSMEM);
    cudaFuncSetAttribute(k_gemmw<3>, cudaFuncAttributeMaxDynamicSharedMemorySize, WSMEM);
    cudaFuncSetAttribute(k_ln1_feat, cudaFuncAttributeMaxDynamicSharedMemorySize, LN1_SMEM);

    dim3 tb32(32, 8);
    const int MT = (KBS + 127) / 128;    // 65

    // 1: QKV weight conversion
    k_f2h4<<<(KNQ*KD/4 + 255)/256, 256>>>(in_pw, p_wqkv, KNQ*KD/4);

    // 2: fused LN1 over feature tokens (reads x NCHW directly)
    k_ln1_feat<<<dim3(KHW/32, KB), 256, LN1_SMEM>>>(x, ln1_g, ln1_b, p_xw, p_xw_h);

    // 3: LN1 for ctx/register token rows
    k_ln1_tok<<<KB*KR1, 256>>>(ctx, reg, ln1_g, ln1_b, p_xw, p_xw_h);

    // 4: QKV GEMM (wide, f32-acc, half output)  <-- profiled slot
    k_gemmw<3><<<dim3(KNQ/256, MT), 256, WSMEM>>>(
        p_xw_h, p_wqkv, in_pb, p_qkv, KBS, KNQ, KD);

    // attention
    k_attn_full<<<KB*KNH*KR1, 128>>>();
    k_attn_sparse<<<(KB*KHW*KNH)/8, 256>>>();

    // remaining weight conversions (one launch)
    {
        int na4 = KD*KD/4, nb4 = KDFF*KD/4, nc4 = KD*KDFF/4;
        int tot = na4 + nb4 + nc4;
        k_f2h_rest<<<(tot + 255)/256, 256>>>(out_w, p_wout, na4, w1, p_w1, nb4, w2, p_w2, nc4);
    }

    // out-proj + residual (h1 = attn@Wo + bo + xw)
    k_gemm<1><<<dim3(KD/GBN, MT), 256>>>(
        p_attn_h, p_wout, out_b, p_xw, p_h1, KBS, KD, KD);

    // LN2
    k_layernorm<<<KBS, 256>>>(p_h1, ln2_g, ln2_b, p_ff_h);

    // FF1 + gelu (wide, half output)
    k_gemmw<2><<<dim3(KDFF/256, MT), 256, WSMEM>>>(
        p_ff_h, p_w1, b1, p_mid_h, KBS, KDFF, KD);

    // FF2 + residual (out = mid@W2 + b2 + h1)
    k_gemm<1><<<dim3(KD/GBN, MT), 256>>>(
        p_mid_h, p_w2, b2, p_h1, p_res, KBS, KD, KDFF);

    // scatter to output layout
    k_scatter_feat<<<dim3(KHW/32, KD/32, KB), tb32>>>(out);
    k_scatter_small<<<(KB*KR1*KD + 255)/256, 256>>>(out);
}

// round 14
// speedup vs baseline: 1.0736x; 1.0143x over previous
#include <cuda_runtime.h>
#include <cuda_fp16.h>
#include <math.h>
#include <stdint.h>

#define KB   8
#define KS   1029
#define KBS  (KB*KS)          // 8232
#define KD   768
#define KHW  1024
#define KNH  12
#define KHD  64
#define KR1  5
#define KDFF 3072
#define KNQ  2304
#define LN_EPS 1e-5f

// ---------------- device scratch (static: allocation-guard safe) -------------
__device__ __half g_xw_h[KBS*KD];
__device__ __half g_qkv[(size_t)KBS*KNQ];
__device__ __half g_attn_h[KBS*KD];
__device__ float  g_h1[KBS*KD];
__device__ __half g_ff_h[KBS*KD];
__device__ __half g_mid_h[(size_t)KBS*KDFF];
__device__ float  g_res[KBS*KD];
__device__ __half g_wqkv_h[KNQ*KD];
__device__ __half g_wout_h[KD*KD];
__device__ __half g_w1_h[KDFF*KD];
__device__ __half g_w2_h[KD*KDFF];

// ---------------- helpers -----------------------------------------------------
__device__ __forceinline__ uint32_t smem_u32(const void* p) {
    return (uint32_t)__cvta_generic_to_shared(p);
}
__device__ __forceinline__ void ldsm_x4(uint32_t& r0, uint32_t& r1, uint32_t& r2, uint32_t& r3, uint32_t addr) {
    asm volatile("ldmatrix.sync.aligned.m8n8.x4.shared.b16 {%0,%1,%2,%3}, [%4];\n"
                 : "=r"(r0), "=r"(r1), "=r"(r2), "=r"(r3) : "r"(addr));
}
__device__ __forceinline__ void mma_16816(float* d, const uint32_t* a, const uint32_t* b) {
    asm volatile("mma.sync.aligned.m16n8k16.row.col.f32.f16.f16.f32 "
                 "{%0,%1,%2,%3}, {%4,%5,%6,%7}, {%8,%9}, {%0,%1,%2,%3};\n"
                 : "+f"(d[0]), "+f"(d[1]), "+f"(d[2]), "+f"(d[3])
                 : "r"(a[0]), "r"(a[1]), "r"(a[2]), "r"(a[3]), "r"(b[0]), "r"(b[1]));
}
__device__ __forceinline__ void cpasync16(uint32_t d, const void* g) {
    asm volatile("cp.async.cg.shared.global [%0], [%1], 16;\n" :: "r"(d), "l"(g));
}
__device__ __forceinline__ float gelu_exact(float x) {
    return 0.5f * x * (1.0f + erff(x * 0.70710678118654752f));
}

// ---------------- fused LN1 over feature tokens (reads NCHW x directly) -------
#define LN1_SMEM ((768*33 + 64) * 4)
__global__ void k_ln1_feat(const float* __restrict__ x,
                           const float* __restrict__ gma, const float* __restrict__ bta,
                           __half* __restrict__ outh) {
    extern __shared__ float tile[];
    float* smu = tile + 768*33;
    float* srs = smu + 32;
    int b = blockIdx.y, hw0 = blockIdx.x * 32;
    int tid = threadIdx.x;
    int w = tid >> 5, l = tid & 31;

    #pragma unroll 8
    for (int k = 0; k < 96; k++) {
        int c = w + 8*k;
        tile[c*33 + l] = x[(((size_t)b*KD + c) << 10) + hw0 + l];
    }
    __syncthreads();

    #pragma unroll
    for (int rr = 0; rr < 4; rr++) {
        int row = w*4 + rr;
        float s = 0.f, q = 0.f;
        #pragma unroll
        for (int k = 0; k < 24; k++) {
            float v = tile[(l + 32*k)*33 + row];
            s += v; q += v*v;
        }
        #pragma unroll
        for (int o = 16; o; o >>= 1) {
            s += __shfl_xor_sync(0xffffffffu, s, o);
            q += __shfl_xor_sync(0xffffffffu, q, o);
        }
        if (l == 0) {
            float mu = s * (1.0f/KD);
            smu[row] = mu;
            srs[row] = rsqrtf(q * (1.0f/KD) - mu*mu + LN_EPS);
        }
    }
    __syncthreads();

    #pragma unroll
    for (int rr = 0; rr < 4; rr++) {
        int row = w*4 + rr;
        float mu = smu[row], rs = srs[row];
        size_t gbase = ((size_t)(b*KS + KR1 + hw0 + row))*KD;
        #pragma unroll 4
        for (int i = 0; i < 24; i++) {
            int c = l + 32*i;
            float v = (tile[c*33 + row] - mu) * rs * __ldg(gma + c) + __ldg(bta + c);
            outh[gbase + c] = __float2half(v);
        }
    }
}

// ---------------- LN1 for token rows (ctx + registers), grid KB*KR1 -----------
__global__ void k_ln1_tok(const float* __restrict__ ctx, const float* __restrict__ reg,
                          const float* __restrict__ gma, const float* __restrict__ bta,
                          __half* __restrict__ outh) {
    int rb = blockIdx.x;
    int b = rb / KR1, t = rb % KR1;
    const float* p = (t == 0) ? (ctx + (size_t)b*KD)
                              : (reg + ((size_t)b*(KR1-1) + (t-1))*KD);
    size_t row = (size_t)b*KS + t;
    int tid = threadIdx.x;
    int lane = tid & 31, warp = tid >> 5;
    float v0 = p[tid], v1 = p[tid + 256], v2 = p[tid + 512];
    float s = v0 + v1 + v2;
    __shared__ float red[8];
    __shared__ float s_mu, s_rstd;
    #pragma unroll
    for (int o = 16; o; o >>= 1) s += __shfl_xor_sync(0xffffffffu, s, o);
    if (lane == 0) red[warp] = s;
    __syncthreads();
    if (tid == 0) {
        float t2 = 0;
        #pragma unroll
        for (int i = 0; i < 8; i++) t2 += red[i];
        s_mu = t2 * (1.0f / KD);
    }
    __syncthreads();
    float mu = s_mu;
    float d0 = v0 - mu, d1 = v1 - mu, d2 = v2 - mu;
    float q = d0*d0 + d1*d1 + d2*d2;
    #pragma unroll
    for (int o = 16; o; o >>= 1) q += __shfl_xor_sync(0xffffffffu, q, o);
    if (lane == 0) red[warp] = q;
    __syncthreads();
    if (tid == 0) {
        float t2 = 0;
        #pragma unroll
        for (int i = 0; i < 8; i++) t2 += red[i];
        s_rstd = rsqrtf(t2 * (1.0f / KD) + LN_EPS);
    }
    __syncthreads();
    float r = s_rstd;
    #pragma unroll
    for (int i = 0; i < 3; i++) {
        int c = tid + i * 256;
        float vv = (i == 0) ? v0 : (i == 1) ? v1 : v2;
        float o = (vv - mu) * r * gma[c] + bta[c];
        outh[row*KD + c] = __float2half(o);
    }
}

// ---------------- layernorm LN2 ------------------------------------------------
__global__ void k_layernorm(const float* __restrict__ in,
                            const float* __restrict__ gma, const float* __restrict__ bta,
                            __half* __restrict__ outh) {
    int row = blockIdx.x;
    const float* p = in + (size_t)row * KD;
    int tid = threadIdx.x;
    int lane = tid & 31, warp = tid >> 5;
    float v0 = p[tid], v1 = p[tid + 256], v2 = p[tid + 512];
    float s = v0 + v1 + v2;
    __shared__ float red[8];
    __shared__ float s_mu, s_rstd;
    #pragma unroll
    for (int o = 16; o; o >>= 1) s += __shfl_xor_sync(0xffffffffu, s, o);
    if (lane == 0) red[warp] = s;
    __syncthreads();
    if (tid == 0) {
        float t = 0;
        #pragma unroll
        for (int i = 0; i < 8; i++) t += red[i];
        s_mu = t * (1.0f / KD);
    }
    __syncthreads();
    float mu = s_mu;
    float d0 = v0 - mu, d1 = v1 - mu, d2 = v2 - mu;
    float q = d0*d0 + d1*d1 + d2*d2;
    #pragma unroll
    for (int o = 16; o; o >>= 1) q += __shfl_xor_sync(0xffffffffu, q, o);
    if (lane == 0) red[warp] = q;
    __syncthreads();
    if (tid == 0) {
        float t = 0;
        #pragma unroll
        for (int i = 0; i < 8; i++) t += red[i];
        s_rstd = rsqrtf(t * (1.0f / KD) + LN_EPS);
    }
    __syncthreads();
    float r = s_rstd;
    #pragma unroll
    for (int i = 0; i < 3; i++) {
        int c = tid + i * 256;
        float vv = (i == 0) ? v0 : (i == 1) ? v1 : v2;
        float o = (vv - mu) * r * gma[c] + bta[c];
        outh[(size_t)row*KD + c] = __float2half(o);
    }
}

// ---------------- all weight conversions, one launch ---------------------------
__global__ void k_f2h_all(const float* __restrict__ a, __half* __restrict__ oa, int na4,
                          const float* __restrict__ b, __half* __restrict__ ob, int nb4,
                          const float* __restrict__ c, __half* __restrict__ oc, int nc4,
                          const float* __restrict__ d, __half* __restrict__ od, int nd4) {
    int i = blockIdx.x * blockDim.x + threadIdx.x;
    const float* src; __half* dst; int j = i;
    if (j < na4) { src = a; dst = oa; }
    else {
        j -= na4;
        if (j < nb4) { src = b; dst = ob; }
        else {
            j -= nb4;
            if (j < nc4) { src = c; dst = oc; }
            else { j -= nc4; if (j >= nd4) return; src = d; dst = od; }
        }
    }
    float4 v = ((const float4*)src)[j];
    ((__half2*)dst)[j*2]   = __floats2half2_rn(v.x, v.y);
    ((__half2*)dst)[j*2+1] = __floats2half2_rn(v.z, v.w);
}

#define SSTR 72                       // half stride (144B rows) conflict-free ldmatrix

// ============ WIDE GEMM (f32 acc): 128x256, warp 64x64, NSTG=3 ================
#define WASTGH (128*SSTR)
#define WBSTGH (256*SSTR)
#define WNSTG 3
#define WSMEM ((WNSTG*(WASTGH+WBSTGH))*2)   // 165888 B

template<int EPI>   // 2: gelu(acc+bias) ; 3: acc+bias
__global__ void __launch_bounds__(256) k_gemmw(
    const __half* __restrict__ A, const __half* __restrict__ Wt,
    const float* __restrict__ bias,
    __half* __restrict__ Ch,
    int M, int N, int K)
{
    extern __shared__ char smemraw[];
    __half* As = (__half*)smemraw;
    __half* Bs = As + WNSTG * WASTGH;
    int tid = threadIdx.x;
    int lane = tid & 31, warp = tid >> 5;
    int wm = warp & 1, wn = warp >> 1;
    int m0 = blockIdx.y * 128, n0 = blockIdx.x * 256;
    const int nIter = K / 64;

    float acc[4][8][4];
    #pragma unroll
    for (int i = 0; i < 4; i++)
        #pragma unroll
        for (int j = 0; j < 8; j++)
            #pragma unroll
            for (int c = 0; c < 4; c++) acc[i][j][c] = 0.f;

    int cr = tid >> 3;
    int cc = (tid & 7) << 3;

    auto load_stage = [&](int iter, int st) {
        int k0 = iter * 64;
        uint32_t abase = smem_u32(As + st * WASTGH);
        uint32_t bbase = smem_u32(Bs + st * WBSTGH);
        #pragma unroll
        for (int h = 0; h < 4; h++) {
            int r = cr + h * 32;
            int gm = m0 + r; if (gm > M-1) gm = M-1;
            cpasync16(abase + (r * SSTR + cc) * 2, A + (size_t)gm * K + k0 + cc);
        }
        #pragma unroll
        for (int h = 0; h < 8; h++) {
            int r = cr + h * 32;
            cpasync16(bbase + (r * SSTR + cc) * 2, Wt + (size_t)(n0 + r) * K + k0 + cc);
        }
        asm volatile("cp.async.commit_group;\n" ::: "memory");
    };

    load_stage(0, 0);
    load_stage(1, 1);

    int a_rl = (lane & 15);
    int a_co = (lane & 16) ? 8 : 0;
    int b_rl = (lane & 7) + ((lane & 16) ? 8 : 0);
    int b_co = (lane & 8) ? 8 : 0;

    int s = 0;
    for (int i = 0; i < nIter; i++) {
        asm volatile("cp.async.wait_group 1;\n" ::: "memory");
        __syncthreads();
        const __half* as = As + s * WASTGH;
        const __half* bs = Bs + s * WBSTGH;
        int j = i + 2;
        int sj = s + 2; if (sj >= WNSTG) sj -= WNSTG;

        #pragma unroll
        for (int ks = 0; ks < 4; ks++) {
            uint32_t afr[4][4];
            #pragma unroll
            for (int mi = 0; mi < 4; mi++) {
                uint32_t addr = smem_u32(as + (wm*64 + mi*16 + a_rl) * SSTR + ks*16 + a_co);
                ldsm_x4(afr[mi][0], afr[mi][1], afr[mi][2], afr[mi][3], addr);
            }
            #pragma unroll
            for (int nb = 0; nb < 4; nb++) {
                uint32_t addr = smem_u32(bs + (wn*64 + nb*16 + b_rl) * SSTR + ks*16 + b_co);
                uint32_t b0[2], b1[2];
                ldsm_x4(b0[0], b0[1], b1[0], b1[1], addr);
                #pragma unroll
                for (int mi = 0; mi < 4; mi++) {
                    mma_16816(acc[mi][nb*2],   afr[mi], b0);
                    mma_16816(acc[mi][nb*2+1], afr[mi], b1);
                }
            }
            if (ks == 1 && j < nIter) load_stage(j, sj);
        }
        if (j >= nIter)
            asm volatile("cp.async.commit_group;\n" ::: "memory");
        if (++s == WNSTG) s = 0;
    }

    __syncthreads();

    #pragma unroll
    for (int mi = 0; mi < 4; mi++) {
        int rbase = m0 + wm*64 + mi*16 + (lane >> 2);
        #pragma unroll
        for (int ni = 0; ni < 8; ni++) {
            int col = n0 + wn*64 + ni*8 + ((lane & 3) << 1);
            float bx = __ldg(bias + col), by = __ldg(bias + col + 1);
            #pragma unroll
            for (int hh = 0; hh < 2; hh++) {
                int row = rbase + hh * 8;
                if (row < M) {
                    float v0 = acc[mi][ni][hh*2 + 0] + bx;
                    float v1 = acc[mi][ni][hh*2 + 1] + by;
                    if constexpr (EPI == 2) { v0 = gelu_exact(v0); v1 = gelu_exact(v1); }
                    *(__half2*)(Ch + (size_t)row * N + col) = __floats2half2_rn(v0, v1);
                }
            }
        }
    }
}

// ============ NARROW GEMM: 128x128, warp 32x64, NSTG=3 ========================
// EPI 1: Cf = acc + bias + resf(f32) ;  EPI 4: Cf = acc + bias + resh(f16)
#define GBM 128
#define GBN 128
#define NSTG 3
#define ASTGH (GBM*SSTR)

template<int EPI>
__global__ void __launch_bounds__(256, 2) k_gemm(
    const __half* __restrict__ A, const __half* __restrict__ Wt,
    const float* __restrict__ bias,
    const float* __restrict__ resf, const __half* __restrict__ resh,
    float* __restrict__ Cf,
    int M, int N, int K)
{
    __shared__ __half As[NSTG * ASTGH];
    __shared__ __half Bs[NSTG * ASTGH];
    int tid = threadIdx.x;
    int lane = tid & 31, warp = tid >> 5;
    int wm = warp & 3, wn = warp >> 2;
    int m0 = blockIdx.y * GBM, n0 = blockIdx.x * GBN;
    const int nIter = K / 64;

    float acc[2][8][4];
    #pragma unroll
    for (int i = 0; i < 2; i++)
        #pragma unroll
        for (int j = 0; j < 8; j++)
            #pragma unroll
            for (int c = 0; c < 4; c++) acc[i][j][c] = 0.f;

    int cr = tid >> 3;
    int cc = (tid & 7) << 3;

    auto load_stage = [&](int iter, int st) {
        int k0 = iter * 64;
        uint32_t abase = smem_u32(As + st * ASTGH);
        uint32_t bbase = smem_u32(Bs + st * ASTGH);
        #pragma unroll
        for (int h = 0; h < 4; h++) {
            int r = cr + h * 32;
            int gm = m0 + r; if (gm > M-1) gm = M-1;
            cpasync16(abase + (r * SSTR + cc) * 2, A + (size_t)gm * K + k0 + cc);
            cpasync16(bbase + (r * SSTR + cc) * 2, Wt + (size_t)(n0 + r) * K + k0 + cc);
        }
        asm volatile("cp.async.commit_group;\n" ::: "memory");
    };

    load_stage(0, 0);
    load_stage(1, 1);

    int a_rl = (lane & 15);
    int a_co = (lane & 16) ? 8 : 0;
    int b_rl = (lane & 7) + ((lane & 16) ? 8 : 0);
    int b_co = (lane & 8) ? 8 : 0;

    int s = 0;
    for (int i = 0; i < nIter; i++) {
        asm volatile("cp.async.wait_group 1;\n" ::: "memory");
        __syncthreads();
        const __half* as = As + s * ASTGH;
        const __half* bs = Bs + s * ASTGH;
        int j = i + 2;
        int sj = s + 2; if (sj >= NSTG) sj -= NSTG;

        #pragma unroll
        for (int ks = 0; ks < 4; ks++) {
            uint32_t afr[2][4];
            #pragma unroll
            for (int mi = 0; mi < 2; mi++) {
                uint32_t addr = smem_u32(as + (wm*32 + mi*16 + a_rl) * SSTR + ks*16 + a_co);
                ldsm_x4(afr[mi][0], afr[mi][1], afr[mi][2], afr[mi][3], addr);
            }
            uint32_t bfr[8][2];
            #pragma unroll
            for (int nb = 0; nb < 4; nb++) {
                uint32_t addr = smem_u32(bs + (wn*64 + nb*16 + b_rl) * SSTR + ks*16 + b_co);
                uint32_t r0, r1, r2, r3;
                ldsm_x4(r0, r1, r2, r3, addr);
                bfr[nb*2][0] = r0; bfr[nb*2][1] = r1;
                bfr[nb*2+1][0] = r2; bfr[nb*2+1][1] = r3;
            }
            #pragma unroll
            for (int mi = 0; mi < 2; mi++)
                #pragma unroll
                for (int ni = 0; ni < 8; ni++)
                    mma_16816(acc[mi][ni], afr[mi], bfr[ni]);

            if (ks == 1 && j < nIter) load_stage(j, sj);
        }
        if (j >= nIter)
            asm volatile("cp.async.commit_group;\n" ::: "memory");
        if (++s == NSTG) s = 0;
    }

    __syncthreads();

    #pragma unroll
    for (int mi = 0; mi < 2; mi++) {
        int rbase = m0 + wm*32 + mi*16 + (lane >> 2);
        #pragma unroll
        for (int ni = 0; ni < 8; ni++) {
            int col = n0 + wn*64 + ni*8 + ((lane & 3) << 1);
            float bx = __ldg(bias + col), by = __ldg(bias + col + 1);
            #pragma unroll
            for (int hh = 0; hh < 2; hh++) {
                int row = rbase + hh * 8;
                if (row < M) {
                    float v0 = acc[mi][ni][hh*2 + 0] + bx;
                    float v1 = acc[mi][ni][hh*2 + 1] + by;
                    if constexpr (EPI == 1) {
                        v0 += __ldg(resf + (size_t)row * N + col);
                        v1 += __ldg(resf + (size_t)row * N + col + 1);
                    }
                    if constexpr (EPI == 4) {
                        float2 rr = __half22float2(*(const __half2*)(resh + (size_t)row * N + col));
                        v0 += rr.x; v1 += rr.y;
                    }
                    Cf[(size_t)row * N + col]     = v0;
                    Cf[(size_t)row * N + col + 1] = v1;
                }
            }
        }
    }
}

// ---------------- attention: full rows (queries 0..4), 128 threads ------------
__global__ void k_attn_full() {
    int idx = blockIdx.x;
    int qi = idx % KR1; idx /= KR1;
    int h = idx % KNH;
    int b = idx / KNH;
    int tid = threadIdx.x;
    int lane = tid & 31, warp = tid >> 5;
    int row = b*KS + qi;

    __shared__ float sc[KS];
    __shared__ float qsh[KHD];
    __shared__ float wredm[4], wreds[4];
    __shared__ float osh[64];

    if (tid < KHD) qsh[tid] = __half2float(g_qkv[(size_t)row*KNQ + h*KHD + tid]);
    __syncthreads();

    for (int j = tid; j < KS; j += 128) {
        const __half2* kp = (const __half2*)(g_qkv + (size_t)(b*KS + j)*KNQ + KD + h*KHD);
        float s = 0.f;
        #pragma unroll 8
        for (int d = 0; d < KHD/2; d++) {
            float2 kf = __half22float2(kp[d]);
            s += qsh[2*d] * kf.x + qsh[2*d+1] * kf.y;
        }
        sc[j] = s * 0.125f;
    }
    __syncthreads();

    float m = -1e30f;
    for (int j = tid; j < KS; j += 128) m = fmaxf(m, sc[j]);
    #pragma unroll
    for (int o = 16; o; o >>= 1) m = fmaxf(m, __shfl_xor_sync(0xffffffffu, m, o));
    if (lane == 0) wredm[warp] = m;
    __syncthreads();
    m = fmaxf(fmaxf(wredm[0], wredm[1]), fmaxf(wredm[2], wredm[3]));

    float sum = 0.f;
    for (int j = tid; j < KS; j += 128) { float e = expf(sc[j] - m); sc[j] = e; sum += e; }
    #pragma unroll
    for (int o = 16; o; o >>= 1) sum += __shfl_xor_sync(0xffffffffu, sum, o);
    if (lane == 0) wreds[warp] = sum;
    __syncthreads();
    float inv = 1.0f / (wreds[0] + wreds[1] + wreds[2] + wreds[3]);

    int half = tid >> 6, d = tid & 63;
    float o = 0.f;
    for (int j = half; j < KS; j += 2)
        o += sc[j] * __half2float(g_qkv[(size_t)(b*KS + j)*KNQ + 2*KD + h*KHD + d]);
    if (half) osh[d] = o;
    __syncthreads();
    if (tid < 64)
        g_attn_h[(size_t)row*KD + h*KHD + tid] = __float2half((o + osh[tid]) * inv);
}

// ---------------- attention: sparse rows (feature tokens) ---------------------
__global__ void k_attn_sparse() {
    int gw = (blockIdx.x * blockDim.x + threadIdx.x) >> 5;
    int lane = threadIdx.x & 31;
    if (gw >= KB*KHW*KNH) return;
    int h = gw % KNH; int rest = gw / KNH;
    int f = rest % KHW; int b = rest / KHW;
    int row = b*KS + KR1 + f;

    float2 qf = __half22float2(((const __half2*)(g_qkv + (size_t)row*KNQ + h*KHD))[lane]);

    float sc[6];
    #pragma unroll
    for (int j = 0; j < 6; j++) {
        int krow = (j < 5) ? (b*KS + j) : row;
        float2 kf = __half22float2(
            ((const __half2*)(g_qkv + (size_t)krow*KNQ + KD + h*KHD))[lane]);
        float p = qf.x*kf.x + qf.y*kf.y;
        #pragma unroll
        for (int o = 16; o; o >>= 1) p += __shfl_xor_sync(0xffffffffu, p, o);
        sc[j] = p * 0.125f;
    }
    float m = sc[0];
    #pragma unroll
    for (int j = 1; j < 6; j++) m = fmaxf(m, sc[j]);
    float sum = 0.f;
    #pragma unroll
    for (int j = 0; j < 6; j++) { sc[j] = expf(sc[j] - m); sum += sc[j]; }
    float inv = 1.0f / sum;

    float o0 = 0.f, o1 = 0.f;
    #pragma unroll
    for (int j = 0; j < 6; j++) {
        int krow = (j < 5) ? (b*KS + j) : row;
        float2 vf = __half22float2(
            ((const __half2*)(g_qkv + (size_t)krow*KNQ + 2*KD + h*KHD))[lane]);
        o0 += sc[j] * vf.x;
        o1 += sc[j] * vf.y;
    }
    ((__half2*)(g_attn_h + (size_t)row*KD + h*KHD))[lane] = __floats2half2_rn(o0 * inv, o1 * inv);
}

// ---------------- output scatter ----------------------------------------------
__global__ void k_scatter_feat(float* __restrict__ out) {
    __shared__ float tile[32][33];
    int b = blockIdx.z;
    int hw0 = blockIdx.x * 32, c0 = blockIdx.y * 32;
    int tx = threadIdx.x, ty = threadIdx.y;
    #pragma unroll
    for (int i = 0; i < 32; i += 8)
        tile[ty + i][tx] = g_res[((size_t)(b*KS + KR1 + hw0 + ty + i))*KD + c0 + tx];
    __syncthreads();
    #pragma unroll
    for (int i = 0; i < 32; i += 8)
        out[((size_t)b*KD + c0 + ty + i)*KHW + hw0 + tx] = tile[tx][ty + i];
}

__global__ void k_scatter_small(float* __restrict__ out) {
    const size_t FEAT = (size_t)KB * KD * KHW;
    const size_t CTXS = (size_t)KB * KD;
    int i = blockIdx.x * blockDim.x + threadIdx.x;
    if (i >= KB*KR1*KD) return;
    int c = i % KD;
    int t = (i / KD) % KR1;
    int b = i / (KD*KR1);
    float v = g_res[((size_t)(b*KS + t))*KD + c];
    if (t == 0) out[FEAT + (size_t)b*KD + c] = v;
    else        out[FEAT + CTXS + ((size_t)(b*(KR1-1) + (t-1)))*KD + c] = v;
}

// ---------------- launch -------------------------------------------------------
extern "C" void kernel_launch(void* const* d_in, const int* in_sizes, int n_in,
                              void* d_out, int out_size) {
    const float* x        = (const float*)d_in[0];
    const float* ctx      = (const float*)d_in[1];
    const float* reg      = (const float*)d_in[2];
    const float* in_pw    = (const float*)d_in[3];
    const float* in_pb    = (const float*)d_in[4];
    const float* out_w    = (const float*)d_in[5];
    const float* out_b    = (const float*)d_in[6];
    const float* ln1_g    = (const float*)d_in[7];
    const float* ln1_b    = (const float*)d_in[8];
    const float* ln2_g    = (const float*)d_in[9];
    const float* ln2_b    = (const float*)d_in[10];
    const float* w1       = (const float*)d_in[11];
    const float* b1       = (const float*)d_in[12];
    const float* w2       = (const float*)d_in[13];
    const float* b2       = (const float*)d_in[14];
    float* out = (float*)d_out;

    float *p_h1, *p_res;
    __half *p_qkv, *p_xw_h, *p_attn_h, *p_ff_h, *p_mid_h, *p_wqkv, *p_wout, *p_w1, *p_w2;
    cudaGetSymbolAddress((void**)&p_qkv,    g_qkv);
    cudaGetSymbolAddress((void**)&p_h1,     g_h1);
    cudaGetSymbolAddress((void**)&p_res,    g_res);
    cudaGetSymbolAddress((void**)&p_xw_h,   g_xw_h);
    cudaGetSymbolAddress((void**)&p_attn_h, g_attn_h);
    cudaGetSymbolAddress((void**)&p_ff_h,   g_ff_h);
    cudaGetSymbolAddress((void**)&p_mid_h,  g_mid_h);
    cudaGetSymbolAddress((void**)&p_wqkv,   g_wqkv_h);
    cudaGetSymbolAddress((void**)&p_wout,   g_wout_h);
    cudaGetSymbolAddress((void**)&p_w1,     g_w1_h);
    cudaGetSymbolAddress((void**)&p_w2,     g_w2_h);

    cudaFuncSetAttribute(k_gemmw<2>, cudaFuncAttributeMaxDynamicSharedMemorySize, WSMEM);
    cudaFuncSetAttribute(k_gemmw<3>, cudaFuncAttributeMaxDynamicSharedMemorySize, WSMEM);
    cudaFuncSetAttribute(k_ln1_feat, cudaFuncAttributeMaxDynamicSharedMemorySize, LN1_SMEM);

    dim3 tb32(32, 8);
    const int MT = (KBS + 127) / 128;    // 65

    // 1: ALL weight conversions (one launch)
    {
        int na4 = KNQ*KD/4, nb4 = KD*KD/4, nc4 = KDFF*KD/4, nd4 = KD*KDFF/4;
        int tot = na4 + nb4 + nc4 + nd4;
        k_f2h_all<<<(tot + 255)/256, 256>>>(in_pw, p_wqkv, na4, out_w, p_wout, nb4,
                                            w1, p_w1, nc4, w2, p_w2, nd4);
    }

    // 2: fused LN1 over feature tokens
    k_ln1_feat<<<dim3(KHW/32, KB), 256, LN1_SMEM>>>(x, ln1_g, ln1_b, p_xw_h);

    // 3: LN1 for ctx/register token rows
    k_ln1_tok<<<KB*KR1, 256>>>(ctx, reg, ln1_g, ln1_b, p_xw_h);

    // 4: QKV GEMM (wide, f32-acc, half output)  <-- profiled slot
    k_gemmw<3><<<dim3(KNQ/256, MT), 256, WSMEM>>>(
        p_xw_h, p_wqkv, in_pb, p_qkv, KBS, KNQ, KD);

    // attention
    k_attn_full<<<KB*KNH*KR1, 128>>>();
    k_attn_sparse<<<(KB*KHW*KNH)/8, 256>>>();

    // out-proj + residual (h1 = attn@Wo + bo + xw_h)
    k_gemm<4><<<dim3(KD/GBN, MT), 256>>>(
        p_attn_h, p_wout, out_b, nullptr, p_xw_h, p_h1, KBS, KD, KD);

    // LN2
    k_layernorm<<<KBS, 256>>>(p_h1, ln2_g, ln2_b, p_ff_h);

    // FF1 + gelu (wide)
    k_gemmw<2><<<dim3(KDFF/256, MT), 256, WSMEM>>>(
        p_ff_h, p_w1, b1, p_mid_h, KBS, KDFF, KD);

    // FF2 + residual (out = mid@W2 + b2 + h1)
    k_gemm<1><<<dim3(KD/GBN, MT), 256>>>(
        p_mid_h, p_w2, b2, p_h1, nullptr, p_res, KBS, KD, KDFF);

    // scatter to output layout
    k_scatter_feat<<<dim3(KHW/32, KD/32, KB), tb32>>>(out);
    k_scatter_small<<<(KB*KR1*KD + 255)/256, 256>>>(out);
}

// round 15
// speedup vs baseline: 1.0831x; 1.0088x over previous
#include <cuda_runtime.h>
#include <cuda_fp16.h>
#include <math.h>
#include <stdint.h>

#define KB   8
#define KS   1029
#define KBS  (KB*KS)          // 8232
#define KD   768
#define KHW  1024
#define KNH  12
#define KHD  64
#define KR1  5
#define KDFF 3072
#define KNQ  2304
#define LN_EPS 1e-5f

// ---------------- device scratch (static: allocation-guard safe) -------------
__device__ __half g_xw_h[KBS*KD];
__device__ __half g_qkv[(size_t)KBS*KNQ];
__device__ __half g_attn_h[KBS*KD];
__device__ __half g_h1_h[KBS*KD];
__device__ __half g_ff_h[KBS*KD];
__device__ __half g_mid_h[(size_t)KBS*KDFF];
__device__ __half g_wqkv_h[KNQ*KD];
__device__ __half g_wout_h[KD*KD];
__device__ __half g_w1_h[KDFF*KD];
__device__ __half g_w2_h[KD*KDFF];

// ---------------- helpers -----------------------------------------------------
__device__ __forceinline__ uint32_t smem_u32(const void* p) {
    return (uint32_t)__cvta_generic_to_shared(p);
}
__device__ __forceinline__ void ldsm_x4(uint32_t& r0, uint32_t& r1, uint32_t& r2, uint32_t& r3, uint32_t addr) {
    asm volatile("ldmatrix.sync.aligned.m8n8.x4.shared.b16 {%0,%1,%2,%3}, [%4];\n"
                 : "=r"(r0), "=r"(r1), "=r"(r2), "=r"(r3) : "r"(addr));
}
__device__ __forceinline__ void mma_16816(float* d, const uint32_t* a, const uint32_t* b) {
    asm volatile("mma.sync.aligned.m16n8k16.row.col.f32.f16.f16.f32 "
                 "{%0,%1,%2,%3}, {%4,%5,%6,%7}, {%8,%9}, {%0,%1,%2,%3};\n"
                 : "+f"(d[0]), "+f"(d[1]), "+f"(d[2]), "+f"(d[3])
                 : "r"(a[0]), "r"(a[1]), "r"(a[2]), "r"(a[3]), "r"(b[0]), "r"(b[1]));
}
__device__ __forceinline__ void cpasync16(uint32_t d, const void* g) {
    asm volatile("cp.async.cg.shared.global [%0], [%1], 16;\n" :: "r"(d), "l"(g));
}
__device__ __forceinline__ float gelu_exact(float x) {
    return 0.5f * x * (1.0f + erff(x * 0.70710678118654752f));
}

// ---------------- fused LN1 over feature tokens (reads NCHW x directly) -------
#define LN1_SMEM ((768*33 + 64) * 4)
__global__ void k_ln1_feat(const float* __restrict__ x,
                           const float* __restrict__ gma, const float* __restrict__ bta,
                           __half* __restrict__ outh) {
    extern __shared__ float tile[];
    float* smu = tile + 768*33;
    float* srs = smu + 32;
    int b = blockIdx.y, hw0 = blockIdx.x * 32;
    int tid = threadIdx.x;
    int w = tid >> 5, l = tid & 31;

    #pragma unroll 8
    for (int k = 0; k < 96; k++) {
        int c = w + 8*k;
        tile[c*33 + l] = x[(((size_t)b*KD + c) << 10) + hw0 + l];
    }
    __syncthreads();

    #pragma unroll
    for (int rr = 0; rr < 4; rr++) {
        int row = w*4 + rr;
        float s = 0.f, q = 0.f;
        #pragma unroll
        for (int k = 0; k < 24; k++) {
            float v = tile[(l + 32*k)*33 + row];
            s += v; q += v*v;
        }
        #pragma unroll
        for (int o = 16; o; o >>= 1) {
            s += __shfl_xor_sync(0xffffffffu, s, o);
            q += __shfl_xor_sync(0xffffffffu, q, o);
        }
        if (l == 0) {
            float mu = s * (1.0f/KD);
            smu[row] = mu;
            srs[row] = rsqrtf(q * (1.0f/KD) - mu*mu + LN_EPS);
        }
    }
    __syncthreads();

    #pragma unroll
    for (int rr = 0; rr < 4; rr++) {
        int row = w*4 + rr;
        float mu = smu[row], rs = srs[row];
        size_t gbase = ((size_t)(b*KS + KR1 + hw0 + row))*KD;
        #pragma unroll 4
        for (int i = 0; i < 24; i++) {
            int c = l + 32*i;
            float v = (tile[c*33 + row] - mu) * rs * __ldg(gma + c) + __ldg(bta + c);
            outh[gbase + c] = __float2half(v);
        }
    }
}

// ---------------- LN1 for token rows -------------------------------------------
__global__ void k_ln1_tok(const float* __restrict__ ctx, const float* __restrict__ reg,
                          const float* __restrict__ gma, const float* __restrict__ bta,
                          __half* __restrict__ outh) {
    int rb = blockIdx.x;
    int b = rb / KR1, t = rb % KR1;
    const float* p = (t == 0) ? (ctx + (size_t)b*KD)
                              : (reg + ((size_t)b*(KR1-1) + (t-1))*KD);
    size_t row = (size_t)b*KS + t;
    int tid = threadIdx.x;
    int lane = tid & 31, warp = tid >> 5;
    float v0 = p[tid], v1 = p[tid + 256], v2 = p[tid + 512];
    float s = v0 + v1 + v2;
    __shared__ float red[8];
    __shared__ float s_mu, s_rstd;
    #pragma unroll
    for (int o = 16; o; o >>= 1) s += __shfl_xor_sync(0xffffffffu, s, o);
    if (lane == 0) red[warp] = s;
    __syncthreads();
    if (tid == 0) {
        float t2 = 0;
        #pragma unroll
        for (int i = 0; i < 8; i++) t2 += red[i];
        s_mu = t2 * (1.0f / KD);
    }
    __syncthreads();
    float mu = s_mu;
    float d0 = v0 - mu, d1 = v1 - mu, d2 = v2 - mu;
    float q = d0*d0 + d1*d1 + d2*d2;
    #pragma unroll
    for (int o = 16; o; o >>= 1) q += __shfl_xor_sync(0xffffffffu, q, o);
    if (lane == 0) red[warp] = q;
    __syncthreads();
    if (tid == 0) {
        float t2 = 0;
        #pragma unroll
        for (int i = 0; i < 8; i++) t2 += red[i];
        s_rstd = rsqrtf(t2 * (1.0f / KD) + LN_EPS);
    }
    __syncthreads();
    float r = s_rstd;
    #pragma unroll
    for (int i = 0; i < 3; i++) {
        int c = tid + i * 256;
        float vv = (i == 0) ? v0 : (i == 1) ? v1 : v2;
        float o = (vv - mu) * r * gma[c] + bta[c];
        outh[row*KD + c] = __float2half(o);
    }
}

// ---------------- LN2 (half input) ---------------------------------------------
__global__ void k_layernorm_h(const __half* __restrict__ in,
                              const float* __restrict__ gma, const float* __restrict__ bta,
                              __half* __restrict__ outh) {
    int row = blockIdx.x;
    const __half* p = in + (size_t)row * KD;
    int tid = threadIdx.x;
    int lane = tid & 31, warp = tid >> 5;
    float v0 = __half2float(p[tid]);
    float v1 = __half2float(p[tid + 256]);
    float v2 = __half2float(p[tid + 512]);
    float s = v0 + v1 + v2;
    __shared__ float red[8];
    __shared__ float s_mu, s_rstd;
    #pragma unroll
    for (int o = 16; o; o >>= 1) s += __shfl_xor_sync(0xffffffffu, s, o);
    if (lane == 0) red[warp] = s;
    __syncthreads();
    if (tid == 0) {
        float t = 0;
        #pragma unroll
        for (int i = 0; i < 8; i++) t += red[i];
        s_mu = t * (1.0f / KD);
    }
    __syncthreads();
    float mu = s_mu;
    float d0 = v0 - mu, d1 = v1 - mu, d2 = v2 - mu;
    float q = d0*d0 + d1*d1 + d2*d2;
    #pragma unroll
    for (int o = 16; o; o >>= 1) q += __shfl_xor_sync(0xffffffffu, q, o);
    if (lane == 0) red[warp] = q;
    __syncthreads();
    if (tid == 0) {
        float t = 0;
        #pragma unroll
        for (int i = 0; i < 8; i++) t += red[i];
        s_rstd = rsqrtf(t * (1.0f / KD) + LN_EPS);
    }
    __syncthreads();
    float r = s_rstd;
    #pragma unroll
    for (int i = 0; i < 3; i++) {
        int c = tid + i * 256;
        float vv = (i == 0) ? v0 : (i == 1) ? v1 : v2;
        float o = (vv - mu) * r * gma[c] + bta[c];
        outh[(size_t)row*KD + c] = __float2half(o);
    }
}

// ---------------- all weight conversions, one launch ---------------------------
__global__ void k_f2h_all(const float* __restrict__ a, __half* __restrict__ oa, int na4,
                          const float* __restrict__ b, __half* __restrict__ ob, int nb4,
                          const float* __restrict__ c, __half* __restrict__ oc, int nc4,
                          const float* __restrict__ d, __half* __restrict__ od, int nd4) {
    int i = blockIdx.x * blockDim.x + threadIdx.x;
    const float* src; __half* dst; int j = i;
    if (j < na4) { src = a; dst = oa; }
    else {
        j -= na4;
        if (j < nb4) { src = b; dst = ob; }
        else {
            j -= nb4;
            if (j < nc4) { src = c; dst = oc; }
            else { j -= nc4; if (j >= nd4) return; src = d; dst = od; }
        }
    }
    float4 v = ((const float4*)src)[j];
    ((__half2*)dst)[j*2]   = __floats2half2_rn(v.x, v.y);
    ((__half2*)dst)[j*2+1] = __floats2half2_rn(v.z, v.w);
}

#define SSTR 72                       // half stride (144B rows) conflict-free ldmatrix

// ============ WIDE GEMM (f32 acc): 128x256, warp 64x64, NSTG=3 ================
#define WASTGH (128*SSTR)
#define WBSTGH (256*SSTR)
#define WNSTG 3
#define WSMEM ((WNSTG*(WASTGH+WBSTGH))*2)   // 165888 B

template<int EPI>   // 2: gelu(acc+bias) ; 3: acc+bias
__global__ void __launch_bounds__(256) k_gemmw(
    const __half* __restrict__ A, const __half* __restrict__ Wt,
    const float* __restrict__ bias,
    __half* __restrict__ Ch,
    int M, int N, int K)
{
    extern __shared__ char smemraw[];
    __half* As = (__half*)smemraw;
    __half* Bs = As + WNSTG * WASTGH;
    int tid = threadIdx.x;
    int lane = tid & 31, warp = tid >> 5;
    int wm = warp & 1, wn = warp >> 1;
    int m0 = blockIdx.y * 128, n0 = blockIdx.x * 256;
    const int nIter = K / 64;

    float acc[4][8][4];
    #pragma unroll
    for (int i = 0; i < 4; i++)
        #pragma unroll
        for (int j = 0; j < 8; j++)
            #pragma unroll
            for (int c = 0; c < 4; c++) acc[i][j][c] = 0.f;

    int cr = tid >> 3;
    int cc = (tid & 7) << 3;

    auto load_stage = [&](int iter, int st) {
        int k0 = iter * 64;
        uint32_t abase = smem_u32(As + st * WASTGH);
        uint32_t bbase = smem_u32(Bs + st * WBSTGH);
        #pragma unroll
        for (int h = 0; h < 4; h++) {
            int r = cr + h * 32;
            int gm = m0 + r; if (gm > M-1) gm = M-1;
            cpasync16(abase + (r * SSTR + cc) * 2, A + (size_t)gm * K + k0 + cc);
        }
        #pragma unroll
        for (int h = 0; h < 8; h++) {
            int r = cr + h * 32;
            cpasync16(bbase + (r * SSTR + cc) * 2, Wt + (size_t)(n0 + r) * K + k0 + cc);
        }
        asm volatile("cp.async.commit_group;\n" ::: "memory");
    };

    load_stage(0, 0);
    load_stage(1, 1);

    int a_rl = (lane & 15);
    int a_co = (lane & 16) ? 8 : 0;
    int b_rl = (lane & 7) + ((lane & 16) ? 8 : 0);
    int b_co = (lane & 8) ? 8 : 0;

    int s = 0;
    for (int i = 0; i < nIter; i++) {
        asm volatile("cp.async.wait_group 1;\n" ::: "memory");
        __syncthreads();
        const __half* as = As + s * WASTGH;
        const __half* bs = Bs + s * WBSTGH;
        int j = i + 2;
        int sj = s + 2; if (sj >= WNSTG) sj -= WNSTG;

        #pragma unroll
        for (int ks = 0; ks < 4; ks++) {
            uint32_t afr[4][4];
            #pragma unroll
            for (int mi = 0; mi < 4; mi++) {
                uint32_t addr = smem_u32(as + (wm*64 + mi*16 + a_rl) * SSTR + ks*16 + a_co);
                ldsm_x4(afr[mi][0], afr[mi][1], afr[mi][2], afr[mi][3], addr);
            }
            #pragma unroll
            for (int nb = 0; nb < 4; nb++) {
                uint32_t addr = smem_u32(bs + (wn*64 + nb*16 + b_rl) * SSTR + ks*16 + b_co);
                uint32_t b0[2], b1[2];
                ldsm_x4(b0[0], b0[1], b1[0], b1[1], addr);
                #pragma unroll
                for (int mi = 0; mi < 4; mi++) {
                    mma_16816(acc[mi][nb*2],   afr[mi], b0);
                    mma_16816(acc[mi][nb*2+1], afr[mi], b1);
                }
            }
            if (ks == 1 && j < nIter) load_stage(j, sj);
        }
        if (j >= nIter)
            asm volatile("cp.async.commit_group;\n" ::: "memory");
        if (++s == WNSTG) s = 0;
    }

    __syncthreads();

    #pragma unroll
    for (int mi = 0; mi < 4; mi++) {
        int rbase = m0 + wm*64 + mi*16 + (lane >> 2);
        #pragma unroll
        for (int ni = 0; ni < 8; ni++) {
            int col = n0 + wn*64 + ni*8 + ((lane & 3) << 1);
            float bx = __ldg(bias + col), by = __ldg(bias + col + 1);
            #pragma unroll
            for (int hh = 0; hh < 2; hh++) {
                int row = rbase + hh * 8;
                if (row < M) {
                    float v0 = acc[mi][ni][hh*2 + 0] + bx;
                    float v1 = acc[mi][ni][hh*2 + 1] + by;
                    if constexpr (EPI == 2) { v0 = gelu_exact(v0); v1 = gelu_exact(v1); }
                    *(__half2*)(Ch + (size_t)row * N + col) = __floats2half2_rn(v0, v1);
                }
            }
        }
    }
}

// ============ NARROW GEMM: 128x128, warp 32x64, NSTG=3 ========================
// EPI 4: Ch = half(acc + bias + resh)         (out-proj -> h1 half)
// EPI 5: fused transpose-scatter to output    (FF2: out = acc + bias + resh)
#define GBM 128
#define GBN 128
#define NSTG 3
#define ASTGH (GBM*SSTR)
#define NSMEM (NSTG * ASTGH * 2 * 2)     // 110592 B (two stage arrays)
#define ESTR 129

template<int EPI>
__global__ void __launch_bounds__(256, 2) k_gemm(
    const __half* __restrict__ A, const __half* __restrict__ Wt,
    const float* __restrict__ bias, const __half* __restrict__ resh,
    __half* __restrict__ Ch, float* __restrict__ outp,
    int M, int N, int K)
{
    __shared__ __align__(16) char sraw[NSMEM];
    __half* As = (__half*)sraw;
    __half* Bs = (__half*)(sraw + NSTG * ASTGH * 2);
    int tid = threadIdx.x;
    int lane = tid & 31, warp = tid >> 5;
    int wm = warp & 3, wn = warp >> 2;
    int m0 = blockIdx.y * GBM, n0 = blockIdx.x * GBN;
    const int nIter = K / 64;

    float acc[2][8][4];
    #pragma unroll
    for (int i = 0; i < 2; i++)
        #pragma unroll
        for (int j = 0; j < 8; j++)
            #pragma unroll
            for (int c = 0; c < 4; c++) acc[i][j][c] = 0.f;

    int cr = tid >> 3;
    int cc = (tid & 7) << 3;

    auto load_stage = [&](int iter, int st) {
        int k0 = iter * 64;
        uint32_t abase = smem_u32(As + st * ASTGH);
        uint32_t bbase = smem_u32(Bs + st * ASTGH);
        #pragma unroll
        for (int h = 0; h < 4; h++) {
            int r = cr + h * 32;
            int gm = m0 + r; if (gm > M-1) gm = M-1;
            cpasync16(abase + (r * SSTR + cc) * 2, A + (size_t)gm * K + k0 + cc);
            cpasync16(bbase + (r * SSTR + cc) * 2, Wt + (size_t)(n0 + r) * K + k0 + cc);
        }
        asm volatile("cp.async.commit_group;\n" ::: "memory");
    };

    load_stage(0, 0);
    load_stage(1, 1);

    int a_rl = (lane & 15);
    int a_co = (lane & 16) ? 8 : 0;
    int b_rl = (lane & 7) + ((lane & 16) ? 8 : 0);
    int b_co = (lane & 8) ? 8 : 0;

    int s = 0;
    for (int i = 0; i < nIter; i++) {
        asm volatile("cp.async.wait_group 1;\n" ::: "memory");
        __syncthreads();
        const __half* as = As + s * ASTGH;
        const __half* bs = Bs + s * ASTGH;
        int j = i + 2;
        int sj = s + 2; if (sj >= NSTG) sj -= NSTG;

        #pragma unroll
        for (int ks = 0; ks < 4; ks++) {
            uint32_t afr[2][4];
            #pragma unroll
            for (int mi = 0; mi < 2; mi++) {
                uint32_t addr = smem_u32(as + (wm*32 + mi*16 + a_rl) * SSTR + ks*16 + a_co);
                ldsm_x4(afr[mi][0], afr[mi][1], afr[mi][2], afr[mi][3], addr);
            }
            uint32_t bfr[8][2];
            #pragma unroll
            for (int nb = 0; nb < 4; nb++) {
                uint32_t addr = smem_u32(bs + (wn*64 + nb*16 + b_rl) * SSTR + ks*16 + b_co);
                uint32_t r0, r1, r2, r3;
                ldsm_x4(r0, r1, r2, r3, addr);
                bfr[nb*2][0] = r0; bfr[nb*2][1] = r1;
                bfr[nb*2+1][0] = r2; bfr[nb*2+1][1] = r3;
            }
            #pragma unroll
            for (int mi = 0; mi < 2; mi++)
                #pragma unroll
                for (int ni = 0; ni < 8; ni++)
                    mma_16816(acc[mi][ni], afr[mi], bfr[ni]);

            if (ks == 1 && j < nIter) load_stage(j, sj);
        }
        if (j >= nIter)
            asm volatile("cp.async.commit_group;\n" ::: "memory");
        if (++s == NSTG) s = 0;
    }

    __syncthreads();

    if constexpr (EPI == 4) {
        #pragma unroll
        for (int mi = 0; mi < 2; mi++) {
            int rbase = m0 + wm*32 + mi*16 + (lane >> 2);
            #pragma unroll
            for (int ni = 0; ni < 8; ni++) {
                int col = n0 + wn*64 + ni*8 + ((lane & 3) << 1);
                float bx = __ldg(bias + col), by = __ldg(bias + col + 1);
                #pragma unroll
                for (int hh = 0; hh < 2; hh++) {
                    int row = rbase + hh * 8;
                    if (row < M) {
                        float2 rr = __half22float2(*(const __half2*)(resh + (size_t)row * N + col));
                        *(__half2*)(Ch + (size_t)row * N + col) =
                            __floats2half2_rn(acc[mi][ni][hh*2] + bx + rr.x,
                                              acc[mi][ni][hh*2+1] + by + rr.y);
                    }
                }
            }
        }
    } else {
        // EPI 5: stage fp32 tile in smem, then transposed coalesced write to out
        float* ebuf = (float*)sraw;     // 128*129*4 = 66048 B <= NSMEM
        #pragma unroll
        for (int mi = 0; mi < 2; mi++) {
            int rl0 = wm*32 + mi*16 + (lane >> 2);
            #pragma unroll
            for (int ni = 0; ni < 8; ni++) {
                int cl = wn*64 + ni*8 + ((lane & 3) << 1);
                int col = n0 + cl;
                float bx = __ldg(bias + col), by = __ldg(bias + col + 1);
                #pragma unroll
                for (int hh = 0; hh < 2; hh++) {
                    int rl = rl0 + hh * 8;
                    int row = m0 + rl;
                    float2 rr = (row < M)
                        ? __half22float2(*(const __half2*)(resh + (size_t)row * N + col))
                        : make_float2(0.f, 0.f);
                    ebuf[rl*ESTR + cl]     = acc[mi][ni][hh*2]   + bx + rr.x;
                    ebuf[rl*ESTR + cl + 1] = acc[mi][ni][hh*2+1] + by + rr.y;
                }
            }
        }
        __syncthreads();

        const size_t FEAT = (size_t)KB * KD * KHW;
        const size_t CTXS = (size_t)KB * KD;
        #pragma unroll
        for (int ci = 0; ci < 16; ci++) {
            int cl = warp * 16 + ci;
            int cg = n0 + cl;
            #pragma unroll
            for (int rr = 0; rr < 4; rr++) {
                int rl = lane + rr * 32;
                int row = m0 + rl;
                if (row < M) {
                    float v = ebuf[rl*ESTR + cl];
                    int b = row / KS;
                    int t = row - b * KS;
                    if (t >= KR1)
                        outp[((size_t)b*KD + cg)*KHW + (t - KR1)] = v;
                    else if (t == 0)
                        outp[FEAT + (size_t)b*KD + cg] = v;
                    else
                        outp[FEAT + CTXS + ((size_t)(b*(KR1-1) + t - 1))*KD + cg] = v;
                }
            }
        }
    }
}

// ---------------- attention: full rows (queries 0..4), 128 threads ------------
__global__ void k_attn_full() {
    int idx = blockIdx.x;
    int qi = idx % KR1; idx /= KR1;
    int h = idx % KNH;
    int b = idx / KNH;
    int tid = threadIdx.x;
    int lane = tid & 31, warp = tid >> 5;
    int row = b*KS + qi;

    __shared__ float sc[KS];
    __shared__ float qsh[KHD];
    __shared__ float wredm[4], wreds[4];
    __shared__ float osh[64];

    if (tid < KHD) qsh[tid] = __half2float(g_qkv[(size_t)row*KNQ + h*KHD + tid]);
    __syncthreads();

    for (int j = tid; j < KS; j += 128) {
        const __half2* kp = (const __half2*)(g_qkv + (size_t)(b*KS + j)*KNQ + KD + h*KHD);
        float s = 0.f;
        #pragma unroll 8
        for (int d = 0; d < KHD/2; d++) {
            float2 kf = __half22float2(kp[d]);
            s += qsh[2*d] * kf.x + qsh[2*d+1] * kf.y;
        }
        sc[j] = s * 0.125f;
    }
    __syncthreads();

    float m = -1e30f;
    for (int j = tid; j < KS; j += 128) m = fmaxf(m, sc[j]);
    #pragma unroll
    for (int o = 16; o; o >>= 1) m = fmaxf(m, __shfl_xor_sync(0xffffffffu, m, o));
    if (lane == 0) wredm[warp] = m;
    __syncthreads();
    m = fmaxf(fmaxf(wredm[0], wredm[1]), fmaxf(wredm[2], wredm[3]));

    float sum = 0.f;
    for (int j = tid; j < KS; j += 128) { float e = expf(sc[j] - m); sc[j] = e; sum += e; }
    #pragma unroll
    for (int o = 16; o; o >>= 1) sum += __shfl_xor_sync(0xffffffffu, sum, o);
    if (lane == 0) wreds[warp] = sum;
    __syncthreads();
    float inv = 1.0f / (wreds[0] + wreds[1] + wreds[2] + wreds[3]);

    int half = tid >> 6, d = tid & 63;
    float o = 0.f;
    for (int j = half; j < KS; j += 2)
        o += sc[j] * __half2float(g_qkv[(size_t)(b*KS + j)*KNQ + 2*KD + h*KHD + d]);
    if (half) osh[d] = o;
    __syncthreads();
    if (tid < 64)
        g_attn_h[(size_t)row*KD + h*KHD + tid] = __float2half((o + osh[tid]) * inv);
}

// ---------------- attention: sparse rows (feature tokens) ---------------------
__global__ void k_attn_sparse() {
    int gw = (blockIdx.x * blockDim.x + threadIdx.x) >> 5;
    int lane = threadIdx.x & 31;
    if (gw >= KB*KHW*KNH) return;
    int h = gw % KNH; int rest = gw / KNH;
    int f = rest % KHW; int b = rest / KHW;
    int row = b*KS + KR1 + f;

    float2 qf = __half22float2(((const __half2*)(g_qkv + (size_t)row*KNQ + h*KHD))[lane]);

    float sc[6];
    #pragma unroll
    for (int j = 0; j < 6; j++) {
        int krow = (j < 5) ? (b*KS + j) : row;
        float2 kf = __half22float2(
            ((const __half2*)(g_qkv + (size_t)krow*KNQ + KD + h*KHD))[lane]);
        float p = qf.x*kf.x + qf.y*kf.y;
        #pragma unroll
        for (int o = 16; o; o >>= 1) p += __shfl_xor_sync(0xffffffffu, p, o);
        sc[j] = p * 0.125f;
    }
    float m = sc[0];
    #pragma unroll
    for (int j = 1; j < 6; j++) m = fmaxf(m, sc[j]);
    float sum = 0.f;
    #pragma unroll
    for (int j = 0; j < 6; j++) { sc[j] = expf(sc[j] - m); sum += sc[j]; }
    float inv = 1.0f / sum;

    float o0 = 0.f, o1 = 0.f;
    #pragma unroll
    for (int j = 0; j < 6; j++) {
        int krow = (j < 5) ? (b*KS + j) : row;
        float2 vf = __half22float2(
            ((const __half2*)(g_qkv + (size_t)krow*KNQ + 2*KD + h*KHD))[lane]);
        o0 += sc[j] * vf.x;
        o1 += sc[j] * vf.y;
    }
    ((__half2*)(g_attn_h + (size_t)row*KD + h*KHD))[lane] = __floats2half2_rn(o0 * inv, o1 * inv);
}

// ---------------- launch -------------------------------------------------------
extern "C" void kernel_launch(void* const* d_in, const int* in_sizes, int n_in,
                              void* d_out, int out_size) {
    const float* x        = (const float*)d_in[0];
    const float* ctx      = (const float*)d_in[1];
    const float* reg      = (const float*)d_in[2];
    const float* in_pw    = (const float*)d_in[3];
    const float* in_pb    = (const float*)d_in[4];
    const float* out_w    = (const float*)d_in[5];
    const float* out_b    = (const float*)d_in[6];
    const float* ln1_g    = (const float*)d_in[7];
    const float* ln1_b    = (const float*)d_in[8];
    const float* ln2_g    = (const float*)d_in[9];
    const float* ln2_b    = (const float*)d_in[10];
    const float* w1       = (const float*)d_in[11];
    const float* b1       = (const float*)d_in[12];
    const float* w2       = (const float*)d_in[13];
    const float* b2       = (const float*)d_in[14];
    float* out = (float*)d_out;

    __half *p_qkv, *p_xw_h, *p_attn_h, *p_h1_h, *p_ff_h, *p_mid_h, *p_wqkv, *p_wout, *p_w1, *p_w2;
    cudaGetSymbolAddress((void**)&p_qkv,    g_qkv);
    cudaGetSymbolAddress((void**)&p_xw_h,   g_xw_h);
    cudaGetSymbolAddress((void**)&p_attn_h, g_attn_h);
    cudaGetSymbolAddress((void**)&p_h1_h,   g_h1_h);
    cudaGetSymbolAddress((void**)&p_ff_h,   g_ff_h);
    cudaGetSymbolAddress((void**)&p_mid_h,  g_mid_h);
    cudaGetSymbolAddress((void**)&p_wqkv,   g_wqkv_h);
    cudaGetSymbolAddress((void**)&p_wout,   g_wout_h);
    cudaGetSymbolAddress((void**)&p_w1,     g_w1_h);
    cudaGetSymbolAddress((void**)&p_w2,     g_w2_h);

    cudaFuncSetAttribute(k_gemmw<2>, cudaFuncAttributeMaxDynamicSharedMemorySize, WSMEM);
    cudaFuncSetAttribute(k_gemmw<3>, cudaFuncAttributeMaxDynamicSharedMemorySize, WSMEM);
    cudaFuncSetAttribute(k_ln1_feat, cudaFuncAttributeMaxDynamicSharedMemorySize, LN1_SMEM);

    const int MT = (KBS + 127) / 128;    // 65

    // 1: ALL weight conversions (one launch)
    {
        int na4 = KNQ*KD/4, nb4 = KD*KD/4, nc4 = KDFF*KD/4, nd4 = KD*KDFF/4;
        int tot = na4 + nb4 + nc4 + nd4;
        k_f2h_all<<<(tot + 255)/256, 256>>>(in_pw, p_wqkv, na4, out_w, p_wout, nb4,
                                            w1, p_w1, nc4, w2, p_w2, nd4);
    }

    // 2: fused LN1 over feature tokens
    k_ln1_feat<<<dim3(KHW/32, KB), 256, LN1_SMEM>>>(x, ln1_g, ln1_b, p_xw_h);

    // 3: LN1 for ctx/register token rows
    k_ln1_tok<<<KB*KR1, 256>>>(ctx, reg, ln1_g, ln1_b, p_xw_h);

    // 4: QKV GEMM (wide)  <-- profiled slot
    k_gemmw<3><<<dim3(KNQ/256, MT), 256, WSMEM>>>(
        p_xw_h, p_wqkv, in_pb, p_qkv, KBS, KNQ, KD);

    // attention
    k_attn_full<<<KB*KNH*KR1, 128>>>();
    k_attn_sparse<<<(KB*KHW*KNH)/8, 256>>>();

    // out-proj + residual (h1_h = attn@Wo + bo + xw_h), half output
    k_gemm<4><<<dim3(KD/GBN, MT), 256>>>(
        p_attn_h, p_wout, out_b, p_xw_h, p_h1_h, nullptr, KBS, KD, KD);

    // LN2 (half input)
    k_layernorm_h<<<KBS, 256>>>(p_h1_h, ln2_g, ln2_b, p_ff_h);

    // FF1 + gelu (wide)
    k_gemmw<2><<<dim3(KDFF/256, MT), 256, WSMEM>>>(
        p_ff_h, p_w1, b1, p_mid_h, KBS, KDFF, KD);

    // FF2 + residual + fused transpose-scatter directly to output
    k_gemm<5><<<dim3(KD/GBN, MT), 256>>>(
        p_mid_h, p_w2, b2, p_h1_h, nullptr, out, KBS, KD, KDFF);
}

// round 16
// speedup vs baseline: 1.1419x; 1.0543x over previous
#include <cuda_runtime.h>
#include <cuda_fp16.h>
#include <math.h>
#include <stdint.h>

#define KB   8
#define KS   1029
#define KBS  (KB*KS)          // 8232
#define KD   768
#define KHW  1024
#define KNH  12
#define KHD  64
#define KR1  5
#define KDFF 3072
#define KNQ  2304
#define LN_EPS 1e-5f

// ---------------- device scratch (static: allocation-guard safe) -------------
__device__ __half g_xw_h[KBS*KD];
__device__ __half g_qkv[(size_t)KBS*KNQ];
__device__ __half g_attn_h[KBS*KD];
__device__ __half g_h1_h[KBS*KD];
__device__ __half g_ff_h[KBS*KD];
__device__ __half g_mid_h[(size_t)KBS*KDFF];
__device__ __half g_wqkv_h[KNQ*KD];
__device__ __half g_wout_h[KD*KD];
__device__ __half g_w1_h[KDFF*KD];
__device__ __half g_w2_h[KD*KDFF];

// ---------------- helpers -----------------------------------------------------
__device__ __forceinline__ uint32_t smem_u32(const void* p) {
    return (uint32_t)__cvta_generic_to_shared(p);
}
__device__ __forceinline__ void ldsm_x4(uint32_t& r0, uint32_t& r1, uint32_t& r2, uint32_t& r3, uint32_t addr) {
    asm volatile("ldmatrix.sync.aligned.m8n8.x4.shared.b16 {%0,%1,%2,%3}, [%4];\n"
                 : "=r"(r0), "=r"(r1), "=r"(r2), "=r"(r3) : "r"(addr));
}
__device__ __forceinline__ void mma_16816(float* d, const uint32_t* a, const uint32_t* b) {
    asm volatile("mma.sync.aligned.m16n8k16.row.col.f32.f16.f16.f32 "
                 "{%0,%1,%2,%3}, {%4,%5,%6,%7}, {%8,%9}, {%0,%1,%2,%3};\n"
                 : "+f"(d[0]), "+f"(d[1]), "+f"(d[2]), "+f"(d[3])
                 : "r"(a[0]), "r"(a[1]), "r"(a[2]), "r"(a[3]), "r"(b[0]), "r"(b[1]));
}
__device__ __forceinline__ void cpasync16(uint32_t d, const void* g) {
    asm volatile("cp.async.cg.shared.global [%0], [%1], 16;\n" :: "r"(d), "l"(g));
}
__device__ __forceinline__ float gelu_exact(float x) {
    return 0.5f * x * (1.0f + erff(x * 0.70710678118654752f));
}

// ---------------- fused LN1 (feature tokens + ctx/reg tokens) ------------------
// grid (33, KB): x<32 -> 32 hw rows of batch b ; x==32 -> the 5 token rows
#define LN1_SMEM ((768*33 + 64) * 4)
__global__ void k_ln1_feat(const float* __restrict__ x,
                           const float* __restrict__ ctx, const float* __restrict__ reg,
                           const float* __restrict__ gma, const float* __restrict__ bta,
                           __half* __restrict__ outh) {
    extern __shared__ float tile[];
    float* smu = tile + 768*33;
    float* srs = smu + 32;
    int b = blockIdx.y;
    int tid = threadIdx.x;
    int w = tid >> 5, l = tid & 31;

    if (blockIdx.x == 32) {
        // token rows: 5 rows per batch, 256-thread row reduction each
        int lane = tid & 31, warp = tid >> 5;
        __shared__ float red[8];
        __shared__ float s_mu, s_rstd;
        for (int t = 0; t < KR1; t++) {
            const float* p = (t == 0) ? (ctx + (size_t)b*KD)
                                      : (reg + ((size_t)b*(KR1-1) + (t-1))*KD);
            size_t row = (size_t)b*KS + t;
            float v0 = p[tid], v1 = p[tid + 256], v2 = p[tid + 512];
            float s = v0 + v1 + v2;
            #pragma unroll
            for (int o = 16; o; o >>= 1) s += __shfl_xor_sync(0xffffffffu, s, o);
            if (lane == 0) red[warp] = s;
            __syncthreads();
            if (tid == 0) {
                float t2 = 0;
                #pragma unroll
                for (int i = 0; i < 8; i++) t2 += red[i];
                s_mu = t2 * (1.0f / KD);
            }
            __syncthreads();
            float mu = s_mu;
            float d0 = v0 - mu, d1 = v1 - mu, d2 = v2 - mu;
            float q = d0*d0 + d1*d1 + d2*d2;
            #pragma unroll
            for (int o = 16; o; o >>= 1) q += __shfl_xor_sync(0xffffffffu, q, o);
            if (lane == 0) red[warp] = q;
            __syncthreads();
            if (tid == 0) {
                float t2 = 0;
                #pragma unroll
                for (int i = 0; i < 8; i++) t2 += red[i];
                s_rstd = rsqrtf(t2 * (1.0f / KD) + LN_EPS);
            }
            __syncthreads();
            float r = s_rstd;
            #pragma unroll
            for (int i = 0; i < 3; i++) {
                int c = tid + i * 256;
                float vv = (i == 0) ? v0 : (i == 1) ? v1 : v2;
                outh[row*KD + c] = __float2half((vv - mu) * r * gma[c] + bta[c]);
            }
            __syncthreads();
        }
        return;
    }

    int hw0 = blockIdx.x * 32;
    #pragma unroll 8
    for (int k = 0; k < 96; k++) {
        int c = w + 8*k;
        tile[c*33 + l] = x[(((size_t)b*KD + c) << 10) + hw0 + l];
    }
    __syncthreads();

    #pragma unroll
    for (int rr = 0; rr < 4; rr++) {
        int row = w*4 + rr;
        float s = 0.f, q = 0.f;
        #pragma unroll
        for (int k = 0; k < 24; k++) {
            float v = tile[(l + 32*k)*33 + row];
            s += v; q += v*v;
        }
        #pragma unroll
        for (int o = 16; o; o >>= 1) {
            s += __shfl_xor_sync(0xffffffffu, s, o);
            q += __shfl_xor_sync(0xffffffffu, q, o);
        }
        if (l == 0) {
            float mu = s * (1.0f/KD);
            smu[row] = mu;
            srs[row] = rsqrtf(q * (1.0f/KD) - mu*mu + LN_EPS);
        }
    }
    __syncthreads();

    #pragma unroll
    for (int rr = 0; rr < 4; rr++) {
        int row = w*4 + rr;
        float mu = smu[row], rs = srs[row];
        size_t gbase = ((size_t)(b*KS + KR1 + hw0 + row))*KD;
        #pragma unroll 4
        for (int i = 0; i < 24; i++) {
            int c = l + 32*i;
            float v = (tile[c*33 + row] - mu) * rs * __ldg(gma + c) + __ldg(bta + c);
            outh[gbase + c] = __float2half(v);
        }
    }
}

// ---------------- LN2 (half input) ---------------------------------------------
__global__ void k_layernorm_h(const __half* __restrict__ in,
                              const float* __restrict__ gma, const float* __restrict__ bta,
                              __half* __restrict__ outh) {
    int row = blockIdx.x;
    const __half* p = in + (size_t)row * KD;
    int tid = threadIdx.x;
    int lane = tid & 31, warp = tid >> 5;
    float v0 = __half2float(p[tid]);
    float v1 = __half2float(p[tid + 256]);
    float v2 = __half2float(p[tid + 512]);
    float s = v0 + v1 + v2;
    __shared__ float red[8];
    __shared__ float s_mu, s_rstd;
    #pragma unroll
    for (int o = 16; o; o >>= 1) s += __shfl_xor_sync(0xffffffffu, s, o);
    if (lane == 0) red[warp] = s;
    __syncthreads();
    if (tid == 0) {
        float t = 0;
        #pragma unroll
        for (int i = 0; i < 8; i++) t += red[i];
        s_mu = t * (1.0f / KD);
    }
    __syncthreads();
    float mu = s_mu;
    float d0 = v0 - mu, d1 = v1 - mu, d2 = v2 - mu;
    float q = d0*d0 + d1*d1 + d2*d2;
    #pragma unroll
    for (int o = 16; o; o >>= 1) q += __shfl_xor_sync(0xffffffffu, q, o);
    if (lane == 0) red[warp] = q;
    __syncthreads();
    if (tid == 0) {
        float t = 0;
        #pragma unroll
        for (int i = 0; i < 8; i++) t += red[i];
        s_rstd = rsqrtf(t * (1.0f / KD) + LN_EPS);
    }
    __syncthreads();
    float r = s_rstd;
    #pragma unroll
    for (int i = 0; i < 3; i++) {
        int c = tid + i * 256;
        float vv = (i == 0) ? v0 : (i == 1) ? v1 : v2;
        outh[(size_t)row*KD + c] = __float2half((vv - mu) * r * gma[c] + bta[c]);
    }
}

// ---------------- all weight conversions, one launch ---------------------------
__global__ void k_f2h_all(const float* __restrict__ a, __half* __restrict__ oa, int na4,
                          const float* __restrict__ b, __half* __restrict__ ob, int nb4,
                          const float* __restrict__ c, __half* __restrict__ oc, int nc4,
                          const float* __restrict__ d, __half* __restrict__ od, int nd4) {
    int i = blockIdx.x * blockDim.x + threadIdx.x;
    const float* src; __half* dst; int j = i;
    if (j < na4) { src = a; dst = oa; }
    else {
        j -= na4;
        if (j < nb4) { src = b; dst = ob; }
        else {
            j -= nb4;
            if (j < nc4) { src = c; dst = oc; }
            else { j -= nc4; if (j >= nd4) return; src = d; dst = od; }
        }
    }
    float4 v = ((const float4*)src)[j];
    ((__half2*)dst)[j*2]   = __floats2half2_rn(v.x, v.y);
    ((__half2*)dst)[j*2+1] = __floats2half2_rn(v.z, v.w);
}

#define SSTR 72                       // half stride (144B rows) conflict-free ldmatrix

// ============ WIDE GEMM (f32 acc): 128x256, warp 64x64, NSTG=3 ================
#define WASTGH (128*SSTR)
#define WBSTGH (256*SSTR)
#define WNSTG 3
#define WSMEM ((WNSTG*(WASTGH+WBSTGH))*2)   // 165888 B

template<int EPI>   // 2: gelu(acc+bias) ; 3: acc+bias
__global__ void __launch_bounds__(256) k_gemmw(
    const __half* __restrict__ A, const __half* __restrict__ Wt,
    const float* __restrict__ bias,
    __half* __restrict__ Ch,
    int M, int N, int K)
{
    extern __shared__ char smemraw[];
    __half* As = (__half*)smemraw;
    __half* Bs = As + WNSTG * WASTGH;
    int tid = threadIdx.x;
    int lane = tid & 31, warp = tid >> 5;
    int wm = warp & 1, wn = warp >> 1;
    int m0 = blockIdx.y * 128, n0 = blockIdx.x * 256;
    const int nIter = K / 64;

    float acc[4][8][4];
    #pragma unroll
    for (int i = 0; i < 4; i++)
        #pragma unroll
        for (int j = 0; j < 8; j++)
            #pragma unroll
            for (int c = 0; c < 4; c++) acc[i][j][c] = 0.f;

    int cr = tid >> 3;
    int cc = (tid & 7) << 3;

    auto load_stage = [&](int iter, int st) {
        int k0 = iter * 64;
        uint32_t abase = smem_u32(As + st * WASTGH);
        uint32_t bbase = smem_u32(Bs + st * WBSTGH);
        #pragma unroll
        for (int h = 0; h < 4; h++) {
            int r = cr + h * 32;
            int gm = m0 + r; if (gm > M-1) gm = M-1;
            cpasync16(abase + (r * SSTR + cc) * 2, A + (size_t)gm * K + k0 + cc);
        }
        #pragma unroll
        for (int h = 0; h < 8; h++) {
            int r = cr + h * 32;
            cpasync16(bbase + (r * SSTR + cc) * 2, Wt + (size_t)(n0 + r) * K + k0 + cc);
        }
        asm volatile("cp.async.commit_group;\n" ::: "memory");
    };

    load_stage(0, 0);
    load_stage(1, 1);

    int a_rl = (lane & 15);
    int a_co = (lane & 16) ? 8 : 0;
    int b_rl = (lane & 7) + ((lane & 16) ? 8 : 0);
    int b_co = (lane & 8) ? 8 : 0;

    int s = 0;
    for (int i = 0; i < nIter; i++) {
        asm volatile("cp.async.wait_group 1;\n" ::: "memory");
        __syncthreads();
        const __half* as = As + s * WASTGH;
        const __half* bs = Bs + s * WBSTGH;
        int j = i + 2;
        int sj = s + 2; if (sj >= WNSTG) sj -= WNSTG;

        #pragma unroll
        for (int ks = 0; ks < 4; ks++) {
            uint32_t afr[4][4];
            #pragma unroll
            for (int mi = 0; mi < 4; mi++) {
                uint32_t addr = smem_u32(as + (wm*64 + mi*16 + a_rl) * SSTR + ks*16 + a_co);
                ldsm_x4(afr[mi][0], afr[mi][1], afr[mi][2], afr[mi][3], addr);
            }
            #pragma unroll
            for (int nb = 0; nb < 4; nb++) {
                uint32_t addr = smem_u32(bs + (wn*64 + nb*16 + b_rl) * SSTR + ks*16 + b_co);
                uint32_t b0[2], b1[2];
                ldsm_x4(b0[0], b0[1], b1[0], b1[1], addr);
                #pragma unroll
                for (int mi = 0; mi < 4; mi++) {
                    mma_16816(acc[mi][nb*2],   afr[mi], b0);
                    mma_16816(acc[mi][nb*2+1], afr[mi], b1);
                }
            }
            if (ks == 1 && j < nIter) load_stage(j, sj);
        }
        if (j >= nIter)
            asm volatile("cp.async.commit_group;\n" ::: "memory");
        if (++s == WNSTG) s = 0;
    }

    __syncthreads();

    #pragma unroll
    for (int mi = 0; mi < 4; mi++) {
        int rbase = m0 + wm*64 + mi*16 + (lane >> 2);
        #pragma unroll
        for (int ni = 0; ni < 8; ni++) {
            int col = n0 + wn*64 + ni*8 + ((lane & 3) << 1);
            float bx = __ldg(bias + col), by = __ldg(bias + col + 1);
            #pragma unroll
            for (int hh = 0; hh < 2; hh++) {
                int row = rbase + hh * 8;
                if (row < M) {
                    float v0 = acc[mi][ni][hh*2 + 0] + bx;
                    float v1 = acc[mi][ni][hh*2 + 1] + by;
                    if constexpr (EPI == 2) { v0 = gelu_exact(v0); v1 = gelu_exact(v1); }
                    *(__half2*)(Ch + (size_t)row * N + col) = __floats2half2_rn(v0, v1);
                }
            }
        }
    }
}

// ============ NARROW GEMM: 128x128, warp 32x64, NSTG=3 ========================
// EPI 4: Ch = half(acc + bias + resh) ; EPI 5: fused transpose-scatter to output
#define GBM 128
#define GBN 128
#define NSTG 3
#define ASTGH (GBM*SSTR)
#define NSMEM (NSTG * ASTGH * 2 * 2)
#define ESTR 129

template<int EPI>
__global__ void __launch_bounds__(256, 2) k_gemm(
    const __half* __restrict__ A, const __half* __restrict__ Wt,
    const float* __restrict__ bias, const __half* __restrict__ resh,
    __half* __restrict__ Ch, float* __restrict__ outp,
    int M, int N, int K)
{
    __shared__ __align__(16) char sraw[NSMEM];
    __half* As = (__half*)sraw;
    __half* Bs = (__half*)(sraw + NSTG * ASTGH * 2);
    int tid = threadIdx.x;
    int lane = tid & 31, warp = tid >> 5;
    int wm = warp & 3, wn = warp >> 2;
    int m0 = blockIdx.y * GBM, n0 = blockIdx.x * GBN;
    const int nIter = K / 64;

    float acc[2][8][4];
    #pragma unroll
    for (int i = 0; i < 2; i++)
        #pragma unroll
        for (int j = 0; j < 8; j++)
            #pragma unroll
            for (int c = 0; c < 4; c++) acc[i][j][c] = 0.f;

    int cr = tid >> 3;
    int cc = (tid & 7) << 3;

    auto load_stage = [&](int iter, int st) {
        int k0 = iter * 64;
        uint32_t abase = smem_u32(As + st * ASTGH);
        uint32_t bbase = smem_u32(Bs + st * ASTGH);
        #pragma unroll
        for (int h = 0; h < 4; h++) {
            int r = cr + h * 32;
            int gm = m0 + r; if (gm > M-1) gm = M-1;
            cpasync16(abase + (r * SSTR + cc) * 2, A + (size_t)gm * K + k0 + cc);
            cpasync16(bbase + (r * SSTR + cc) * 2, Wt + (size_t)(n0 + r) * K + k0 + cc);
        }
        asm volatile("cp.async.commit_group;\n" ::: "memory");
    };

    load_stage(0, 0);
    load_stage(1, 1);

    int a_rl = (lane & 15);
    int a_co = (lane & 16) ? 8 : 0;
    int b_rl = (lane & 7) + ((lane & 16) ? 8 : 0);
    int b_co = (lane & 8) ? 8 : 0;

    int s = 0;
    for (int i = 0; i < nIter; i++) {
        asm volatile("cp.async.wait_group 1;\n" ::: "memory");
        __syncthreads();
        const __half* as = As + s * ASTGH;
        const __half* bs = Bs + s * ASTGH;
        int j = i + 2;
        int sj = s + 2; if (sj >= NSTG) sj -= NSTG;

        #pragma unroll
        for (int ks = 0; ks < 4; ks++) {
            uint32_t afr[2][4];
            #pragma unroll
            for (int mi = 0; mi < 2; mi++) {
                uint32_t addr = smem_u32(as + (wm*32 + mi*16 + a_rl) * SSTR + ks*16 + a_co);
                ldsm_x4(afr[mi][0], afr[mi][1], afr[mi][2], afr[mi][3], addr);
            }
            uint32_t bfr[8][2];
            #pragma unroll
            for (int nb = 0; nb < 4; nb++) {
                uint32_t addr = smem_u32(bs + (wn*64 + nb*16 + b_rl) * SSTR + ks*16 + b_co);
                uint32_t r0, r1, r2, r3;
                ldsm_x4(r0, r1, r2, r3, addr);
                bfr[nb*2][0] = r0; bfr[nb*2][1] = r1;
                bfr[nb*2+1][0] = r2; bfr[nb*2+1][1] = r3;
            }
            #pragma unroll
            for (int mi = 0; mi < 2; mi++)
                #pragma unroll
                for (int ni = 0; ni < 8; ni++)
                    mma_16816(acc[mi][ni], afr[mi], bfr[ni]);

            if (ks == 1 && j < nIter) load_stage(j, sj);
        }
        if (j >= nIter)
            asm volatile("cp.async.commit_group;\n" ::: "memory");
        if (++s == NSTG) s = 0;
    }

    __syncthreads();

    if constexpr (EPI == 4) {
        #pragma unroll
        for (int mi = 0; mi < 2; mi++) {
            int rbase = m0 + wm*32 + mi*16 + (lane >> 2);
            #pragma unroll
            for (int ni = 0; ni < 8; ni++) {
                int col = n0 + wn*64 + ni*8 + ((lane & 3) << 1);
                float bx = __ldg(bias + col), by = __ldg(bias + col + 1);
                #pragma unroll
                for (int hh = 0; hh < 2; hh++) {
                    int row = rbase + hh * 8;
                    if (row < M) {
                        float2 rr = __half22float2(*(const __half2*)(resh + (size_t)row * N + col));
                        *(__half2*)(Ch + (size_t)row * N + col) =
                            __floats2half2_rn(acc[mi][ni][hh*2] + bx + rr.x,
                                              acc[mi][ni][hh*2+1] + by + rr.y);
                    }
                }
            }
        }
    } else {
        float* ebuf = (float*)sraw;
        #pragma unroll
        for (int mi = 0; mi < 2; mi++) {
            int rl0 = wm*32 + mi*16 + (lane >> 2);
            #pragma unroll
            for (int ni = 0; ni < 8; ni++) {
                int cl = wn*64 + ni*8 + ((lane & 3) << 1);
                int col = n0 + cl;
                float bx = __ldg(bias + col), by = __ldg(bias + col + 1);
                #pragma unroll
                for (int hh = 0; hh < 2; hh++) {
                    int rl = rl0 + hh * 8;
                    int row = m0 + rl;
                    float2 rr = (row < M)
                        ? __half22float2(*(const __half2*)(resh + (size_t)row * N + col))
                        : make_float2(0.f, 0.f);
                    ebuf[rl*ESTR + cl]     = acc[mi][ni][hh*2]   + bx + rr.x;
                    ebuf[rl*ESTR + cl + 1] = acc[mi][ni][hh*2+1] + by + rr.y;
                }
            }
        }
        __syncthreads();

        const size_t FEAT = (size_t)KB * KD * KHW;
        const size_t CTXS = (size_t)KB * KD;
        #pragma unroll
        for (int ci = 0; ci < 16; ci++) {
            int cl = warp * 16 + ci;
            int cg = n0 + cl;
            #pragma unroll
            for (int rr = 0; rr < 4; rr++) {
                int rl = lane + rr * 32;
                int row = m0 + rl;
                if (row < M) {
                    float v = ebuf[rl*ESTR + cl];
                    int b = row / KS;
                    int t = row - b * KS;
                    if (t >= KR1)
                        outp[((size_t)b*KD + cg)*KHW + (t - KR1)] = v;
                    else if (t == 0)
                        outp[FEAT + (size_t)b*KD + cg] = v;
                    else
                        outp[FEAT + CTXS + ((size_t)(b*(KR1-1) + t - 1))*KD + cg] = v;
                }
            }
        }
    }
}

// ---------------- unified attention: 128-thread blocks -------------------------
// blocks [0, 480): full rows (b, h, qi).  blocks [480, 480+24576): sparse, 4 warps each.
#define ATT_FULL_BLOCKS (KB*KNH*KR1)
#define ATT_SPARSE_BLOCKS ((KB*KHW*KNH)/4)
__global__ void k_attn() {
    int tid = threadIdx.x;
    int lane = tid & 31, warp = tid >> 5;

    if (blockIdx.x < ATT_FULL_BLOCKS) {
        int idx = blockIdx.x;
        int qi = idx % KR1; idx /= KR1;
        int h = idx % KNH;
        int b = idx / KNH;
        int row = b*KS + qi;

        __shared__ float sc[KS];
        __shared__ float qsh[KHD];
        __shared__ float wredm[4], wreds[4];
        __shared__ float osh[64];

        if (tid < KHD) qsh[tid] = __half2float(g_qkv[(size_t)row*KNQ + h*KHD + tid]);
        __syncthreads();

        for (int j = tid; j < KS; j += 128) {
            const __half2* kp = (const __half2*)(g_qkv + (size_t)(b*KS + j)*KNQ + KD + h*KHD);
            float s = 0.f;
            #pragma unroll 8
            for (int d = 0; d < KHD/2; d++) {
                float2 kf = __half22float2(kp[d]);
                s += qsh[2*d] * kf.x + qsh[2*d+1] * kf.y;
            }
            sc[j] = s * 0.125f;
        }
        __syncthreads();

        float m = -1e30f;
        for (int j = tid; j < KS; j += 128) m = fmaxf(m, sc[j]);
        #pragma unroll
        for (int o = 16; o; o >>= 1) m = fmaxf(m, __shfl_xor_sync(0xffffffffu, m, o));
        if (lane == 0) wredm[warp] = m;
        __syncthreads();
        m = fmaxf(fmaxf(wredm[0], wredm[1]), fmaxf(wredm[2], wredm[3]));

        float sum = 0.f;
        for (int j = tid; j < KS; j += 128) { float e = __expf(sc[j] - m); sc[j] = e; sum += e; }
        #pragma unroll
        for (int o = 16; o; o >>= 1) sum += __shfl_xor_sync(0xffffffffu, sum, o);
        if (lane == 0) wreds[warp] = sum;
        __syncthreads();
        float inv = 1.0f / (wreds[0] + wreds[1] + wreds[2] + wreds[3]);

        int half = tid >> 6, d = tid & 63;
        float o = 0.f;
        for (int j = half; j < KS; j += 2)
            o += sc[j] * __half2float(g_qkv[(size_t)(b*KS + j)*KNQ + 2*KD + h*KHD + d]);
        if (half) osh[d] = o;
        __syncthreads();
        if (tid < 64)
            g_attn_h[(size_t)row*KD + h*KHD + tid] = __float2half((o + osh[tid]) * inv);
        return;
    }

    // sparse path
    int gw = (blockIdx.x - ATT_FULL_BLOCKS) * 4 + warp;
    if (gw >= KB*KHW*KNH) return;
    int h = gw % KNH; int rest = gw / KNH;
    int f = rest % KHW; int b = rest / KHW;
    int row = b*KS + KR1 + f;

    float2 qf = __half22float2(((const __half2*)(g_qkv + (size_t)row*KNQ + h*KHD))[lane]);

    float sc[6];
    #pragma unroll
    for (int j = 0; j < 6; j++) {
        int krow = (j < 5) ? (b*KS + j) : row;
        float2 kf = __half22float2(
            ((const __half2*)(g_qkv + (size_t)krow*KNQ + KD + h*KHD))[lane]);
        float p = qf.x*kf.x + qf.y*kf.y;
        #pragma unroll
        for (int o = 16; o; o >>= 1) p += __shfl_xor_sync(0xffffffffu, p, o);
        sc[j] = p * 0.125f;
    }
    float m = sc[0];
    #pragma unroll
    for (int j = 1; j < 6; j++) m = fmaxf(m, sc[j]);
    float sum = 0.f;
    #pragma unroll
    for (int j = 0; j < 6; j++) { sc[j] = __expf(sc[j] - m); sum += sc[j]; }
    float inv = 1.0f / sum;

    float o0 = 0.f, o1 = 0.f;
    #pragma unroll
    for (int j = 0; j < 6; j++) {
        int krow = (j < 5) ? (b*KS + j) : row;
        float2 vf = __half22float2(
            ((const __half2*)(g_qkv + (size_t)krow*KNQ + 2*KD + h*KHD))[lane]);
        o0 += sc[j] * vf.x;
        o1 += sc[j] * vf.y;
    }
    ((__half2*)(g_attn_h + (size_t)row*KD + h*KHD))[lane] = __floats2half2_rn(o0 * inv, o1 * inv);
}

// ---------------- launch -------------------------------------------------------
extern "C" void kernel_launch(void* const* d_in, const int* in_sizes, int n_in,
                              void* d_out, int out_size) {
    const float* x        = (const float*)d_in[0];
    const float* ctx      = (const float*)d_in[1];
    const float* reg      = (const float*)d_in[2];
    const float* in_pw    = (const float*)d_in[3];
    const float* in_pb    = (const float*)d_in[4];
    const float* out_w    = (const float*)d_in[5];
    const float* out_b    = (const float*)d_in[6];
    const float* ln1_g    = (const float*)d_in[7];
    const float* ln1_b    = (const float*)d_in[8];
    const float* ln2_g    = (const float*)d_in[9];
    const float* ln2_b    = (const float*)d_in[10];
    const float* w1       = (const float*)d_in[11];
    const float* b1       = (const float*)d_in[12];
    const float* w2       = (const float*)d_in[13];
    const float* b2       = (const float*)d_in[14];
    float* out = (float*)d_out;

    __half *p_qkv, *p_xw_h, *p_attn_h, *p_h1_h, *p_ff_h, *p_mid_h, *p_wqkv, *p_wout, *p_w1, *p_w2;
    cudaGetSymbolAddress((void**)&p_qkv,    g_qkv);
    cudaGetSymbolAddress((void**)&p_xw_h,   g_xw_h);
    cudaGetSymbolAddress((void**)&p_attn_h, g_attn_h);
    cudaGetSymbolAddress((void**)&p_h1_h,   g_h1_h);
    cudaGetSymbolAddress((void**)&p_ff_h,   g_ff_h);
    cudaGetSymbolAddress((void**)&p_mid_h,  g_mid_h);
    cudaGetSymbolAddress((void**)&p_wqkv,   g_wqkv_h);
    cudaGetSymbolAddress((void**)&p_wout,   g_wout_h);
    cudaGetSymbolAddress((void**)&p_w1,     g_w1_h);
    cudaGetSymbolAddress((void**)&p_w2,     g_w2_h);

    cudaFuncSetAttribute(k_gemmw<2>, cudaFuncAttributeMaxDynamicSharedMemorySize, WSMEM);
    cudaFuncSetAttribute(k_gemmw<3>, cudaFuncAttributeMaxDynamicSharedMemorySize, WSMEM);
    cudaFuncSetAttribute(k_ln1_feat, cudaFuncAttributeMaxDynamicSharedMemorySize, LN1_SMEM);

    const int MT = (KBS + 127) / 128;    // 65

    // 1: ALL weight conversions
    {
        int na4 = KNQ*KD/4, nb4 = KD*KD/4, nc4 = KDFF*KD/4, nd4 = KD*KDFF/4;
        int tot = na4 + nb4 + nc4 + nd4;
        k_f2h_all<<<(tot + 255)/256, 256>>>(in_pw, p_wqkv, na4, out_w, p_wout, nb4,
                                            w1, p_w1, nc4, w2, p_w2, nd4);
    }

    // 2: fused LN1 (features + tokens)
    k_ln1_feat<<<dim3(33, KB), 256, LN1_SMEM>>>(x, ctx, reg, ln1_g, ln1_b, p_xw_h);

    // 3: dummy-free spacing not needed; QKV must be launch #4 for profiling: insert
    //    LN1 already merged, so add attention AFTER QKV as before.
    // 3: QKV GEMM ... (was slot 4; keep a no-dependency tiny kernel? No — accept slot shift)
    // QKV GEMM (wide)
    k_gemmw<3><<<dim3(KNQ/256, MT), 256, WSMEM>>>(
        p_xw_h, p_wqkv, in_pb, p_qkv, KBS, KNQ, KD);

    // 4: unified attention  <-- profiled slot this round (by design)
    k_attn<<<ATT_FULL_BLOCKS + ATT_SPARSE_BLOCKS, 128>>>();

    // out-proj + residual (h1_h = attn@Wo + bo + xw_h)
    k_gemm<4><<<dim3(KD/GBN, MT), 256>>>(
        p_attn_h, p_wout, out_b, p_xw_h, p_h1_h, nullptr, KBS, KD, KD);

    // LN2 (half input)
    k_layernorm_h<<<KBS, 256>>>(p_h1_h, ln2_g, ln2_b, p_ff_h);

    // FF1 + gelu (wide)
    k_gemmw<2><<<dim3(KDFF/256, MT), 256, WSMEM>>>(
        p_ff_h, p_w1, b1, p_mid_h, KBS, KDFF, KD);

    // FF2 + residual + fused transpose-scatter directly to output
    k_gemm<5><<<dim3(KD/GBN, MT), 256>>>(
        p_mid_h, p_w2, b2, p_h1_h, nullptr, out, KBS, KD, KDFF);
}